// round 11
// baseline (speedup 1.0000x reference)
#include <cuda_runtime.h>
#include <cuda_bf16.h>
#include <cstdint>
#include <math.h>

// ---------------------------------------------------------------------------
// Problem constants
// ---------------------------------------------------------------------------
namespace {
constexpr int B_   = 2;
constexpr int S_   = 2048;
constexpr int D_   = 2048;
constexpr int H_   = 16;
constexpr int HKV_ = 4;
constexpr int G_   = H_ / HKV_;
constexpr int RQ_  = 1024;
constexpr int RKV_ = 512;
constexpr int DH_  = 192;
constexpr int DR_  = 64;
constexpr int DN_  = 128;
constexpr int DV_  = 128;
constexpr int M_   = B_ * S_;          // 4096
constexpr int KVA_N    = RKV_ + DR_;   // 576
constexpr int KVA_NPAD = 640;
}

// ---------------------------------------------------------------------------
// Scratch (static device globals)
// ---------------------------------------------------------------------------
__device__ float g_qa  [(size_t)M_ * RQ_];
__device__ float g_qb  [(size_t)M_ * H_ * DH_];
__device__ float g_kva [(size_t)M_ * KVA_NPAD];
__device__ float g_kvb [(size_t)M_ * HKV_ * (DN_ + DV_)];
__device__ float g_bkva[KVA_NPAD];
__device__ float g_ct  [S_ * 32];
__device__ float g_st  [S_ * 32];

// pre-split activations (bf16 hi/lo)
__device__ __nv_bfloat16 g_hsh [(size_t)M_ * D_];
__device__ __nv_bfloat16 g_hsl [(size_t)M_ * D_];
__device__ __nv_bfloat16 g_qnh [(size_t)M_ * RQ_];
__device__ __nv_bfloat16 g_qnl [(size_t)M_ * RQ_];
__device__ __nv_bfloat16 g_kvnh[(size_t)M_ * RKV_];
__device__ __nv_bfloat16 g_kvnl[(size_t)M_ * RKV_];
__device__ __nv_bfloat16 g_atth[(size_t)M_ * H_ * DV_];
__device__ __nv_bfloat16 g_attl[(size_t)M_ * H_ * DV_];

// bf16 hi/lo Q/K ([b,h/hkv,s,d]) and V transposed ([b,hkv,d,s])
__device__ __nv_bfloat16 g_Qh [(size_t)B_ * H_   * S_ * DH_];
__device__ __nv_bfloat16 g_Ql [(size_t)B_ * H_   * S_ * DH_];
__device__ __nv_bfloat16 g_Kh [(size_t)B_ * HKV_ * S_ * DH_];
__device__ __nv_bfloat16 g_Kl [(size_t)B_ * HKV_ * S_ * DH_];
__device__ __nv_bfloat16 g_Vth[(size_t)B_ * HKV_ * DV_ * S_];
__device__ __nv_bfloat16 g_Vtl[(size_t)B_ * HKV_ * DV_ * S_];

// Pre-split / transposed weights: [N, K] bf16, hi + lo
__device__ __nv_bfloat16 g_wqa_h [(size_t)RQ_ * D_];
__device__ __nv_bfloat16 g_wqa_l [(size_t)RQ_ * D_];
__device__ __nv_bfloat16 g_wqb_h [(size_t)(H_ * DH_) * RQ_];
__device__ __nv_bfloat16 g_wqb_l [(size_t)(H_ * DH_) * RQ_];
__device__ __nv_bfloat16 g_wkva_h[(size_t)KVA_NPAD * D_];
__device__ __nv_bfloat16 g_wkva_l[(size_t)KVA_NPAD * D_];
__device__ __nv_bfloat16 g_wkvb_h[(size_t)(HKV_ * (DN_ + DV_)) * RKV_];
__device__ __nv_bfloat16 g_wkvb_l[(size_t)(HKV_ * (DN_ + DV_)) * RKV_];
__device__ __nv_bfloat16 g_wo_h  [(size_t)D_ * D_];
__device__ __nv_bfloat16 g_wo_l  [(size_t)D_ * D_];

// ---------------------------------------------------------------------------
// mma.sync / cp.async helpers
// ---------------------------------------------------------------------------
__device__ __forceinline__ uint32_t smem_u32(const void* p) {
    return (uint32_t)__cvta_generic_to_shared(p);
}
__device__ __forceinline__ void ldm_x4(uint32_t* r, uint32_t addr) {
    asm volatile("ldmatrix.sync.aligned.m8n8.x4.shared.b16 {%0,%1,%2,%3}, [%4];"
                 : "=r"(r[0]), "=r"(r[1]), "=r"(r[2]), "=r"(r[3]) : "r"(addr));
}
__device__ __forceinline__ void mma_bf16(float* c, const uint32_t* a, const uint32_t* b) {
    asm volatile("mma.sync.aligned.m16n8k16.row.col.f32.bf16.bf16.f32 "
                 "{%0,%1,%2,%3}, {%4,%5,%6,%7}, {%8,%9}, {%0,%1,%2,%3};"
                 : "+f"(c[0]), "+f"(c[1]), "+f"(c[2]), "+f"(c[3])
                 : "r"(a[0]), "r"(a[1]), "r"(a[2]), "r"(a[3]), "r"(b[0]), "r"(b[1]));
}
__device__ __forceinline__ void cp16(uint32_t dst, const void* src) {
    asm volatile("cp.async.cg.shared.global [%0], [%1], 16;"
                 :: "r"(dst), "l"(__cvta_generic_to_global(src)));
}
__device__ __forceinline__ void cp_commit() {
    asm volatile("cp.async.commit_group;");
}
template <int N_> __device__ __forceinline__ void cp_wait() {
    asm volatile("cp.async.wait_group %0;" :: "n"(N_));
}
__device__ __forceinline__ uint32_t pack_bf2(__nv_bfloat16 a, __nv_bfloat16 b) {
    return (uint32_t)__bfloat16_as_ushort(a) | ((uint32_t)__bfloat16_as_ushort(b) << 16);
}
__device__ __forceinline__ uint32_t pack_hi2(float x, float y) {
    return pack_bf2(__float2bfloat16(x), __float2bfloat16(y));
}
__device__ __forceinline__ uint32_t pack_lo2(float x, float y) {
    __nv_bfloat16 hx = __float2bfloat16(x), hy = __float2bfloat16(y);
    return pack_bf2(__float2bfloat16(x - __bfloat162float(hx)),
                    __float2bfloat16(y - __bfloat162float(hy)));
}
__device__ __forceinline__ void split_store(__nv_bfloat16* Hh, __nv_bfloat16* Ll,
                                            size_t idx, float v) {
    __nv_bfloat16 h = __float2bfloat16(v);
    Hh[idx] = h;
    Ll[idx] = __float2bfloat16(v - __bfloat162float(h));
}

// ---------------------------------------------------------------------------
// Prep kernels
// ---------------------------------------------------------------------------
__global__ void prep_w(const float* __restrict__ W, __nv_bfloat16* __restrict__ Hh,
                       __nv_bfloat16* __restrict__ Ll, int K, int N, int Npad) {
    __shared__ float t[32][33];
    const int kb = blockIdx.x * 32, nb = blockIdx.y * 32;
    const int tx = threadIdx.x, ty = threadIdx.y;
    #pragma unroll
    for (int i = 0; i < 4; ++i) {
        int k = kb + ty + i * 8;
        int n = nb + tx;
        t[ty + i * 8][tx] = (n < N) ? W[(size_t)k * N + n] : 0.f;
    }
    __syncthreads();
    #pragma unroll
    for (int i = 0; i < 4; ++i) {
        int n = nb + ty + i * 8;
        if (n >= Npad) continue;
        int k = kb + tx;
        split_store(Hh, Ll, (size_t)n * K + k, t[tx][ty + i * 8]);
    }
}

__global__ void pad_bias_kva(const float* __restrict__ b) {
    int i = threadIdx.x + blockIdx.x * blockDim.x;
    if (i < KVA_NPAD) g_bkva[i] = (i < KVA_N) ? b[i] : 0.f;
}

__global__ void rope_table() {
    int i = blockIdx.x * blockDim.x + threadIdx.x;
    if (i >= S_ * 32) return;
    int s = i >> 5, fi = i & 31;
    float ang = (float)s * powf(10000.0f, -(float)(2 * fi) / 64.0f);
    g_ct[i] = cosf(ang);
    g_st[i] = sinf(ang);
}

__global__ void split_act4(const float4* __restrict__ X, uint2* __restrict__ Hh,
                           uint2* __restrict__ Ll, size_t n4) {
    size_t i = (size_t)blockIdx.x * blockDim.x + threadIdx.x;
    if (i >= n4) return;
    float4 v = X[i];
    Hh[i] = make_uint2(pack_hi2(v.x, v.y), pack_hi2(v.z, v.w));
    Ll[i] = make_uint2(pack_lo2(v.x, v.y), pack_lo2(v.z, v.w));
}

// ---------------------------------------------------------------------------
// HMMA GEMM, 4-stage cp.async pipeline, k-chunk 16.
// C[M,N] = (Ah+Al)[M,K] @ (Bh+Bl)[N,K]^T + bias   (3-product hi/lo, fp32 acc)
// Tiles 128x128; 8 warps 4(m)x2(n) each 32x64. Stage = 24.6KB, 4 stages =
// 96KB -> 2 blocks/SM. Always 3 cp.async groups outstanding (wait_group<2>).
// ---------------------------------------------------------------------------
constexpr int ASTRIDE = 24;                        // uint16 per row (48B: 16 elts + pad)
constexpr int GARR    = 128 * ASTRIDE;             // uint16 per array per stage
constexpr int STAGEB  = 4 * GARR * 2;              // bytes per stage (4 arrays)
constexpr int GEMM_SMEM2 = 4 * STAGEB;             // 98304 bytes

__global__ void __launch_bounds__(256)
gemm_mma2(const __nv_bfloat16* __restrict__ Agh, const __nv_bfloat16* __restrict__ Agl,
          const __nv_bfloat16* __restrict__ Bgh, const __nv_bfloat16* __restrict__ Bgl,
          const float* __restrict__ bias, float* __restrict__ C,
          int M, int N, int K) {
    extern __shared__ __align__(16) uint16_t gs[];
    const int tid  = threadIdx.x;
    const int lane = tid & 31;
    const int wid  = tid >> 5;
    const int wm   = wid & 3;
    const int wn   = wid >> 2;
    const int row0 = blockIdx.y * 128, col0 = blockIdx.x * 128;
    const uint32_t sb = smem_u32(gs);

    float acc[2][8][4];
    #pragma unroll
    for (int i = 0; i < 2; ++i)
        #pragma unroll
        for (int j = 0; j < 8; ++j)
            #pragma unroll
            for (int q = 0; q < 4; ++q) acc[i][j][q] = 0.f;

    const int a_row = ((lane >> 3) & 1) * 8 + (lane & 7);
    const int a_kof = (lane >> 4) * 8;
    const int b_row = (lane >> 4) * 8 + (lane & 7);
    const int b_kof = ((lane >> 3) & 1) * 8;

    const int nch = K >> 4;    // k-chunk = 16

    auto prefetch = [&](int c) {
        const int k0 = c << 4;
        const int s = c & 3;
        #pragma unroll
        for (int it = 0; it < 4; ++it) {
            int idx = tid + it * 256;           // 0..1023
            int arr = idx >> 8;                 // 0 Ah, 1 Al, 2 Bh, 3 Bl
            int j   = idx & 255;
            int r   = j >> 1, q = j & 1;        // row, 8-elt segment
            const __nv_bfloat16* src = (arr == 0) ? Agh : (arr == 1) ? Agl
                                     : (arr == 2) ? Bgh : Bgl;
            size_t goff = (size_t)(((arr < 2) ? row0 : col0) + r) * K + k0 + q * 8;
            uint32_t dst = sb + (uint32_t)(s * STAGEB) +
                           (uint32_t)(arr * GARR + r * ASTRIDE + q * 8) * 2;
            cp16(dst, src + goff);
        }
        cp_commit();
    };

    prefetch(0); prefetch(1); prefetch(2);      // nch >= 32 for all calls here
    for (int c = 0; c < nch; ++c) {
        cp_wait<2>();                           // oldest of 3 outstanding done
        __syncthreads();
        if (c + 3 < nch) prefetch(c + 3);
        else             cp_commit();           // empty group keeps accounting exact

        const uint32_t base = sb + (uint32_t)((c & 3) * STAGEB);
        const uint32_t sAh = base;
        const uint32_t sAl = base + (uint32_t)GARR * 2;
        const uint32_t sBh = base + (uint32_t)GARR * 4;
        const uint32_t sBl = base + (uint32_t)GARR * 6;

        uint32_t a_h[2][4], a_l[2][4];
        #pragma unroll
        for (int mi = 0; mi < 2; ++mi) {
            int r = wm * 32 + mi * 16 + a_row;
            uint32_t off = (uint32_t)(r * ASTRIDE + a_kof) * 2;
            ldm_x4(a_h[mi], sAh + off);
            ldm_x4(a_l[mi], sAl + off);
        }
        #pragma unroll
        for (int nb = 0; nb < 4; ++nb) {
            int n = wn * 64 + nb * 16 + b_row;
            uint32_t off = (uint32_t)(n * ASTRIDE + b_kof) * 2;
            uint32_t b_h[4], b_l[4];
            ldm_x4(b_h, sBh + off);
            ldm_x4(b_l, sBl + off);
            #pragma unroll
            for (int mi = 0; mi < 2; ++mi) {
                mma_bf16(acc[mi][nb * 2 + 0], a_h[mi], b_h + 0);
                mma_bf16(acc[mi][nb * 2 + 1], a_h[mi], b_h + 2);
                mma_bf16(acc[mi][nb * 2 + 0], a_h[mi], b_l + 0);
                mma_bf16(acc[mi][nb * 2 + 1], a_h[mi], b_l + 2);
                mma_bf16(acc[mi][nb * 2 + 0], a_l[mi], b_h + 0);
                mma_bf16(acc[mi][nb * 2 + 1], a_l[mi], b_h + 2);
            }
        }
    }

    #pragma unroll
    for (int mi = 0; mi < 2; ++mi) {
        int r = row0 + wm * 32 + mi * 16 + (lane >> 2);
        #pragma unroll
        for (int nj = 0; nj < 8; ++nj) {
            int c = col0 + wn * 64 + nj * 8 + (lane & 3) * 2;
            float2 b2 = *reinterpret_cast<const float2*>(bias + c);
            float2 o0, o1;
            o0.x = acc[mi][nj][0] + b2.x;
            o0.y = acc[mi][nj][1] + b2.y;
            o1.x = acc[mi][nj][2] + b2.x;
            o1.y = acc[mi][nj][3] + b2.y;
            *reinterpret_cast<float2*>(C + (size_t)r * N + c)       = o0;
            *reinterpret_cast<float2*>(C + (size_t)(r + 8) * N + c) = o1;
        }
    }
}

// ---------------------------------------------------------------------------
// RMSNorm with fused hi/lo split output
// ---------------------------------------------------------------------------
__global__ void rmsnorm_split(const float* __restrict__ in, const float* __restrict__ g,
                              __nv_bfloat16* __restrict__ oh, __nv_bfloat16* __restrict__ ol,
                              int ncols, int in_stride) {
    const int row = blockIdx.x;
    const float* x = in + (size_t)row * in_stride;
    float ss = 0.f;
    for (int c = threadIdx.x; c < ncols; c += blockDim.x) {
        float v = x[c];
        ss += v * v;
    }
    __shared__ float red[32];
    #pragma unroll
    for (int o = 16; o > 0; o >>= 1) ss += __shfl_xor_sync(0xffffffff, ss, o);
    if ((threadIdx.x & 31) == 0) red[threadIdx.x >> 5] = ss;
    __syncthreads();
    __shared__ float s_scale;
    if (threadIdx.x == 0) {
        float t = 0.f;
        int nw = blockDim.x >> 5;
        for (int i = 0; i < nw; ++i) t += red[i];
        s_scale = 1.0f / sqrtf(t / (float)ncols + 1e-20f);
    }
    __syncthreads();
    const float sc = s_scale;
    size_t base = (size_t)row * ncols;
    for (int c = threadIdx.x; c < ncols; c += blockDim.x)
        split_store(oh, ol, base + c, x[c] * sc * g[c]);
}

// ---------------------------------------------------------------------------
// Assembles (table RoPE) -> bf16 hi/lo
// ---------------------------------------------------------------------------
__global__ void assemble_q() {
    size_t idx = (size_t)blockIdx.x * blockDim.x + threadIdx.x;
    constexpr size_t total = (size_t)B_ * H_ * S_ * DH_;
    if (idx >= total) return;
    int d = (int)(idx % DH_);
    int s = (int)((idx / DH_) % S_);
    int h = (int)((idx / ((size_t)DH_ * S_)) % H_);
    int b = (int)(idx / ((size_t)DH_ * S_ * H_));
    const float* row = g_qb + ((size_t)(b * S_ + s)) * (H_ * DH_) + h * DH_;
    float val;
    if (d >= DR_) {
        val = row[d - DR_];
    } else {
        int fi = d & 31;
        float x   = row[DN_ + d];
        float rot = (d < 32) ? -row[DN_ + d + 32] : row[DN_ + d - 32];
        val = x * g_ct[s * 32 + fi] + rot * g_st[s * 32 + fi];
    }
    split_store(g_Qh, g_Ql, idx, val);
}

__global__ void assemble_kv() {
    constexpr size_t total_k = (size_t)B_ * HKV_ * S_ * DH_;
    constexpr size_t total_v = (size_t)B_ * HKV_ * DV_ * S_;
    size_t idx = (size_t)blockIdx.x * blockDim.x + threadIdx.x;
    if (idx < total_k) {
        int d  = (int)(idx % DH_);
        int s  = (int)((idx / DH_) % S_);
        int hk = (int)((idx / ((size_t)DH_ * S_)) % HKV_);
        int b  = (int)(idx / ((size_t)DH_ * S_ * HKV_));
        float val;
        if (d >= DR_) {
            val = g_kvb[(size_t)(b * S_ + s) * (HKV_ * (DN_ + DV_)) + hk * (DN_ + DV_) + (d - DR_)];
        } else {
            int fi = d & 31;
            const float* kr = g_kva + (size_t)(b * S_ + s) * KVA_NPAD + RKV_;
            float x   = kr[d];
            float rot = (d < 32) ? -kr[d + 32] : kr[d - 32];
            val = x * g_ct[s * 32 + fi] + rot * g_st[s * 32 + fi];
        }
        split_store(g_Kh, g_Kl, idx, val);
    } else if (idx < total_k + total_v) {
        size_t j = idx - total_k;
        int s  = (int)(j % S_);
        int d  = (int)((j / S_) % DV_);
        int hk = (int)((j / ((size_t)S_ * DV_)) % HKV_);
        int b  = (int)(j / ((size_t)S_ * DV_ * HKV_));
        float v = g_kvb[(size_t)(b * S_ + s) * (HKV_ * (DN_ + DV_)) + hk * (DN_ + DV_) + DN_ + d];
        split_store(g_Vth, g_Vtl, j, v);
    }
}

// ---------------------------------------------------------------------------
// Flash attention on mma.sync bf16 hi/lo (R7-proven version: pre-split Q).
// ---------------------------------------------------------------------------
constexpr int FA_QSTR = 200;
constexpr int FA_VSTR = 72;
constexpr int FA_SMEM = (2 * 128 * FA_QSTR + 2 * 64 * FA_QSTR + 2 * 128 * FA_VSTR) * 2;

__global__ void __launch_bounds__(256, 1)
flash_mma() {
    extern __shared__ __align__(16) uint16_t fs[];
    uint16_t* Qh = fs;
    uint16_t* Ql = Qh + 128 * FA_QSTR;
    uint16_t* Kh = Ql + 128 * FA_QSTR;
    uint16_t* Kl = Kh + 64 * FA_QSTR;
    uint16_t* Vh = Kl + 64 * FA_QSTR;
    uint16_t* Vl = Vh + 128 * FA_VSTR;

    const int bh = blockIdx.x;
    const int b  = bh / H_;
    const int h  = bh % H_;
    const int hkv = h / G_;
    const int qb = (int)gridDim.y - 1 - (int)blockIdx.y;
    const int q0 = qb * 128;

    const int tid  = threadIdx.x;
    const int lane = tid & 31;
    const int wid  = tid >> 5;

    const __nv_bfloat16* Qhg = g_Qh + ((size_t)(b * H_ + h) * S_) * DH_;
    const __nv_bfloat16* Qlg = g_Ql + ((size_t)(b * H_ + h) * S_) * DH_;
    const __nv_bfloat16* Khg = g_Kh + ((size_t)(b * HKV_ + hkv) * S_) * DH_;
    const __nv_bfloat16* Klg = g_Kl + ((size_t)(b * HKV_ + hkv) * S_) * DH_;
    const __nv_bfloat16* Vhg = g_Vth + ((size_t)(b * HKV_ + hkv) * DV_) * S_;
    const __nv_bfloat16* Vlg = g_Vtl + ((size_t)(b * HKV_ + hkv) * DV_) * S_;

    {
        int r = tid >> 1, half = tid & 1;
        #pragma unroll
        for (int i = 0; i < 12; ++i) {
            int q = half * 12 + i;
            *reinterpret_cast<uint4*>(Qh + r * FA_QSTR + q * 8) =
                *reinterpret_cast<const uint4*>(Qhg + (size_t)(q0 + r) * DH_ + q * 8);
            *reinterpret_cast<uint4*>(Ql + r * FA_QSTR + q * 8) =
                *reinterpret_cast<const uint4*>(Qlg + (size_t)(q0 + r) * DH_ + q * 8);
        }
    }

    const int a_row = ((lane >> 3) & 1) * 8 + (lane & 7);
    const int a_kof = (lane >> 4) * 8;
    const int b_row = (lane >> 4) * 8 + (lane & 7);
    const int b_kof = ((lane >> 3) & 1) * 8;
    const int rl = lane >> 2, cb = (lane & 3) * 2;
    const int rg0 = q0 + wid * 16 + rl;
    const float scale = rsqrtf((float)DH_);

    float accO[8][2][4];
    #pragma unroll
    for (int i = 0; i < 8; ++i)
        #pragma unroll
        for (int j = 0; j < 2; ++j)
            #pragma unroll
            for (int q = 0; q < 4; ++q) accO[i][j][q] = 0.f;
    float m0 = -1e30f, m1 = -1e30f, l0 = 0.f, l1 = 0.f;

    const int T = 2 * (qb + 1);
    for (int t = 0; t < T; ++t) {
        const int j0 = t * 64;
        __syncthreads();
        {
            int r = tid >> 2, part = tid & 3;
            #pragma unroll
            for (int i = 0; i < 6; ++i) {
                int q = part * 6 + i;
                *reinterpret_cast<uint4*>(Kh + r * FA_QSTR + q * 8) =
                    *reinterpret_cast<const uint4*>(Khg + (size_t)(j0 + r) * DH_ + q * 8);
                *reinterpret_cast<uint4*>(Kl + r * FA_QSTR + q * 8) =
                    *reinterpret_cast<const uint4*>(Klg + (size_t)(j0 + r) * DH_ + q * 8);
            }
        }
        {
            int r = tid >> 1, part = tid & 1;
            #pragma unroll
            for (int i = 0; i < 4; ++i) {
                int q = part * 4 + i;
                *reinterpret_cast<uint4*>(Vh + r * FA_VSTR + q * 8) =
                    *reinterpret_cast<const uint4*>(Vhg + (size_t)r * S_ + j0 + q * 8);
                *reinterpret_cast<uint4*>(Vl + r * FA_VSTR + q * 8) =
                    *reinterpret_cast<const uint4*>(Vlg + (size_t)r * S_ + j0 + q * 8);
            }
        }
        __syncthreads();

        float Sc[4][2][4];
        #pragma unroll
        for (int i = 0; i < 4; ++i)
            #pragma unroll
            for (int j = 0; j < 2; ++j)
                #pragma unroll
                for (int q = 0; q < 4; ++q) Sc[i][j][q] = 0.f;

        #pragma unroll
        for (int ks = 0; ks < 12; ++ks) {
            uint32_t ah[4], al[4];
            uint32_t qoff = (uint32_t)((wid * 16 + a_row) * FA_QSTR + ks * 16 + a_kof) * 2;
            ldm_x4(ah, smem_u32(Qh) + qoff);
            ldm_x4(al, smem_u32(Ql) + qoff);
            #pragma unroll
            for (int nb = 0; nb < 4; ++nb) {
                uint32_t koff = (uint32_t)((nb * 16 + b_row) * FA_QSTR + ks * 16 + b_kof) * 2;
                uint32_t bh4[4], bl4[4];
                ldm_x4(bh4, smem_u32(Kh) + koff);
                ldm_x4(bl4, smem_u32(Kl) + koff);
                mma_bf16(Sc[nb][0], ah, bh4 + 0);
                mma_bf16(Sc[nb][1], ah, bh4 + 2);
                mma_bf16(Sc[nb][0], ah, bl4 + 0);
                mma_bf16(Sc[nb][1], ah, bl4 + 2);
                mma_bf16(Sc[nb][0], al, bh4 + 0);
                mma_bf16(Sc[nb][1], al, bh4 + 2);
            }
        }

        const bool domask = (j0 + 63) > (q0 + wid * 16);
        #pragma unroll
        for (int nb = 0; nb < 4; ++nb)
            #pragma unroll
            for (int mm = 0; mm < 2; ++mm) {
                int c = j0 + nb * 16 + mm * 8 + cb;
                float* s4 = Sc[nb][mm];
                s4[0] *= scale; s4[1] *= scale; s4[2] *= scale; s4[3] *= scale;
                if (domask) {
                    if (c     > rg0)     s4[0] = -1e30f;
                    if (c + 1 > rg0)     s4[1] = -1e30f;
                    if (c     > rg0 + 8) s4[2] = -1e30f;
                    if (c + 1 > rg0 + 8) s4[3] = -1e30f;
                }
            }

        float mx0 = -1e30f, mx1 = -1e30f;
        #pragma unroll
        for (int nb = 0; nb < 4; ++nb)
            #pragma unroll
            for (int mm = 0; mm < 2; ++mm) {
                mx0 = fmaxf(mx0, fmaxf(Sc[nb][mm][0], Sc[nb][mm][1]));
                mx1 = fmaxf(mx1, fmaxf(Sc[nb][mm][2], Sc[nb][mm][3]));
            }
        mx0 = fmaxf(mx0, __shfl_xor_sync(0xffffffff, mx0, 1));
        mx0 = fmaxf(mx0, __shfl_xor_sync(0xffffffff, mx0, 2));
        mx1 = fmaxf(mx1, __shfl_xor_sync(0xffffffff, mx1, 1));
        mx1 = fmaxf(mx1, __shfl_xor_sync(0xffffffff, mx1, 2));
        float mn0 = fmaxf(m0, mx0), mn1 = fmaxf(m1, mx1);
        float corr0 = __expf(m0 - mn0), corr1 = __expf(m1 - mn1);
        m0 = mn0; m1 = mn1;

        uint32_t aPh[4][4], aPl[4][4];
        float sum0 = 0.f, sum1 = 0.f;
        #pragma unroll
        for (int nb = 0; nb < 4; ++nb) {
            float e00, e01, e02, e03, e10, e11, e12, e13;
            e00 = __expf(Sc[nb][0][0] - mn0);  e01 = __expf(Sc[nb][0][1] - mn0);
            e02 = __expf(Sc[nb][0][2] - mn1);  e03 = __expf(Sc[nb][0][3] - mn1);
            e10 = __expf(Sc[nb][1][0] - mn0);  e11 = __expf(Sc[nb][1][1] - mn0);
            e12 = __expf(Sc[nb][1][2] - mn1);  e13 = __expf(Sc[nb][1][3] - mn1);
            sum0 += e00 + e01 + e10 + e11;
            sum1 += e02 + e03 + e12 + e13;
            aPh[nb][0] = pack_hi2(e00, e01);  aPl[nb][0] = pack_lo2(e00, e01);
            aPh[nb][1] = pack_hi2(e02, e03);  aPl[nb][1] = pack_lo2(e02, e03);
            aPh[nb][2] = pack_hi2(e10, e11);  aPl[nb][2] = pack_lo2(e10, e11);
            aPh[nb][3] = pack_hi2(e12, e13);  aPl[nb][3] = pack_lo2(e12, e13);
        }
        sum0 += __shfl_xor_sync(0xffffffff, sum0, 1);
        sum0 += __shfl_xor_sync(0xffffffff, sum0, 2);
        sum1 += __shfl_xor_sync(0xffffffff, sum1, 1);
        sum1 += __shfl_xor_sync(0xffffffff, sum1, 2);
        l0 = l0 * corr0 + sum0;
        l1 = l1 * corr1 + sum1;

        #pragma unroll
        for (int nv = 0; nv < 8; ++nv)
            #pragma unroll
            for (int mm = 0; mm < 2; ++mm) {
                accO[nv][mm][0] *= corr0; accO[nv][mm][1] *= corr0;
                accO[nv][mm][2] *= corr1; accO[nv][mm][3] *= corr1;
            }

        #pragma unroll
        for (int ks = 0; ks < 4; ++ks) {
            #pragma unroll
            for (int nv = 0; nv < 8; ++nv) {
                uint32_t voff = (uint32_t)((nv * 16 + b_row) * FA_VSTR + ks * 16 + b_kof) * 2;
                uint32_t bh4[4], bl4[4];
                ldm_x4(bh4, smem_u32(Vh) + voff);
                ldm_x4(bl4, smem_u32(Vl) + voff);
                mma_bf16(accO[nv][0], aPh[ks], bh4 + 0);
                mma_bf16(accO[nv][1], aPh[ks], bh4 + 2);
                mma_bf16(accO[nv][0], aPh[ks], bl4 + 0);
                mma_bf16(accO[nv][1], aPh[ks], bl4 + 2);
                mma_bf16(accO[nv][0], aPl[ks], bh4 + 0);
                mma_bf16(accO[nv][1], aPl[ks], bh4 + 2);
            }
        }
    }

    const float il0 = 1.0f / l0, il1 = 1.0f / l1;
    #pragma unroll
    for (int nv = 0; nv < 8; ++nv)
        #pragma unroll
        for (int mm = 0; mm < 2; ++mm) {
            int c = nv * 16 + mm * 8 + cb;
            size_t base0 = ((size_t)(b * S_) + rg0)     * (H_ * DV_) + h * DV_ + c;
            size_t base1 = ((size_t)(b * S_) + rg0 + 8) * (H_ * DV_) + h * DV_ + c;
            float x0 = accO[nv][mm][0] * il0, y0 = accO[nv][mm][1] * il0;
            float x1 = accO[nv][mm][2] * il1, y1 = accO[nv][mm][3] * il1;
            *reinterpret_cast<uint32_t*>(g_atth + base0) = pack_hi2(x0, y0);
            *reinterpret_cast<uint32_t*>(g_attl + base0) = pack_lo2(x0, y0);
            *reinterpret_cast<uint32_t*>(g_atth + base1) = pack_hi2(x1, y1);
            *reinterpret_cast<uint32_t*>(g_attl + base1) = pack_lo2(x1, y1);
        }
}

// ---------------------------------------------------------------------------
// Launch sequence (single stream; ordered so ncu -s 5 captures gemm_mma2)
// ---------------------------------------------------------------------------
extern "C" void kernel_launch(void* const* d_in, const int* in_sizes, int n_in,
                              void* d_out, int out_size) {
    const float* hs    = (const float*)d_in[0];
    const float* w_qa  = (const float*)d_in[2];
    const float* b_qa  = (const float*)d_in[3];
    const float* gq    = (const float*)d_in[4];
    const float* w_qb  = (const float*)d_in[5];
    const float* b_qb  = (const float*)d_in[6];
    const float* w_kva = (const float*)d_in[7];
    const float* b_kva = (const float*)d_in[8];
    const float* gkv   = (const float*)d_in[9];
    const float* w_kvb = (const float*)d_in[10];
    const float* b_kvb = (const float*)d_in[11];
    const float* w_o   = (const float*)d_in[12];
    const float* b_o   = (const float*)d_in[13];
    float* out = (float*)d_out;

    float *p_qa, *p_qb, *p_kva, *p_kvb, *p_bkva;
    cudaGetSymbolAddress((void**)&p_qa,   g_qa);
    cudaGetSymbolAddress((void**)&p_qb,   g_qb);
    cudaGetSymbolAddress((void**)&p_kva,  g_kva);
    cudaGetSymbolAddress((void**)&p_kvb,  g_kvb);
    cudaGetSymbolAddress((void**)&p_bkva, g_bkva);
    __nv_bfloat16 *qa_h, *qa_l, *qb_h, *qb_l, *kva_h, *kva_l, *kvb_h, *kvb_l, *o_h, *o_l;
    cudaGetSymbolAddress((void**)&qa_h,  g_wqa_h);  cudaGetSymbolAddress((void**)&qa_l,  g_wqa_l);
    cudaGetSymbolAddress((void**)&qb_h,  g_wqb_h);  cudaGetSymbolAddress((void**)&qb_l,  g_wqb_l);
    cudaGetSymbolAddress((void**)&kva_h, g_wkva_h); cudaGetSymbolAddress((void**)&kva_l, g_wkva_l);
    cudaGetSymbolAddress((void**)&kvb_h, g_wkvb_h); cudaGetSymbolAddress((void**)&kvb_l, g_wkvb_l);
    cudaGetSymbolAddress((void**)&o_h,   g_wo_h);   cudaGetSymbolAddress((void**)&o_l,   g_wo_l);
    __nv_bfloat16 *hs_h, *hs_l, *qn_h, *qn_l, *kvn_h, *kvn_l, *att_h, *att_l;
    cudaGetSymbolAddress((void**)&hs_h,  g_hsh);  cudaGetSymbolAddress((void**)&hs_l,  g_hsl);
    cudaGetSymbolAddress((void**)&qn_h,  g_qnh);  cudaGetSymbolAddress((void**)&qn_l,  g_qnl);
    cudaGetSymbolAddress((void**)&kvn_h, g_kvnh); cudaGetSymbolAddress((void**)&kvn_l, g_kvnl);
    cudaGetSymbolAddress((void**)&att_h, g_atth); cudaGetSymbolAddress((void**)&att_l, g_attl);

    cudaFuncSetAttribute(flash_mma, cudaFuncAttributeMaxDynamicSharedMemorySize, FA_SMEM);
    cudaFuncSetAttribute(gemm_mma2, cudaFuncAttributeMaxDynamicSharedMemorySize, GEMM_SMEM2);

    dim3 tb(32, 8);
    // launches 1-5 (order matters: ncu -s 5 -c 1 captures launch #6 = gemm qa)
    prep_w<<<dim3(D_ / 32,  RQ_ / 32), tb>>>(w_qa, qa_h, qa_l, D_, RQ_, RQ_);          // 1
    {
        constexpr size_t n4 = (size_t)M_ * D_ / 4;
        split_act4<<<(unsigned)((n4 + 255) / 256), 256>>>(
            (const float4*)hs, (uint2*)hs_h, (uint2*)hs_l, n4);                        // 2
    }
    pad_bias_kva<<<(KVA_NPAD + 255) / 256, 256>>>(b_kva);                              // 3
    prep_w<<<dim3(D_ / 32,  KVA_NPAD / 32), tb>>>(w_kva, kva_h, kva_l, D_, KVA_N, KVA_NPAD); // 4
    prep_w<<<dim3(RQ_ / 32, (H_ * DH_) / 32), tb>>>(w_qb, qb_h, qb_l, RQ_, H_ * DH_, H_ * DH_); // 5

    // 6: profiled GEMM
    gemm_mma2<<<dim3(RQ_ / 128, M_ / 128), 256, GEMM_SMEM2>>>(hs_h, hs_l, qa_h, qa_l, b_qa, p_qa, M_, RQ_, D_);

    prep_w<<<dim3(RKV_ / 32, (HKV_ * 256) / 32), tb>>>(w_kvb, kvb_h, kvb_l, RKV_, HKV_ * 256, HKV_ * 256);
    rope_table<<<(S_ * 32 + 255) / 256, 256>>>();

    rmsnorm_split<<<M_, 256>>>(p_qa, gq, qn_h, qn_l, RQ_, RQ_);
    gemm_mma2<<<dim3((H_ * DH_) / 128, M_ / 128), 256, GEMM_SMEM2>>>(qn_h, qn_l, qb_h, qb_l, b_qb, p_qb, M_, H_ * DH_, RQ_);
    gemm_mma2<<<dim3(KVA_NPAD / 128, M_ / 128), 256, GEMM_SMEM2>>>(hs_h, hs_l, kva_h, kva_l, p_bkva, p_kva, M_, KVA_NPAD, D_);
    rmsnorm_split<<<M_, 256>>>(p_kva, gkv, kvn_h, kvn_l, RKV_, KVA_NPAD);
    gemm_mma2<<<dim3((HKV_ * 256) / 128, M_ / 128), 256, GEMM_SMEM2>>>(kvn_h, kvn_l, kvb_h, kvb_l, b_kvb, p_kvb, M_, HKV_ * 256, RKV_);

    // assembles (Q separate — R7-proven; K/V merged)
    {
        constexpr size_t tq = (size_t)B_ * H_ * S_ * DH_;
        assemble_q<<<(unsigned)((tq + 255) / 256), 256>>>();
        constexpr size_t tkv = (size_t)B_ * HKV_ * S_ * DH_ + (size_t)B_ * HKV_ * DV_ * S_;
        assemble_kv<<<(unsigned)((tkv + 255) / 256), 256>>>();
    }

    // attention + output projection
    flash_mma<<<dim3(B_ * H_, S_ / 128), 256, FA_SMEM>>>();
    prep_w<<<dim3(D_ / 32, D_ / 32), tb>>>(w_o, o_h, o_l, D_, D_, D_);
    gemm_mma2<<<dim3(D_ / 128, M_ / 128), 256, GEMM_SMEM2>>>(
        att_h, att_l, o_h, o_l, b_o, out, M_, D_, D_);
}

// round 13
// speedup vs baseline: 1.0702x; 1.0702x over previous
#include <cuda_runtime.h>
#include <cuda_bf16.h>
#include <cstdint>
#include <math.h>

// ---------------------------------------------------------------------------
// Problem constants
// ---------------------------------------------------------------------------
namespace {
constexpr int B_   = 2;
constexpr int S_   = 2048;
constexpr int D_   = 2048;
constexpr int H_   = 16;
constexpr int HKV_ = 4;
constexpr int G_   = H_ / HKV_;
constexpr int RQ_  = 1024;
constexpr int RKV_ = 512;
constexpr int DH_  = 192;
constexpr int DR_  = 64;
constexpr int DN_  = 128;
constexpr int DV_  = 128;
constexpr int M_   = B_ * S_;          // 4096
constexpr int KVA_N    = RKV_ + DR_;   // 576
constexpr int KVA_NPAD = 640;
}

// ---------------------------------------------------------------------------
// Scratch (static device globals)
// ---------------------------------------------------------------------------
__device__ float g_qa  [(size_t)M_ * RQ_];
__device__ float g_qb  [(size_t)M_ * H_ * DH_];
__device__ float g_kva [(size_t)M_ * KVA_NPAD];
__device__ float g_kvb [(size_t)M_ * HKV_ * (DN_ + DV_)];
__device__ float g_bkva[KVA_NPAD];
__device__ float g_ct  [S_ * 32];
__device__ float g_st  [S_ * 32];

// pre-split activations (bf16 hi/lo)
__device__ __nv_bfloat16 g_hsh [(size_t)M_ * D_];
__device__ __nv_bfloat16 g_hsl [(size_t)M_ * D_];
__device__ __nv_bfloat16 g_qnh [(size_t)M_ * RQ_];
__device__ __nv_bfloat16 g_qnl [(size_t)M_ * RQ_];
__device__ __nv_bfloat16 g_kvnh[(size_t)M_ * RKV_];
__device__ __nv_bfloat16 g_kvnl[(size_t)M_ * RKV_];
__device__ __nv_bfloat16 g_atth[(size_t)M_ * H_ * DV_];
__device__ __nv_bfloat16 g_attl[(size_t)M_ * H_ * DV_];

// bf16 hi/lo Q/K ([b,h/hkv,s,d]) and V transposed ([b,hkv,d,s])
__device__ __nv_bfloat16 g_Qh [(size_t)B_ * H_   * S_ * DH_];
__device__ __nv_bfloat16 g_Ql [(size_t)B_ * H_   * S_ * DH_];
__device__ __nv_bfloat16 g_Kh [(size_t)B_ * HKV_ * S_ * DH_];
__device__ __nv_bfloat16 g_Kl [(size_t)B_ * HKV_ * S_ * DH_];
__device__ __nv_bfloat16 g_Vth[(size_t)B_ * HKV_ * DV_ * S_];
__device__ __nv_bfloat16 g_Vtl[(size_t)B_ * HKV_ * DV_ * S_];

// Pre-split / transposed weights: [N, K] bf16, hi + lo
__device__ __nv_bfloat16 g_wqa_h [(size_t)RQ_ * D_];
__device__ __nv_bfloat16 g_wqa_l [(size_t)RQ_ * D_];
__device__ __nv_bfloat16 g_wqb_h [(size_t)(H_ * DH_) * RQ_];
__device__ __nv_bfloat16 g_wqb_l [(size_t)(H_ * DH_) * RQ_];
__device__ __nv_bfloat16 g_wkva_h[(size_t)KVA_NPAD * D_];
__device__ __nv_bfloat16 g_wkva_l[(size_t)KVA_NPAD * D_];
__device__ __nv_bfloat16 g_wkvb_h[(size_t)(HKV_ * (DN_ + DV_)) * RKV_];
__device__ __nv_bfloat16 g_wkvb_l[(size_t)(HKV_ * (DN_ + DV_)) * RKV_];
__device__ __nv_bfloat16 g_wo_h  [(size_t)D_ * D_];
__device__ __nv_bfloat16 g_wo_l  [(size_t)D_ * D_];

// ---------------------------------------------------------------------------
// mma.sync / cp.async helpers
// ---------------------------------------------------------------------------
__device__ __forceinline__ uint32_t smem_u32(const void* p) {
    return (uint32_t)__cvta_generic_to_shared(p);
}
__device__ __forceinline__ void ldm_x4(uint32_t* r, uint32_t addr) {
    asm volatile("ldmatrix.sync.aligned.m8n8.x4.shared.b16 {%0,%1,%2,%3}, [%4];"
                 : "=r"(r[0]), "=r"(r[1]), "=r"(r[2]), "=r"(r[3]) : "r"(addr));
}
__device__ __forceinline__ void mma_bf16(float* c, const uint32_t* a, const uint32_t* b) {
    asm volatile("mma.sync.aligned.m16n8k16.row.col.f32.bf16.bf16.f32 "
                 "{%0,%1,%2,%3}, {%4,%5,%6,%7}, {%8,%9}, {%0,%1,%2,%3};"
                 : "+f"(c[0]), "+f"(c[1]), "+f"(c[2]), "+f"(c[3])
                 : "r"(a[0]), "r"(a[1]), "r"(a[2]), "r"(a[3]), "r"(b[0]), "r"(b[1]));
}
__device__ __forceinline__ void cp16(uint32_t dst, const void* src) {
    asm volatile("cp.async.cg.shared.global [%0], [%1], 16;"
                 :: "r"(dst), "l"(__cvta_generic_to_global(src)));
}
__device__ __forceinline__ void cp_commit() {
    asm volatile("cp.async.commit_group;");
}
template <int N_> __device__ __forceinline__ void cp_wait() {
    asm volatile("cp.async.wait_group %0;" :: "n"(N_));
}
__device__ __forceinline__ uint32_t pack_bf2(__nv_bfloat16 a, __nv_bfloat16 b) {
    return (uint32_t)__bfloat16_as_ushort(a) | ((uint32_t)__bfloat16_as_ushort(b) << 16);
}
__device__ __forceinline__ uint32_t pack_hi2(float x, float y) {
    return pack_bf2(__float2bfloat16(x), __float2bfloat16(y));
}
__device__ __forceinline__ uint32_t pack_lo2(float x, float y) {
    __nv_bfloat16 hx = __float2bfloat16(x), hy = __float2bfloat16(y);
    return pack_bf2(__float2bfloat16(x - __bfloat162float(hx)),
                    __float2bfloat16(y - __bfloat162float(hy)));
}
__device__ __forceinline__ void split_store(__nv_bfloat16* Hh, __nv_bfloat16* Ll,
                                            size_t idx, float v) {
    __nv_bfloat16 h = __float2bfloat16(v);
    Hh[idx] = h;
    Ll[idx] = __float2bfloat16(v - __bfloat162float(h));
}
// vectorized: split 4 consecutive values, store as uint2 to both arrays
__device__ __forceinline__ void split_store4(__nv_bfloat16* Hh, __nv_bfloat16* Ll,
                                             size_t idx, const float* v) {
    *reinterpret_cast<uint2*>(Hh + idx) = make_uint2(pack_hi2(v[0], v[1]), pack_hi2(v[2], v[3]));
    *reinterpret_cast<uint2*>(Ll + idx) = make_uint2(pack_lo2(v[0], v[1]), pack_lo2(v[2], v[3]));
}

// ---------------------------------------------------------------------------
// Prep kernels
// ---------------------------------------------------------------------------
__global__ void prep_w(const float* __restrict__ W, __nv_bfloat16* __restrict__ Hh,
                       __nv_bfloat16* __restrict__ Ll, int K, int N, int Npad) {
    __shared__ float t[32][33];
    const int kb = blockIdx.x * 32, nb = blockIdx.y * 32;
    const int tx = threadIdx.x, ty = threadIdx.y;
    #pragma unroll
    for (int i = 0; i < 4; ++i) {
        int k = kb + ty + i * 8;
        int n = nb + tx;
        t[ty + i * 8][tx] = (n < N) ? W[(size_t)k * N + n] : 0.f;
    }
    __syncthreads();
    #pragma unroll
    for (int i = 0; i < 4; ++i) {
        int n = nb + ty + i * 8;
        if (n >= Npad) continue;
        int k = kb + tx;
        split_store(Hh, Ll, (size_t)n * K + k, t[tx][ty + i * 8]);
    }
}

__global__ void pad_bias_kva(const float* __restrict__ b) {
    int i = threadIdx.x + blockIdx.x * blockDim.x;
    if (i < KVA_NPAD) g_bkva[i] = (i < KVA_N) ? b[i] : 0.f;
}

__global__ void rope_table() {
    int i = blockIdx.x * blockDim.x + threadIdx.x;
    if (i >= S_ * 32) return;
    int s = i >> 5, fi = i & 31;
    float ang = (float)s * powf(10000.0f, -(float)(2 * fi) / 64.0f);
    g_ct[i] = cosf(ang);
    g_st[i] = sinf(ang);
}

__global__ void split_act4(const float4* __restrict__ X, uint2* __restrict__ Hh,
                           uint2* __restrict__ Ll, size_t n4) {
    size_t i = (size_t)blockIdx.x * blockDim.x + threadIdx.x;
    if (i >= n4) return;
    float4 v = X[i];
    Hh[i] = make_uint2(pack_hi2(v.x, v.y), pack_hi2(v.z, v.w));
    Ll[i] = make_uint2(pack_lo2(v.x, v.y), pack_lo2(v.z, v.w));
}

// ---------------------------------------------------------------------------
// HMMA GEMM (R7-proven): 2-stage cp.async, k-chunk 32, one sync per chunk.
// ---------------------------------------------------------------------------
constexpr int ASTRIDE = 40;
constexpr int GARR    = 128 * ASTRIDE;
constexpr int GEMM_SMEM2 = 2 * 4 * GARR * 2;

__global__ void __launch_bounds__(256)
gemm_mma2(const __nv_bfloat16* __restrict__ Agh, const __nv_bfloat16* __restrict__ Agl,
          const __nv_bfloat16* __restrict__ Bgh, const __nv_bfloat16* __restrict__ Bgl,
          const float* __restrict__ bias, float* __restrict__ C,
          int M, int N, int K) {
    extern __shared__ __align__(16) uint16_t gs[];
    const int tid  = threadIdx.x;
    const int lane = tid & 31;
    const int wid  = tid >> 5;
    const int wm   = wid & 3;
    const int wn   = wid >> 2;
    const int row0 = blockIdx.y * 128, col0 = blockIdx.x * 128;
    const uint32_t sb = smem_u32(gs);

    float acc[2][8][4];
    #pragma unroll
    for (int i = 0; i < 2; ++i)
        #pragma unroll
        for (int j = 0; j < 8; ++j)
            #pragma unroll
            for (int q = 0; q < 4; ++q) acc[i][j][q] = 0.f;

    const int a_row = ((lane >> 3) & 1) * 8 + (lane & 7);
    const int a_kof = (lane >> 4) * 8;
    const int b_row = (lane >> 4) * 8 + (lane & 7);
    const int b_kof = ((lane >> 3) & 1) * 8;

    const int nch = K >> 5;

    auto prefetch = [&](int c) {
        const int k0 = c << 5;
        const int s = c & 1;
        #pragma unroll
        for (int it = 0; it < 8; ++it) {
            int idx = tid + it * 256;
            int arr = idx >> 9;
            int j   = idx & 511;
            int r   = j >> 2, q = j & 3;
            const __nv_bfloat16* src = (arr == 0) ? Agh : (arr == 1) ? Agl
                                     : (arr == 2) ? Bgh : Bgl;
            size_t goff = (size_t)(((arr < 2) ? row0 : col0) + r) * K + k0 + q * 8;
            uint32_t dst = sb + (uint32_t)(((s * 4 + arr) * 128 + r) * ASTRIDE + q * 8) * 2;
            cp16(dst, src + goff);
        }
        cp_commit();
    };

    prefetch(0);
    for (int c = 0; c < nch; ++c) {
        cp_wait<0>();
        __syncthreads();
        if (c + 1 < nch) prefetch(c + 1);

        const uint32_t base = sb + (uint32_t)((c & 1) * 4 * GARR) * 2;
        const uint32_t sAh = base;
        const uint32_t sAl = base + (uint32_t)GARR * 2;
        const uint32_t sBh = base + (uint32_t)GARR * 4;
        const uint32_t sBl = base + (uint32_t)GARR * 6;

        #pragma unroll
        for (int ks = 0; ks < 2; ++ks) {
            const int ke = ks * 16;
            uint32_t a_h[2][4], a_l[2][4];
            #pragma unroll
            for (int mi = 0; mi < 2; ++mi) {
                int r = wm * 32 + mi * 16 + a_row;
                uint32_t off = (uint32_t)(r * ASTRIDE + ke + a_kof) * 2;
                ldm_x4(a_h[mi], sAh + off);
                ldm_x4(a_l[mi], sAl + off);
            }
            #pragma unroll
            for (int nb = 0; nb < 4; ++nb) {
                int n = wn * 64 + nb * 16 + b_row;
                uint32_t off = (uint32_t)(n * ASTRIDE + ke + b_kof) * 2;
                uint32_t b_h[4], b_l[4];
                ldm_x4(b_h, sBh + off);
                ldm_x4(b_l, sBl + off);
                #pragma unroll
                for (int mi = 0; mi < 2; ++mi) {
                    mma_bf16(acc[mi][nb * 2 + 0], a_h[mi], b_h + 0);
                    mma_bf16(acc[mi][nb * 2 + 1], a_h[mi], b_h + 2);
                    mma_bf16(acc[mi][nb * 2 + 0], a_h[mi], b_l + 0);
                    mma_bf16(acc[mi][nb * 2 + 1], a_h[mi], b_l + 2);
                    mma_bf16(acc[mi][nb * 2 + 0], a_l[mi], b_h + 0);
                    mma_bf16(acc[mi][nb * 2 + 1], a_l[mi], b_h + 2);
                }
            }
        }
    }

    #pragma unroll
    for (int mi = 0; mi < 2; ++mi) {
        int r = row0 + wm * 32 + mi * 16 + (lane >> 2);
        #pragma unroll
        for (int nj = 0; nj < 8; ++nj) {
            int c = col0 + wn * 64 + nj * 8 + (lane & 3) * 2;
            float2 b2 = *reinterpret_cast<const float2*>(bias + c);
            float2 o0, o1;
            o0.x = acc[mi][nj][0] + b2.x;
            o0.y = acc[mi][nj][1] + b2.y;
            o1.x = acc[mi][nj][2] + b2.x;
            o1.y = acc[mi][nj][3] + b2.y;
            *reinterpret_cast<float2*>(C + (size_t)r * N + c)       = o0;
            *reinterpret_cast<float2*>(C + (size_t)(r + 8) * N + c) = o1;
        }
    }
}

// ---------------------------------------------------------------------------
// RMSNorm with fused hi/lo split output
// ---------------------------------------------------------------------------
__global__ void rmsnorm_split(const float* __restrict__ in, const float* __restrict__ g,
                              __nv_bfloat16* __restrict__ oh, __nv_bfloat16* __restrict__ ol,
                              int ncols, int in_stride) {
    const int row = blockIdx.x;
    const float* x = in + (size_t)row * in_stride;
    float ss = 0.f;
    for (int c = threadIdx.x; c < ncols; c += blockDim.x) {
        float v = x[c];
        ss += v * v;
    }
    __shared__ float red[32];
    #pragma unroll
    for (int o = 16; o > 0; o >>= 1) ss += __shfl_xor_sync(0xffffffff, ss, o);
    if ((threadIdx.x & 31) == 0) red[threadIdx.x >> 5] = ss;
    __syncthreads();
    __shared__ float s_scale;
    if (threadIdx.x == 0) {
        float t = 0.f;
        int nw = blockDim.x >> 5;
        for (int i = 0; i < nw; ++i) t += red[i];
        s_scale = 1.0f / sqrtf(t / (float)ncols + 1e-20f);
    }
    __syncthreads();
    const float sc = s_scale;
    size_t base = (size_t)row * ncols;
    for (int c = threadIdx.x; c < ncols; c += blockDim.x)
        split_store(oh, ol, base + c, x[c] * sc * g[c]);
}

// ---------------------------------------------------------------------------
// Assembles (table RoPE) -> bf16 hi/lo, 4 elements per thread (vectorized)
// ---------------------------------------------------------------------------
__global__ void assemble_q4() {
    constexpr size_t total4 = (size_t)B_ * H_ * S_ * DH_ / 4;
    size_t i = (size_t)blockIdx.x * blockDim.x + threadIdx.x;
    if (i >= total4) return;
    size_t idx = i * 4;
    int d = (int)(idx % DH_);                 // multiple of 4
    int s = (int)((idx / DH_) % S_);
    int h = (int)((idx / ((size_t)DH_ * S_)) % H_);
    int b = (int)(idx / ((size_t)DH_ * S_ * H_));
    const float* row = g_qb + ((size_t)(b * S_ + s)) * (H_ * DH_) + h * DH_;
    float v[4];
    if (d >= DR_) {
        float4 x = *reinterpret_cast<const float4*>(row + d - DR_);
        v[0] = x.x; v[1] = x.y; v[2] = x.z; v[3] = x.w;
    } else {
        int fi = d & 31;                      // quad stays inside one 32-half
        float4 x = *reinterpret_cast<const float4*>(row + DN_ + d);
        float4 r4;
        if (d < 32) {
            float4 p = *reinterpret_cast<const float4*>(row + DN_ + d + 32);
            r4 = make_float4(-p.x, -p.y, -p.z, -p.w);
        } else {
            r4 = *reinterpret_cast<const float4*>(row + DN_ + d - 32);
        }
        float4 ct = *reinterpret_cast<const float4*>(g_ct + s * 32 + fi);
        float4 st = *reinterpret_cast<const float4*>(g_st + s * 32 + fi);
        v[0] = x.x * ct.x + r4.x * st.x;
        v[1] = x.y * ct.y + r4.y * st.y;
        v[2] = x.z * ct.z + r4.z * st.z;
        v[3] = x.w * ct.w + r4.w * st.w;
    }
    split_store4(g_Qh, g_Ql, idx, v);
}

__global__ void assemble_k4() {
    constexpr size_t total4 = (size_t)B_ * HKV_ * S_ * DH_ / 4;
    size_t i = (size_t)blockIdx.x * blockDim.x + threadIdx.x;
    if (i >= total4) return;
    size_t idx = i * 4;
    int d  = (int)(idx % DH_);
    int s  = (int)((idx / DH_) % S_);
    int hk = (int)((idx / ((size_t)DH_ * S_)) % HKV_);
    int b  = (int)(idx / ((size_t)DH_ * S_ * HKV_));
    float v[4];
    if (d >= DR_) {
        const float* src = g_kvb + (size_t)(b * S_ + s) * (HKV_ * (DN_ + DV_)) + hk * (DN_ + DV_);
        float4 x = *reinterpret_cast<const float4*>(src + d - DR_);
        v[0] = x.x; v[1] = x.y; v[2] = x.z; v[3] = x.w;
    } else {
        int fi = d & 31;
        const float* kr = g_kva + (size_t)(b * S_ + s) * KVA_NPAD + RKV_;
        float4 x = *reinterpret_cast<const float4*>(kr + d);
        float4 r4;
        if (d < 32) {
            float4 p = *reinterpret_cast<const float4*>(kr + d + 32);
            r4 = make_float4(-p.x, -p.y, -p.z, -p.w);
        } else {
            r4 = *reinterpret_cast<const float4*>(kr + d - 32);
        }
        float4 ct = *reinterpret_cast<const float4*>(g_ct + s * 32 + fi);
        float4 st = *reinterpret_cast<const float4*>(g_st + s * 32 + fi);
        v[0] = x.x * ct.x + r4.x * st.x;
        v[1] = x.y * ct.y + r4.y * st.y;
        v[2] = x.z * ct.z + r4.z * st.z;
        v[3] = x.w * ct.w + r4.w * st.w;
    }
    split_store4(g_Kh, g_Kl, idx, v);
}

// V transposed: [b, hkv, d, s]; each thread handles 4 consecutive s.
__global__ void assemble_v4() {
    constexpr size_t total4 = (size_t)B_ * HKV_ * DV_ * S_ / 4;
    size_t i = (size_t)blockIdx.x * blockDim.x + threadIdx.x;
    if (i >= total4) return;
    size_t idx = i * 4;
    int s0 = (int)(idx % S_);
    int d  = (int)((idx / S_) % DV_);
    int hk = (int)((idx / ((size_t)S_ * DV_)) % HKV_);
    int b  = (int)(idx / ((size_t)S_ * DV_ * HKV_));
    float v[4];
    #pragma unroll
    for (int k = 0; k < 4; ++k)
        v[k] = g_kvb[(size_t)(b * S_ + s0 + k) * (HKV_ * (DN_ + DV_)) + hk * (DN_ + DV_) + DN_ + d];
    split_store4(g_Vth, g_Vtl, idx, v);
}

// ---------------------------------------------------------------------------
// Flash attention on mma.sync bf16 hi/lo (R7-proven version: pre-split Q).
// ---------------------------------------------------------------------------
constexpr int FA_QSTR = 200;
constexpr int FA_VSTR = 72;
constexpr int FA_SMEM = (2 * 128 * FA_QSTR + 2 * 64 * FA_QSTR + 2 * 128 * FA_VSTR) * 2;

__global__ void __launch_bounds__(256, 1)
flash_mma() {
    extern __shared__ __align__(16) uint16_t fs[];
    uint16_t* Qh = fs;
    uint16_t* Ql = Qh + 128 * FA_QSTR;
    uint16_t* Kh = Ql + 128 * FA_QSTR;
    uint16_t* Kl = Kh + 64 * FA_QSTR;
    uint16_t* Vh = Kl + 64 * FA_QSTR;
    uint16_t* Vl = Vh + 128 * FA_VSTR;

    const int bh = blockIdx.x;
    const int b  = bh / H_;
    const int h  = bh % H_;
    const int hkv = h / G_;
    const int qb = (int)gridDim.y - 1 - (int)blockIdx.y;
    const int q0 = qb * 128;

    const int tid  = threadIdx.x;
    const int lane = tid & 31;
    const int wid  = tid >> 5;

    const __nv_bfloat16* Qhg = g_Qh + ((size_t)(b * H_ + h) * S_) * DH_;
    const __nv_bfloat16* Qlg = g_Ql + ((size_t)(b * H_ + h) * S_) * DH_;
    const __nv_bfloat16* Khg = g_Kh + ((size_t)(b * HKV_ + hkv) * S_) * DH_;
    const __nv_bfloat16* Klg = g_Kl + ((size_t)(b * HKV_ + hkv) * S_) * DH_;
    const __nv_bfloat16* Vhg = g_Vth + ((size_t)(b * HKV_ + hkv) * DV_) * S_;
    const __nv_bfloat16* Vlg = g_Vtl + ((size_t)(b * HKV_ + hkv) * DV_) * S_;

    {
        int r = tid >> 1, half = tid & 1;
        #pragma unroll
        for (int i = 0; i < 12; ++i) {
            int q = half * 12 + i;
            *reinterpret_cast<uint4*>(Qh + r * FA_QSTR + q * 8) =
                *reinterpret_cast<const uint4*>(Qhg + (size_t)(q0 + r) * DH_ + q * 8);
            *reinterpret_cast<uint4*>(Ql + r * FA_QSTR + q * 8) =
                *reinterpret_cast<const uint4*>(Qlg + (size_t)(q0 + r) * DH_ + q * 8);
        }
    }

    const int a_row = ((lane >> 3) & 1) * 8 + (lane & 7);
    const int a_kof = (lane >> 4) * 8;
    const int b_row = (lane >> 4) * 8 + (lane & 7);
    const int b_kof = ((lane >> 3) & 1) * 8;
    const int rl = lane >> 2, cb = (lane & 3) * 2;
    const int rg0 = q0 + wid * 16 + rl;
    const float scale = rsqrtf((float)DH_);

    float accO[8][2][4];
    #pragma unroll
    for (int i = 0; i < 8; ++i)
        #pragma unroll
        for (int j = 0; j < 2; ++j)
            #pragma unroll
            for (int q = 0; q < 4; ++q) accO[i][j][q] = 0.f;
    float m0 = -1e30f, m1 = -1e30f, l0 = 0.f, l1 = 0.f;

    const int T = 2 * (qb + 1);
    for (int t = 0; t < T; ++t) {
        const int j0 = t * 64;
        __syncthreads();
        {
            int r = tid >> 2, part = tid & 3;
            #pragma unroll
            for (int i = 0; i < 6; ++i) {
                int q = part * 6 + i;
                *reinterpret_cast<uint4*>(Kh + r * FA_QSTR + q * 8) =
                    *reinterpret_cast<const uint4*>(Khg + (size_t)(j0 + r) * DH_ + q * 8);
                *reinterpret_cast<uint4*>(Kl + r * FA_QSTR + q * 8) =
                    *reinterpret_cast<const uint4*>(Klg + (size_t)(j0 + r) * DH_ + q * 8);
            }
        }
        {
            int r = tid >> 1, part = tid & 1;
            #pragma unroll
            for (int i = 0; i < 4; ++i) {
                int q = part * 4 + i;
                *reinterpret_cast<uint4*>(Vh + r * FA_VSTR + q * 8) =
                    *reinterpret_cast<const uint4*>(Vhg + (size_t)r * S_ + j0 + q * 8);
                *reinterpret_cast<uint4*>(Vl + r * FA_VSTR + q * 8) =
                    *reinterpret_cast<const uint4*>(Vlg + (size_t)r * S_ + j0 + q * 8);
            }
        }
        __syncthreads();

        float Sc[4][2][4];
        #pragma unroll
        for (int i = 0; i < 4; ++i)
            #pragma unroll
            for (int j = 0; j < 2; ++j)
                #pragma unroll
                for (int q = 0; q < 4; ++q) Sc[i][j][q] = 0.f;

        #pragma unroll
        for (int ks = 0; ks < 12; ++ks) {
            uint32_t ah[4], al[4];
            uint32_t qoff = (uint32_t)((wid * 16 + a_row) * FA_QSTR + ks * 16 + a_kof) * 2;
            ldm_x4(ah, smem_u32(Qh) + qoff);
            ldm_x4(al, smem_u32(Ql) + qoff);
            #pragma unroll
            for (int nb = 0; nb < 4; ++nb) {
                uint32_t koff = (uint32_t)((nb * 16 + b_row) * FA_QSTR + ks * 16 + b_kof) * 2;
                uint32_t bh4[4], bl4[4];
                ldm_x4(bh4, smem_u32(Kh) + koff);
                ldm_x4(bl4, smem_u32(Kl) + koff);
                mma_bf16(Sc[nb][0], ah, bh4 + 0);
                mma_bf16(Sc[nb][1], ah, bh4 + 2);
                mma_bf16(Sc[nb][0], ah, bl4 + 0);
                mma_bf16(Sc[nb][1], ah, bl4 + 2);
                mma_bf16(Sc[nb][0], al, bh4 + 0);
                mma_bf16(Sc[nb][1], al, bh4 + 2);
            }
        }

        const bool domask = (j0 + 63) > (q0 + wid * 16);
        #pragma unroll
        for (int nb = 0; nb < 4; ++nb)
            #pragma unroll
            for (int mm = 0; mm < 2; ++mm) {
                int c = j0 + nb * 16 + mm * 8 + cb;
                float* s4 = Sc[nb][mm];
                s4[0] *= scale; s4[1] *= scale; s4[2] *= scale; s4[3] *= scale;
                if (domask) {
                    if (c     > rg0)     s4[0] = -1e30f;
                    if (c + 1 > rg0)     s4[1] = -1e30f;
                    if (c     > rg0 + 8) s4[2] = -1e30f;
                    if (c + 1 > rg0 + 8) s4[3] = -1e30f;
                }
            }

        float mx0 = -1e30f, mx1 = -1e30f;
        #pragma unroll
        for (int nb = 0; nb < 4; ++nb)
            #pragma unroll
            for (int mm = 0; mm < 2; ++mm) {
                mx0 = fmaxf(mx0, fmaxf(Sc[nb][mm][0], Sc[nb][mm][1]));
                mx1 = fmaxf(mx1, fmaxf(Sc[nb][mm][2], Sc[nb][mm][3]));
            }
        mx0 = fmaxf(mx0, __shfl_xor_sync(0xffffffff, mx0, 1));
        mx0 = fmaxf(mx0, __shfl_xor_sync(0xffffffff, mx0, 2));
        mx1 = fmaxf(mx1, __shfl_xor_sync(0xffffffff, mx1, 1));
        mx1 = fmaxf(mx1, __shfl_xor_sync(0xffffffff, mx1, 2));
        float mn0 = fmaxf(m0, mx0), mn1 = fmaxf(m1, mx1);
        float corr0 = __expf(m0 - mn0), corr1 = __expf(m1 - mn1);
        m0 = mn0; m1 = mn1;

        uint32_t aPh[4][4], aPl[4][4];
        float sum0 = 0.f, sum1 = 0.f;
        #pragma unroll
        for (int nb = 0; nb < 4; ++nb) {
            float e00, e01, e02, e03, e10, e11, e12, e13;
            e00 = __expf(Sc[nb][0][0] - mn0);  e01 = __expf(Sc[nb][0][1] - mn0);
            e02 = __expf(Sc[nb][0][2] - mn1);  e03 = __expf(Sc[nb][0][3] - mn1);
            e10 = __expf(Sc[nb][1][0] - mn0);  e11 = __expf(Sc[nb][1][1] - mn0);
            e12 = __expf(Sc[nb][1][2] - mn1);  e13 = __expf(Sc[nb][1][3] - mn1);
            sum0 += e00 + e01 + e10 + e11;
            sum1 += e02 + e03 + e12 + e13;
            aPh[nb][0] = pack_hi2(e00, e01);  aPl[nb][0] = pack_lo2(e00, e01);
            aPh[nb][1] = pack_hi2(e02, e03);  aPl[nb][1] = pack_lo2(e02, e03);
            aPh[nb][2] = pack_hi2(e10, e11);  aPl[nb][2] = pack_lo2(e10, e11);
            aPh[nb][3] = pack_hi2(e12, e13);  aPl[nb][3] = pack_lo2(e12, e13);
        }
        sum0 += __shfl_xor_sync(0xffffffff, sum0, 1);
        sum0 += __shfl_xor_sync(0xffffffff, sum0, 2);
        sum1 += __shfl_xor_sync(0xffffffff, sum1, 1);
        sum1 += __shfl_xor_sync(0xffffffff, sum1, 2);
        l0 = l0 * corr0 + sum0;
        l1 = l1 * corr1 + sum1;

        #pragma unroll
        for (int nv = 0; nv < 8; ++nv)
            #pragma unroll
            for (int mm = 0; mm < 2; ++mm) {
                accO[nv][mm][0] *= corr0; accO[nv][mm][1] *= corr0;
                accO[nv][mm][2] *= corr1; accO[nv][mm][3] *= corr1;
            }

        #pragma unroll
        for (int ks = 0; ks < 4; ++ks) {
            #pragma unroll
            for (int nv = 0; nv < 8; ++nv) {
                uint32_t voff = (uint32_t)((nv * 16 + b_row) * FA_VSTR + ks * 16 + b_kof) * 2;
                uint32_t bh4[4], bl4[4];
                ldm_x4(bh4, smem_u32(Vh) + voff);
                ldm_x4(bl4, smem_u32(Vl) + voff);
                mma_bf16(accO[nv][0], aPh[ks], bh4 + 0);
                mma_bf16(accO[nv][1], aPh[ks], bh4 + 2);
                mma_bf16(accO[nv][0], aPh[ks], bl4 + 0);
                mma_bf16(accO[nv][1], aPh[ks], bl4 + 2);
                mma_bf16(accO[nv][0], aPl[ks], bh4 + 0);
                mma_bf16(accO[nv][1], aPl[ks], bh4 + 2);
            }
        }
    }

    const float il0 = 1.0f / l0, il1 = 1.0f / l1;
    #pragma unroll
    for (int nv = 0; nv < 8; ++nv)
        #pragma unroll
        for (int mm = 0; mm < 2; ++mm) {
            int c = nv * 16 + mm * 8 + cb;
            size_t base0 = ((size_t)(b * S_) + rg0)     * (H_ * DV_) + h * DV_ + c;
            size_t base1 = ((size_t)(b * S_) + rg0 + 8) * (H_ * DV_) + h * DV_ + c;
            float x0 = accO[nv][mm][0] * il0, y0 = accO[nv][mm][1] * il0;
            float x1 = accO[nv][mm][2] * il1, y1 = accO[nv][mm][3] * il1;
            *reinterpret_cast<uint32_t*>(g_atth + base0) = pack_hi2(x0, y0);
            *reinterpret_cast<uint32_t*>(g_attl + base0) = pack_lo2(x0, y0);
            *reinterpret_cast<uint32_t*>(g_atth + base1) = pack_hi2(x1, y1);
            *reinterpret_cast<uint32_t*>(g_attl + base1) = pack_lo2(x1, y1);
        }
}

// ---------------------------------------------------------------------------
// Launch sequence (single stream, R7-proven ordering)
// ---------------------------------------------------------------------------
extern "C" void kernel_launch(void* const* d_in, const int* in_sizes, int n_in,
                              void* d_out, int out_size) {
    const float* hs    = (const float*)d_in[0];
    const float* w_qa  = (const float*)d_in[2];
    const float* b_qa  = (const float*)d_in[3];
    const float* gq    = (const float*)d_in[4];
    const float* w_qb  = (const float*)d_in[5];
    const float* b_qb  = (const float*)d_in[6];
    const float* w_kva = (const float*)d_in[7];
    const float* b_kva = (const float*)d_in[8];
    const float* gkv   = (const float*)d_in[9];
    const float* w_kvb = (const float*)d_in[10];
    const float* b_kvb = (const float*)d_in[11];
    const float* w_o   = (const float*)d_in[12];
    const float* b_o   = (const float*)d_in[13];
    float* out = (float*)d_out;

    float *p_qa, *p_qb, *p_kva, *p_kvb, *p_bkva;
    cudaGetSymbolAddress((void**)&p_qa,   g_qa);
    cudaGetSymbolAddress((void**)&p_qb,   g_qb);
    cudaGetSymbolAddress((void**)&p_kva,  g_kva);
    cudaGetSymbolAddress((void**)&p_kvb,  g_kvb);
    cudaGetSymbolAddress((void**)&p_bkva, g_bkva);
    __nv_bfloat16 *qa_h, *qa_l, *qb_h, *qb_l, *kva_h, *kva_l, *kvb_h, *kvb_l, *o_h, *o_l;
    cudaGetSymbolAddress((void**)&qa_h,  g_wqa_h);  cudaGetSymbolAddress((void**)&qa_l,  g_wqa_l);
    cudaGetSymbolAddress((void**)&qb_h,  g_wqb_h);  cudaGetSymbolAddress((void**)&qb_l,  g_wqb_l);
    cudaGetSymbolAddress((void**)&kva_h, g_wkva_h); cudaGetSymbolAddress((void**)&kva_l, g_wkva_l);
    cudaGetSymbolAddress((void**)&kvb_h, g_wkvb_h); cudaGetSymbolAddress((void**)&kvb_l, g_wkvb_l);
    cudaGetSymbolAddress((void**)&o_h,   g_wo_h);   cudaGetSymbolAddress((void**)&o_l,   g_wo_l);
    __nv_bfloat16 *hs_h, *hs_l, *qn_h, *qn_l, *kvn_h, *kvn_l, *att_h, *att_l;
    cudaGetSymbolAddress((void**)&hs_h,  g_hsh);  cudaGetSymbolAddress((void**)&hs_l,  g_hsl);
    cudaGetSymbolAddress((void**)&qn_h,  g_qnh);  cudaGetSymbolAddress((void**)&qn_l,  g_qnl);
    cudaGetSymbolAddress((void**)&kvn_h, g_kvnh); cudaGetSymbolAddress((void**)&kvn_l, g_kvnl);
    cudaGetSymbolAddress((void**)&att_h, g_atth); cudaGetSymbolAddress((void**)&att_l, g_attl);

    cudaFuncSetAttribute(flash_mma, cudaFuncAttributeMaxDynamicSharedMemorySize, FA_SMEM);
    cudaFuncSetAttribute(gemm_mma2, cudaFuncAttributeMaxDynamicSharedMemorySize, GEMM_SMEM2);

    // ---- prep: weights, bias pad, rope table, hs split ----
    dim3 tb(32, 8);
    prep_w<<<dim3(D_ / 32,  RQ_ / 32),           tb>>>(w_qa,  qa_h,  qa_l,  D_,  RQ_,       RQ_);
    prep_w<<<dim3(RQ_ / 32, (H_ * DH_) / 32),    tb>>>(w_qb,  qb_h,  qb_l,  RQ_, H_ * DH_,  H_ * DH_);
    prep_w<<<dim3(D_ / 32,  KVA_NPAD / 32),      tb>>>(w_kva, kva_h, kva_l, D_,  KVA_N,     KVA_NPAD);
    prep_w<<<dim3(RKV_ / 32, (HKV_ * 256) / 32), tb>>>(w_kvb, kvb_h, kvb_l, RKV_, HKV_ * 256, HKV_ * 256);
    prep_w<<<dim3(D_ / 32,  D_ / 32),            tb>>>(w_o,   o_h,   o_l,   D_,  D_,        D_);
    pad_bias_kva<<<(KVA_NPAD + 255) / 256, 256>>>(b_kva);
    rope_table<<<(S_ * 32 + 255) / 256, 256>>>();
    {
        constexpr size_t n4 = (size_t)M_ * D_ / 4;
        split_act4<<<(unsigned)((n4 + 255) / 256), 256>>>(
            (const float4*)hs, (uint2*)hs_h, (uint2*)hs_l, n4);
    }

    // ---- projections ----
    gemm_mma2<<<dim3(RQ_ / 128, M_ / 128), 256, GEMM_SMEM2>>>(hs_h, hs_l, qa_h, qa_l, b_qa, p_qa, M_, RQ_, D_);
    rmsnorm_split<<<M_, 256>>>(p_qa, gq, qn_h, qn_l, RQ_, RQ_);
    gemm_mma2<<<dim3((H_ * DH_) / 128, M_ / 128), 256, GEMM_SMEM2>>>(qn_h, qn_l, qb_h, qb_l, b_qb, p_qb, M_, H_ * DH_, RQ_);
    gemm_mma2<<<dim3(KVA_NPAD / 128, M_ / 128), 256, GEMM_SMEM2>>>(hs_h, hs_l, kva_h, kva_l, p_bkva, p_kva, M_, KVA_NPAD, D_);
    rmsnorm_split<<<M_, 256>>>(p_kva, gkv, kvn_h, kvn_l, RKV_, KVA_NPAD);
    gemm_mma2<<<dim3((HKV_ * 256) / 128, M_ / 128), 256, GEMM_SMEM2>>>(kvn_h, kvn_l, kvb_h, kvb_l, b_kvb, p_kvb, M_, HKV_ * 256, RKV_);

    // ---- assemble Q/K/V (vectorized 4-wide) ----
    {
        constexpr size_t tq4 = (size_t)B_ * H_ * S_ * DH_ / 4;
        assemble_q4<<<(unsigned)((tq4 + 255) / 256), 256>>>();
        constexpr size_t tk4 = (size_t)B_ * HKV_ * S_ * DH_ / 4;
        assemble_k4<<<(unsigned)((tk4 + 255) / 256), 256>>>();
        constexpr size_t tv4 = (size_t)B_ * HKV_ * DV_ * S_ / 4;
        assemble_v4<<<(unsigned)((tv4 + 255) / 256), 256>>>();
    }

    // ---- attention + output projection ----
    flash_mma<<<dim3(B_ * H_, S_ / 128), 256, FA_SMEM>>>();
    gemm_mma2<<<dim3(D_ / 128, M_ / 128), 256, GEMM_SMEM2>>>(
        att_h, att_l, o_h, o_l, b_o, out, M_, D_, D_);
}

// round 14
// speedup vs baseline: 1.0983x; 1.0263x over previous
#include <cuda_runtime.h>
#include <cuda_bf16.h>
#include <cstdint>
#include <math.h>

// ---------------------------------------------------------------------------
// Problem constants
// ---------------------------------------------------------------------------
namespace {
constexpr int B_   = 2;
constexpr int S_   = 2048;
constexpr int D_   = 2048;
constexpr int H_   = 16;
constexpr int HKV_ = 4;
constexpr int G_   = H_ / HKV_;
constexpr int RQ_  = 1024;
constexpr int RKV_ = 512;
constexpr int DH_  = 192;
constexpr int DR_  = 64;
constexpr int DN_  = 128;
constexpr int DV_  = 128;
constexpr int M_   = B_ * S_;          // 4096
constexpr int KVA_N    = RKV_ + DR_;   // 576
constexpr int KVA_NPAD = 640;
}

// ---------------------------------------------------------------------------
// Scratch (static device globals)
// ---------------------------------------------------------------------------
__device__ float g_qa  [(size_t)M_ * RQ_];
__device__ float g_kva [(size_t)M_ * KVA_NPAD];
__device__ float g_kvb [(size_t)M_ * HKV_ * (DN_ + DV_)];
__device__ float g_bkva[KVA_NPAD];
__device__ float g_ct  [S_ * 32];
__device__ float g_st  [S_ * 32];

// pre-split activations (bf16 hi/lo)
__device__ __nv_bfloat16 g_hsh [(size_t)M_ * D_];
__device__ __nv_bfloat16 g_hsl [(size_t)M_ * D_];
__device__ __nv_bfloat16 g_qnh [(size_t)M_ * RQ_];
__device__ __nv_bfloat16 g_qnl [(size_t)M_ * RQ_];
__device__ __nv_bfloat16 g_kvnh[(size_t)M_ * RKV_];
__device__ __nv_bfloat16 g_kvnl[(size_t)M_ * RKV_];
__device__ __nv_bfloat16 g_atth[(size_t)M_ * H_ * DV_];
__device__ __nv_bfloat16 g_attl[(size_t)M_ * H_ * DV_];

// bf16 hi/lo Q/K ([b,h/hkv,s,d]) and V transposed ([b,hkv,d,s])
__device__ __nv_bfloat16 g_Qh [(size_t)B_ * H_   * S_ * DH_];
__device__ __nv_bfloat16 g_Ql [(size_t)B_ * H_   * S_ * DH_];
__device__ __nv_bfloat16 g_Kh [(size_t)B_ * HKV_ * S_ * DH_];
__device__ __nv_bfloat16 g_Kl [(size_t)B_ * HKV_ * S_ * DH_];
__device__ __nv_bfloat16 g_Vth[(size_t)B_ * HKV_ * DV_ * S_];
__device__ __nv_bfloat16 g_Vtl[(size_t)B_ * HKV_ * DV_ * S_];

// Pre-split / transposed weights: [N, K] bf16, hi + lo
__device__ __nv_bfloat16 g_wqa_h [(size_t)RQ_ * D_];
__device__ __nv_bfloat16 g_wqa_l [(size_t)RQ_ * D_];
__device__ __nv_bfloat16 g_wqb_h [(size_t)(H_ * DH_) * RQ_];
__device__ __nv_bfloat16 g_wqb_l [(size_t)(H_ * DH_) * RQ_];
__device__ __nv_bfloat16 g_wkva_h[(size_t)KVA_NPAD * D_];
__device__ __nv_bfloat16 g_wkva_l[(size_t)KVA_NPAD * D_];
__device__ __nv_bfloat16 g_wkvb_h[(size_t)(HKV_ * (DN_ + DV_)) * RKV_];
__device__ __nv_bfloat16 g_wkvb_l[(size_t)(HKV_ * (DN_ + DV_)) * RKV_];
__device__ __nv_bfloat16 g_wo_h  [(size_t)D_ * D_];
__device__ __nv_bfloat16 g_wo_l  [(size_t)D_ * D_];

// ---------------------------------------------------------------------------
// mma.sync / cp.async helpers
// ---------------------------------------------------------------------------
__device__ __forceinline__ uint32_t smem_u32(const void* p) {
    return (uint32_t)__cvta_generic_to_shared(p);
}
__device__ __forceinline__ void ldm_x4(uint32_t* r, uint32_t addr) {
    asm volatile("ldmatrix.sync.aligned.m8n8.x4.shared.b16 {%0,%1,%2,%3}, [%4];"
                 : "=r"(r[0]), "=r"(r[1]), "=r"(r[2]), "=r"(r[3]) : "r"(addr));
}
__device__ __forceinline__ void mma_bf16(float* c, const uint32_t* a, const uint32_t* b) {
    asm volatile("mma.sync.aligned.m16n8k16.row.col.f32.bf16.bf16.f32 "
                 "{%0,%1,%2,%3}, {%4,%5,%6,%7}, {%8,%9}, {%0,%1,%2,%3};"
                 : "+f"(c[0]), "+f"(c[1]), "+f"(c[2]), "+f"(c[3])
                 : "r"(a[0]), "r"(a[1]), "r"(a[2]), "r"(a[3]), "r"(b[0]), "r"(b[1]));
}
__device__ __forceinline__ void cp16(uint32_t dst, const void* src) {
    asm volatile("cp.async.cg.shared.global [%0], [%1], 16;"
                 :: "r"(dst), "l"(__cvta_generic_to_global(src)));
}
__device__ __forceinline__ void cp_commit() {
    asm volatile("cp.async.commit_group;");
}
template <int N_> __device__ __forceinline__ void cp_wait() {
    asm volatile("cp.async.wait_group %0;" :: "n"(N_));
}
__device__ __forceinline__ uint32_t pack_bf2(__nv_bfloat16 a, __nv_bfloat16 b) {
    return (uint32_t)__bfloat16_as_ushort(a) | ((uint32_t)__bfloat16_as_ushort(b) << 16);
}
__device__ __forceinline__ uint32_t pack_hi2(float x, float y) {
    return pack_bf2(__float2bfloat16(x), __float2bfloat16(y));
}
__device__ __forceinline__ uint32_t pack_lo2(float x, float y) {
    __nv_bfloat16 hx = __float2bfloat16(x), hy = __float2bfloat16(y);
    return pack_bf2(__float2bfloat16(x - __bfloat162float(hx)),
                    __float2bfloat16(y - __bfloat162float(hy)));
}
__device__ __forceinline__ void split_store(__nv_bfloat16* Hh, __nv_bfloat16* Ll,
                                            size_t idx, float v) {
    __nv_bfloat16 h = __float2bfloat16(v);
    Hh[idx] = h;
    Ll[idx] = __float2bfloat16(v - __bfloat162float(h));
}
__device__ __forceinline__ void split_store4(__nv_bfloat16* Hh, __nv_bfloat16* Ll,
                                             size_t idx, const float* v) {
    *reinterpret_cast<uint2*>(Hh + idx) = make_uint2(pack_hi2(v[0], v[1]), pack_hi2(v[2], v[3]));
    *reinterpret_cast<uint2*>(Ll + idx) = make_uint2(pack_lo2(v[0], v[1]), pack_lo2(v[2], v[3]));
}

// ---------------------------------------------------------------------------
// Prep kernels
// ---------------------------------------------------------------------------
__global__ void prep_w(const float* __restrict__ W, __nv_bfloat16* __restrict__ Hh,
                       __nv_bfloat16* __restrict__ Ll, int K, int N, int Npad) {
    __shared__ float t[32][33];
    const int kb = blockIdx.x * 32, nb = blockIdx.y * 32;
    const int tx = threadIdx.x, ty = threadIdx.y;
    #pragma unroll
    for (int i = 0; i < 4; ++i) {
        int k = kb + ty + i * 8;
        int n = nb + tx;
        t[ty + i * 8][tx] = (n < N) ? W[(size_t)k * N + n] : 0.f;
    }
    __syncthreads();
    #pragma unroll
    for (int i = 0; i < 4; ++i) {
        int n = nb + ty + i * 8;
        if (n >= Npad) continue;
        int k = kb + tx;
        split_store(Hh, Ll, (size_t)n * K + k, t[tx][ty + i * 8]);
    }
}

__global__ void pad_bias_kva(const float* __restrict__ b) {
    int i = threadIdx.x + blockIdx.x * blockDim.x;
    if (i < KVA_NPAD) g_bkva[i] = (i < KVA_N) ? b[i] : 0.f;
}

__global__ void rope_table() {
    int i = blockIdx.x * blockDim.x + threadIdx.x;
    if (i >= S_ * 32) return;
    int s = i >> 5, fi = i & 31;
    float ang = (float)s * powf(10000.0f, -(float)(2 * fi) / 64.0f);
    g_ct[i] = cosf(ang);
    g_st[i] = sinf(ang);
}

__global__ void split_act4(const float4* __restrict__ X, uint2* __restrict__ Hh,
                           uint2* __restrict__ Ll, size_t n4) {
    size_t i = (size_t)blockIdx.x * blockDim.x + threadIdx.x;
    if (i >= n4) return;
    float4 v = X[i];
    Hh[i] = make_uint2(pack_hi2(v.x, v.y), pack_hi2(v.z, v.w));
    Ll[i] = make_uint2(pack_lo2(v.x, v.y), pack_lo2(v.z, v.w));
}

// ---------------------------------------------------------------------------
// HMMA GEMM (R7-proven): 2-stage cp.async, k-chunk 32, one sync per chunk.
// ---------------------------------------------------------------------------
constexpr int ASTRIDE = 40;
constexpr int GARR    = 128 * ASTRIDE;
constexpr int GEMM_SMEM2 = 2 * 4 * GARR * 2;

// mainloop shared by both GEMM variants; accumulates into acc[2][8][4]
#define GEMM_MAINLOOP(Agh, Agl, Bgh, Bgl, K)                                          \
    const int nch = (K) >> 5;                                                         \
    auto prefetch = [&](int c) {                                                      \
        const int k0 = c << 5;                                                        \
        const int s = c & 1;                                                          \
        _Pragma("unroll")                                                             \
        for (int it = 0; it < 8; ++it) {                                              \
            int idx = tid + it * 256;                                                 \
            int arr = idx >> 9;                                                       \
            int j   = idx & 511;                                                      \
            int r   = j >> 2, q = j & 3;                                              \
            const __nv_bfloat16* src = (arr == 0) ? (Agh) : (arr == 1) ? (Agl)        \
                                     : (arr == 2) ? (Bgh) : (Bgl);                    \
            size_t goff = (size_t)(((arr < 2) ? row0 : col0) + r) * (K) + k0 + q * 8; \
            uint32_t dst = sb + (uint32_t)(((s * 4 + arr) * 128 + r) * ASTRIDE + q * 8) * 2; \
            cp16(dst, src + goff);                                                    \
        }                                                                             \
        cp_commit();                                                                  \
    };                                                                                \
    prefetch(0);                                                                      \
    for (int c = 0; c < nch; ++c) {                                                   \
        cp_wait<0>();                                                                 \
        __syncthreads();                                                              \
        if (c + 1 < nch) prefetch(c + 1);                                             \
        const uint32_t base = sb + (uint32_t)((c & 1) * 4 * GARR) * 2;                \
        const uint32_t sAh = base;                                                    \
        const uint32_t sAl = base + (uint32_t)GARR * 2;                               \
        const uint32_t sBh = base + (uint32_t)GARR * 4;                               \
        const uint32_t sBl = base + (uint32_t)GARR * 6;                               \
        _Pragma("unroll")                                                             \
        for (int ks = 0; ks < 2; ++ks) {                                              \
            const int ke = ks * 16;                                                   \
            uint32_t a_h[2][4], a_l[2][4];                                            \
            _Pragma("unroll")                                                         \
            for (int mi = 0; mi < 2; ++mi) {                                          \
                int r = wm * 32 + mi * 16 + a_row;                                    \
                uint32_t off = (uint32_t)(r * ASTRIDE + ke + a_kof) * 2;              \
                ldm_x4(a_h[mi], sAh + off);                                           \
                ldm_x4(a_l[mi], sAl + off);                                           \
            }                                                                         \
            _Pragma("unroll")                                                         \
            for (int nb = 0; nb < 4; ++nb) {                                          \
                int n = wn * 64 + nb * 16 + b_row;                                    \
                uint32_t off = (uint32_t)(n * ASTRIDE + ke + b_kof) * 2;              \
                uint32_t b_h[4], b_l[4];                                              \
                ldm_x4(b_h, sBh + off);                                               \
                ldm_x4(b_l, sBl + off);                                               \
                _Pragma("unroll")                                                     \
                for (int mi = 0; mi < 2; ++mi) {                                      \
                    mma_bf16(acc[mi][nb * 2 + 0], a_h[mi], b_h + 0);                  \
                    mma_bf16(acc[mi][nb * 2 + 1], a_h[mi], b_h + 2);                  \
                    mma_bf16(acc[mi][nb * 2 + 0], a_h[mi], b_l + 0);                  \
                    mma_bf16(acc[mi][nb * 2 + 1], a_h[mi], b_l + 2);                  \
                    mma_bf16(acc[mi][nb * 2 + 0], a_l[mi], b_h + 0);                  \
                    mma_bf16(acc[mi][nb * 2 + 1], a_l[mi], b_h + 2);                  \
                }                                                                     \
            }                                                                         \
        }                                                                             \
    }

#define GEMM_PREAMBLE                                                                 \
    extern __shared__ __align__(16) uint16_t gs[];                                    \
    const int tid  = threadIdx.x;                                                     \
    const int lane = tid & 31;                                                        \
    const int wid  = tid >> 5;                                                        \
    const int wm   = wid & 3;                                                         \
    const int wn   = wid >> 2;                                                        \
    const int row0 = blockIdx.y * 128, col0 = blockIdx.x * 128;                       \
    const uint32_t sb = smem_u32(gs);                                                 \
    float acc[2][8][4];                                                               \
    _Pragma("unroll")                                                                 \
    for (int i = 0; i < 2; ++i)                                                       \
        _Pragma("unroll")                                                             \
        for (int j = 0; j < 8; ++j)                                                   \
            _Pragma("unroll")                                                         \
            for (int q = 0; q < 4; ++q) acc[i][j][q] = 0.f;                           \
    const int a_row = ((lane >> 3) & 1) * 8 + (lane & 7);                             \
    const int a_kof = (lane >> 4) * 8;                                                \
    const int b_row = (lane >> 4) * 8 + (lane & 7);                                   \
    const int b_kof = ((lane >> 3) & 1) * 8;

__global__ void __launch_bounds__(256)
gemm_mma2(const __nv_bfloat16* __restrict__ Agh, const __nv_bfloat16* __restrict__ Agl,
          const __nv_bfloat16* __restrict__ Bgh, const __nv_bfloat16* __restrict__ Bgl,
          const float* __restrict__ bias, float* __restrict__ C,
          int M, int N, int K) {
    GEMM_PREAMBLE
    GEMM_MAINLOOP(Agh, Agl, Bgh, Bgl, K)

    #pragma unroll
    for (int mi = 0; mi < 2; ++mi) {
        int r = row0 + wm * 32 + mi * 16 + (lane >> 2);
        #pragma unroll
        for (int nj = 0; nj < 8; ++nj) {
            int c = col0 + wn * 64 + nj * 8 + (lane & 3) * 2;
            float2 b2 = *reinterpret_cast<const float2*>(bias + c);
            float2 o0, o1;
            o0.x = acc[mi][nj][0] + b2.x;
            o0.y = acc[mi][nj][1] + b2.y;
            o1.x = acc[mi][nj][2] + b2.x;
            o1.y = acc[mi][nj][3] + b2.y;
            *reinterpret_cast<float2*>(C + (size_t)r * N + c)       = o0;
            *reinterpret_cast<float2*>(C + (size_t)(r + 8) * N + c) = o1;
        }
    }
}

// qb GEMM with fused bias + RoPE + hi/lo split epilogue -> g_Qh/g_Ql.
// N = 3072 = H*192. Each 64-col warp tile is exactly one third of a head:
// type 0/1 = nrope cols 0-63 / 64-127 (-> out d = 64+type*64+cc),
// type 2   = rope cols 0-63 (partner d±32 lives in nj^4, same lane/row).
__global__ void __launch_bounds__(256)
gemm_qb_rope(const __nv_bfloat16* __restrict__ Agh, const __nv_bfloat16* __restrict__ Agl,
             const __nv_bfloat16* __restrict__ Bgh, const __nv_bfloat16* __restrict__ Bgl,
             const float* __restrict__ bias) {
    GEMM_PREAMBLE
    GEMM_MAINLOOP(Agh, Agl, Bgh, Bgl, RQ_)

    const int bi   = (col0 >> 6) + wn;        // 64-col block index (col0/64 even)
    const int type = bi % 3;
    const int hh   = bi / 3;
    const int cbl  = (lane & 3) * 2;          // col within 8-seg
    const float* biasw = bias + col0 + wn * 64;

    #pragma unroll
    for (int mi = 0; mi < 2; ++mi) {
        #pragma unroll
        for (int rr = 0; rr < 2; ++rr) {
            int r = row0 + wm * 32 + mi * 16 + (lane >> 2) + rr * 8;
            int bb = r >> 11, s = r & (S_ - 1);
            size_t qbase = ((size_t)(bb * H_ + hh) * S_ + s) * DH_;
            #pragma unroll
            for (int nj = 0; nj < 8; ++nj) {
                int cc = nj * 8 + cbl;                       // 0..63 in block
                float x0 = acc[mi][nj][rr * 2 + 0] + biasw[cc];
                float x1 = acc[mi][nj][rr * 2 + 1] + biasw[cc + 1];
                int out_d;
                float v0, v1;
                if (type < 2) {
                    out_d = DR_ + type * 64 + cc;            // nrope -> d = 64 + dd
                    v0 = x0; v1 = x1;
                } else {
                    out_d = cc;                               // rope -> d = dd
                    int fi = cc & 31;
                    float ct0 = g_ct[s * 32 + fi],     st0 = g_st[s * 32 + fi];
                    float ct1 = g_ct[s * 32 + fi + 1], st1 = g_st[s * 32 + fi + 1];
                    float p0, p1;
                    if (nj < 4) {   // dd < 32: rot = -(value at dd+32)
                        p0 = -(acc[mi][nj + 4][rr * 2 + 0] + biasw[cc + 32]);
                        p1 = -(acc[mi][nj + 4][rr * 2 + 1] + biasw[cc + 33]);
                    } else {        // dd >= 32: rot = +(value at dd-32)
                        p0 =  (acc[mi][nj - 4][rr * 2 + 0] + biasw[cc - 32]);
                        p1 =  (acc[mi][nj - 4][rr * 2 + 1] + biasw[cc - 31]);
                    }
                    v0 = x0 * ct0 + p0 * st0;
                    v1 = x1 * ct1 + p1 * st1;
                }
                *reinterpret_cast<uint32_t*>(g_Qh + qbase + out_d) = pack_hi2(v0, v1);
                *reinterpret_cast<uint32_t*>(g_Ql + qbase + out_d) = pack_lo2(v0, v1);
            }
        }
    }
}

// ---------------------------------------------------------------------------
// RMSNorm with fused hi/lo split output
// ---------------------------------------------------------------------------
__global__ void rmsnorm_split(const float* __restrict__ in, const float* __restrict__ g,
                              __nv_bfloat16* __restrict__ oh, __nv_bfloat16* __restrict__ ol,
                              int ncols, int in_stride) {
    const int row = blockIdx.x;
    const float* x = in + (size_t)row * in_stride;
    float ss = 0.f;
    for (int c = threadIdx.x; c < ncols; c += blockDim.x) {
        float v = x[c];
        ss += v * v;
    }
    __shared__ float red[32];
    #pragma unroll
    for (int o = 16; o > 0; o >>= 1) ss += __shfl_xor_sync(0xffffffff, ss, o);
    if ((threadIdx.x & 31) == 0) red[threadIdx.x >> 5] = ss;
    __syncthreads();
    __shared__ float s_scale;
    if (threadIdx.x == 0) {
        float t = 0.f;
        int nw = blockDim.x >> 5;
        for (int i = 0; i < nw; ++i) t += red[i];
        s_scale = 1.0f / sqrtf(t / (float)ncols + 1e-20f);
    }
    __syncthreads();
    const float sc = s_scale;
    size_t base = (size_t)row * ncols;
    for (int c = threadIdx.x; c < ncols; c += blockDim.x)
        split_store(oh, ol, base + c, x[c] * sc * g[c]);
}

// ---------------------------------------------------------------------------
// K/V assembles (table RoPE) -> bf16 hi/lo, vectorized (proven in R13)
// ---------------------------------------------------------------------------
__global__ void assemble_k4() {
    constexpr size_t total4 = (size_t)B_ * HKV_ * S_ * DH_ / 4;
    size_t i = (size_t)blockIdx.x * blockDim.x + threadIdx.x;
    if (i >= total4) return;
    size_t idx = i * 4;
    int d  = (int)(idx % DH_);
    int s  = (int)((idx / DH_) % S_);
    int hk = (int)((idx / ((size_t)DH_ * S_)) % HKV_);
    int b  = (int)(idx / ((size_t)DH_ * S_ * HKV_));
    float v[4];
    if (d >= DR_) {
        const float* src = g_kvb + (size_t)(b * S_ + s) * (HKV_ * (DN_ + DV_)) + hk * (DN_ + DV_);
        float4 x = *reinterpret_cast<const float4*>(src + d - DR_);
        v[0] = x.x; v[1] = x.y; v[2] = x.z; v[3] = x.w;
    } else {
        int fi = d & 31;
        const float* kr = g_kva + (size_t)(b * S_ + s) * KVA_NPAD + RKV_;
        float4 x = *reinterpret_cast<const float4*>(kr + d);
        float4 r4;
        if (d < 32) {
            float4 p = *reinterpret_cast<const float4*>(kr + d + 32);
            r4 = make_float4(-p.x, -p.y, -p.z, -p.w);
        } else {
            r4 = *reinterpret_cast<const float4*>(kr + d - 32);
        }
        float4 ct = *reinterpret_cast<const float4*>(g_ct + s * 32 + fi);
        float4 st = *reinterpret_cast<const float4*>(g_st + s * 32 + fi);
        v[0] = x.x * ct.x + r4.x * st.x;
        v[1] = x.y * ct.y + r4.y * st.y;
        v[2] = x.z * ct.z + r4.z * st.z;
        v[3] = x.w * ct.w + r4.w * st.w;
    }
    split_store4(g_Kh, g_Kl, idx, v);
}

__global__ void assemble_v4() {
    constexpr size_t total4 = (size_t)B_ * HKV_ * DV_ * S_ / 4;
    size_t i = (size_t)blockIdx.x * blockDim.x + threadIdx.x;
    if (i >= total4) return;
    size_t idx = i * 4;
    int s0 = (int)(idx % S_);
    int d  = (int)((idx / S_) % DV_);
    int hk = (int)((idx / ((size_t)S_ * DV_)) % HKV_);
    int b  = (int)(idx / ((size_t)S_ * DV_ * HKV_));
    float v[4];
    #pragma unroll
    for (int k = 0; k < 4; ++k)
        v[k] = g_kvb[(size_t)(b * S_ + s0 + k) * (HKV_ * (DN_ + DV_)) + hk * (DN_ + DV_) + DN_ + d];
    split_store4(g_Vth, g_Vtl, idx, v);
}

// ---------------------------------------------------------------------------
// Flash attention on mma.sync bf16 hi/lo (R7-proven version: pre-split Q).
// ---------------------------------------------------------------------------
constexpr int FA_QSTR = 200;
constexpr int FA_VSTR = 72;
constexpr int FA_SMEM = (2 * 128 * FA_QSTR + 2 * 64 * FA_QSTR + 2 * 128 * FA_VSTR) * 2;

__global__ void __launch_bounds__(256, 1)
flash_mma() {
    extern __shared__ __align__(16) uint16_t fs[];
    uint16_t* Qh = fs;
    uint16_t* Ql = Qh + 128 * FA_QSTR;
    uint16_t* Kh = Ql + 128 * FA_QSTR;
    uint16_t* Kl = Kh + 64 * FA_QSTR;
    uint16_t* Vh = Kl + 64 * FA_QSTR;
    uint16_t* Vl = Vh + 128 * FA_VSTR;

    const int bh = blockIdx.x;
    const int b  = bh / H_;
    const int h  = bh % H_;
    const int hkv = h / G_;
    const int qb = (int)gridDim.y - 1 - (int)blockIdx.y;
    const int q0 = qb * 128;

    const int tid  = threadIdx.x;
    const int lane = tid & 31;
    const int wid  = tid >> 5;

    const __nv_bfloat16* Qhg = g_Qh + ((size_t)(b * H_ + h) * S_) * DH_;
    const __nv_bfloat16* Qlg = g_Ql + ((size_t)(b * H_ + h) * S_) * DH_;
    const __nv_bfloat16* Khg = g_Kh + ((size_t)(b * HKV_ + hkv) * S_) * DH_;
    const __nv_bfloat16* Klg = g_Kl + ((size_t)(b * HKV_ + hkv) * S_) * DH_;
    const __nv_bfloat16* Vhg = g_Vth + ((size_t)(b * HKV_ + hkv) * DV_) * S_;
    const __nv_bfloat16* Vlg = g_Vtl + ((size_t)(b * HKV_ + hkv) * DV_) * S_;

    {
        int r = tid >> 1, half = tid & 1;
        #pragma unroll
        for (int i = 0; i < 12; ++i) {
            int q = half * 12 + i;
            *reinterpret_cast<uint4*>(Qh + r * FA_QSTR + q * 8) =
                *reinterpret_cast<const uint4*>(Qhg + (size_t)(q0 + r) * DH_ + q * 8);
            *reinterpret_cast<uint4*>(Ql + r * FA_QSTR + q * 8) =
                *reinterpret_cast<const uint4*>(Qlg + (size_t)(q0 + r) * DH_ + q * 8);
        }
    }

    const int a_row = ((lane >> 3) & 1) * 8 + (lane & 7);
    const int a_kof = (lane >> 4) * 8;
    const int b_row = (lane >> 4) * 8 + (lane & 7);
    const int b_kof = ((lane >> 3) & 1) * 8;
    const int rl = lane >> 2, cb = (lane & 3) * 2;
    const int rg0 = q0 + wid * 16 + rl;
    const float scale = rsqrtf((float)DH_);

    float accO[8][2][4];
    #pragma unroll
    for (int i = 0; i < 8; ++i)
        #pragma unroll
        for (int j = 0; j < 2; ++j)
            #pragma unroll
            for (int q = 0; q < 4; ++q) accO[i][j][q] = 0.f;
    float m0 = -1e30f, m1 = -1e30f, l0 = 0.f, l1 = 0.f;

    const int T = 2 * (qb + 1);
    for (int t = 0; t < T; ++t) {
        const int j0 = t * 64;
        __syncthreads();
        {
            int r = tid >> 2, part = tid & 3;
            #pragma unroll
            for (int i = 0; i < 6; ++i) {
                int q = part * 6 + i;
                *reinterpret_cast<uint4*>(Kh + r * FA_QSTR + q * 8) =
                    *reinterpret_cast<const uint4*>(Khg + (size_t)(j0 + r) * DH_ + q * 8);
                *reinterpret_cast<uint4*>(Kl + r * FA_QSTR + q * 8) =
                    *reinterpret_cast<const uint4*>(Klg + (size_t)(j0 + r) * DH_ + q * 8);
            }
        }
        {
            int r = tid >> 1, part = tid & 1;
            #pragma unroll
            for (int i = 0; i < 4; ++i) {
                int q = part * 4 + i;
                *reinterpret_cast<uint4*>(Vh + r * FA_VSTR + q * 8) =
                    *reinterpret_cast<const uint4*>(Vhg + (size_t)r * S_ + j0 + q * 8);
                *reinterpret_cast<uint4*>(Vl + r * FA_VSTR + q * 8) =
                    *reinterpret_cast<const uint4*>(Vlg + (size_t)r * S_ + j0 + q * 8);
            }
        }
        __syncthreads();

        float Sc[4][2][4];
        #pragma unroll
        for (int i = 0; i < 4; ++i)
            #pragma unroll
            for (int j = 0; j < 2; ++j)
                #pragma unroll
                for (int q = 0; q < 4; ++q) Sc[i][j][q] = 0.f;

        #pragma unroll
        for (int ks = 0; ks < 12; ++ks) {
            uint32_t ah[4], al[4];
            uint32_t qoff = (uint32_t)((wid * 16 + a_row) * FA_QSTR + ks * 16 + a_kof) * 2;
            ldm_x4(ah, smem_u32(Qh) + qoff);
            ldm_x4(al, smem_u32(Ql) + qoff);
            #pragma unroll
            for (int nb = 0; nb < 4; ++nb) {
                uint32_t koff = (uint32_t)((nb * 16 + b_row) * FA_QSTR + ks * 16 + b_kof) * 2;
                uint32_t bh4[4], bl4[4];
                ldm_x4(bh4, smem_u32(Kh) + koff);
                ldm_x4(bl4, smem_u32(Kl) + koff);
                mma_bf16(Sc[nb][0], ah, bh4 + 0);
                mma_bf16(Sc[nb][1], ah, bh4 + 2);
                mma_bf16(Sc[nb][0], ah, bl4 + 0);
                mma_bf16(Sc[nb][1], ah, bl4 + 2);
                mma_bf16(Sc[nb][0], al, bh4 + 0);
                mma_bf16(Sc[nb][1], al, bh4 + 2);
            }
        }

        const bool domask = (j0 + 63) > (q0 + wid * 16);
        #pragma unroll
        for (int nb = 0; nb < 4; ++nb)
            #pragma unroll
            for (int mm = 0; mm < 2; ++mm) {
                int c = j0 + nb * 16 + mm * 8 + cb;
                float* s4 = Sc[nb][mm];
                s4[0] *= scale; s4[1] *= scale; s4[2] *= scale; s4[3] *= scale;
                if (domask) {
                    if (c     > rg0)     s4[0] = -1e30f;
                    if (c + 1 > rg0)     s4[1] = -1e30f;
                    if (c     > rg0 + 8) s4[2] = -1e30f;
                    if (c + 1 > rg0 + 8) s4[3] = -1e30f;
                }
            }

        float mx0 = -1e30f, mx1 = -1e30f;
        #pragma unroll
        for (int nb = 0; nb < 4; ++nb)
            #pragma unroll
            for (int mm = 0; mm < 2; ++mm) {
                mx0 = fmaxf(mx0, fmaxf(Sc[nb][mm][0], Sc[nb][mm][1]));
                mx1 = fmaxf(mx1, fmaxf(Sc[nb][mm][2], Sc[nb][mm][3]));
            }
        mx0 = fmaxf(mx0, __shfl_xor_sync(0xffffffff, mx0, 1));
        mx0 = fmaxf(mx0, __shfl_xor_sync(0xffffffff, mx0, 2));
        mx1 = fmaxf(mx1, __shfl_xor_sync(0xffffffff, mx1, 1));
        mx1 = fmaxf(mx1, __shfl_xor_sync(0xffffffff, mx1, 2));
        float mn0 = fmaxf(m0, mx0), mn1 = fmaxf(m1, mx1);
        float corr0 = __expf(m0 - mn0), corr1 = __expf(m1 - mn1);
        m0 = mn0; m1 = mn1;

        uint32_t aPh[4][4], aPl[4][4];
        float sum0 = 0.f, sum1 = 0.f;
        #pragma unroll
        for (int nb = 0; nb < 4; ++nb) {
            float e00, e01, e02, e03, e10, e11, e12, e13;
            e00 = __expf(Sc[nb][0][0] - mn0);  e01 = __expf(Sc[nb][0][1] - mn0);
            e02 = __expf(Sc[nb][0][2] - mn1);  e03 = __expf(Sc[nb][0][3] - mn1);
            e10 = __expf(Sc[nb][1][0] - mn0);  e11 = __expf(Sc[nb][1][1] - mn0);
            e12 = __expf(Sc[nb][1][2] - mn1);  e13 = __expf(Sc[nb][1][3] - mn1);
            sum0 += e00 + e01 + e10 + e11;
            sum1 += e02 + e03 + e12 + e13;
            aPh[nb][0] = pack_hi2(e00, e01);  aPl[nb][0] = pack_lo2(e00, e01);
            aPh[nb][1] = pack_hi2(e02, e03);  aPl[nb][1] = pack_lo2(e02, e03);
            aPh[nb][2] = pack_hi2(e10, e11);  aPl[nb][2] = pack_lo2(e10, e11);
            aPh[nb][3] = pack_hi2(e12, e13);  aPl[nb][3] = pack_lo2(e12, e13);
        }
        sum0 += __shfl_xor_sync(0xffffffff, sum0, 1);
        sum0 += __shfl_xor_sync(0xffffffff, sum0, 2);
        sum1 += __shfl_xor_sync(0xffffffff, sum1, 1);
        sum1 += __shfl_xor_sync(0xffffffff, sum1, 2);
        l0 = l0 * corr0 + sum0;
        l1 = l1 * corr1 + sum1;

        #pragma unroll
        for (int nv = 0; nv < 8; ++nv)
            #pragma unroll
            for (int mm = 0; mm < 2; ++mm) {
                accO[nv][mm][0] *= corr0; accO[nv][mm][1] *= corr0;
                accO[nv][mm][2] *= corr1; accO[nv][mm][3] *= corr1;
            }

        #pragma unroll
        for (int ks = 0; ks < 4; ++ks) {
            #pragma unroll
            for (int nv = 0; nv < 8; ++nv) {
                uint32_t voff = (uint32_t)((nv * 16 + b_row) * FA_VSTR + ks * 16 + b_kof) * 2;
                uint32_t bh4[4], bl4[4];
                ldm_x4(bh4, smem_u32(Vh) + voff);
                ldm_x4(bl4, smem_u32(Vl) + voff);
                mma_bf16(accO[nv][0], aPh[ks], bh4 + 0);
                mma_bf16(accO[nv][1], aPh[ks], bh4 + 2);
                mma_bf16(accO[nv][0], aPh[ks], bl4 + 0);
                mma_bf16(accO[nv][1], aPh[ks], bl4 + 2);
                mma_bf16(accO[nv][0], aPl[ks], bh4 + 0);
                mma_bf16(accO[nv][1], aPl[ks], bh4 + 2);
            }
        }
    }

    const float il0 = 1.0f / l0, il1 = 1.0f / l1;
    #pragma unroll
    for (int nv = 0; nv < 8; ++nv)
        #pragma unroll
        for (int mm = 0; mm < 2; ++mm) {
            int c = nv * 16 + mm * 8 + cb;
            size_t base0 = ((size_t)(b * S_) + rg0)     * (H_ * DV_) + h * DV_ + c;
            size_t base1 = ((size_t)(b * S_) + rg0 + 8) * (H_ * DV_) + h * DV_ + c;
            float x0 = accO[nv][mm][0] * il0, y0 = accO[nv][mm][1] * il0;
            float x1 = accO[nv][mm][2] * il1, y1 = accO[nv][mm][3] * il1;
            *reinterpret_cast<uint32_t*>(g_atth + base0) = pack_hi2(x0, y0);
            *reinterpret_cast<uint32_t*>(g_attl + base0) = pack_lo2(x0, y0);
            *reinterpret_cast<uint32_t*>(g_atth + base1) = pack_hi2(x1, y1);
            *reinterpret_cast<uint32_t*>(g_attl + base1) = pack_lo2(x1, y1);
        }
}

// ---------------------------------------------------------------------------
// Launch sequence (single stream)
// ---------------------------------------------------------------------------
extern "C" void kernel_launch(void* const* d_in, const int* in_sizes, int n_in,
                              void* d_out, int out_size) {
    const float* hs    = (const float*)d_in[0];
    const float* w_qa  = (const float*)d_in[2];
    const float* b_qa  = (const float*)d_in[3];
    const float* gq    = (const float*)d_in[4];
    const float* w_qb  = (const float*)d_in[5];
    const float* b_qb  = (const float*)d_in[6];
    const float* w_kva = (const float*)d_in[7];
    const float* b_kva = (const float*)d_in[8];
    const float* gkv   = (const float*)d_in[9];
    const float* w_kvb = (const float*)d_in[10];
    const float* b_kvb = (const float*)d_in[11];
    const float* w_o   = (const float*)d_in[12];
    const float* b_o   = (const float*)d_in[13];
    float* out = (float*)d_out;

    float *p_qa, *p_kva, *p_kvb, *p_bkva;
    cudaGetSymbolAddress((void**)&p_qa,   g_qa);
    cudaGetSymbolAddress((void**)&p_kva,  g_kva);
    cudaGetSymbolAddress((void**)&p_kvb,  g_kvb);
    cudaGetSymbolAddress((void**)&p_bkva, g_bkva);
    __nv_bfloat16 *qa_h, *qa_l, *qb_h, *qb_l, *kva_h, *kva_l, *kvb_h, *kvb_l, *o_h, *o_l;
    cudaGetSymbolAddress((void**)&qa_h,  g_wqa_h);  cudaGetSymbolAddress((void**)&qa_l,  g_wqa_l);
    cudaGetSymbolAddress((void**)&qb_h,  g_wqb_h);  cudaGetSymbolAddress((void**)&qb_l,  g_wqb_l);
    cudaGetSymbolAddress((void**)&kva_h, g_wkva_h); cudaGetSymbolAddress((void**)&kva_l, g_wkva_l);
    cudaGetSymbolAddress((void**)&kvb_h, g_wkvb_h); cudaGetSymbolAddress((void**)&kvb_l, g_wkvb_l);
    cudaGetSymbolAddress((void**)&o_h,   g_wo_h);   cudaGetSymbolAddress((void**)&o_l,   g_wo_l);
    __nv_bfloat16 *hs_h, *hs_l, *qn_h, *qn_l, *kvn_h, *kvn_l, *att_h, *att_l;
    cudaGetSymbolAddress((void**)&hs_h,  g_hsh);  cudaGetSymbolAddress((void**)&hs_l,  g_hsl);
    cudaGetSymbolAddress((void**)&qn_h,  g_qnh);  cudaGetSymbolAddress((void**)&qn_l,  g_qnl);
    cudaGetSymbolAddress((void**)&kvn_h, g_kvnh); cudaGetSymbolAddress((void**)&kvn_l, g_kvnl);
    cudaGetSymbolAddress((void**)&att_h, g_atth); cudaGetSymbolAddress((void**)&att_l, g_attl);

    cudaFuncSetAttribute(flash_mma, cudaFuncAttributeMaxDynamicSharedMemorySize, FA_SMEM);
    cudaFuncSetAttribute(gemm_mma2, cudaFuncAttributeMaxDynamicSharedMemorySize, GEMM_SMEM2);
    cudaFuncSetAttribute(gemm_qb_rope, cudaFuncAttributeMaxDynamicSharedMemorySize, GEMM_SMEM2);

    // ---- prep: weights, bias pad, rope table, hs split ----
    dim3 tb(32, 8);
    prep_w<<<dim3(D_ / 32,  RQ_ / 32),           tb>>>(w_qa,  qa_h,  qa_l,  D_,  RQ_,       RQ_);
    prep_w<<<dim3(RQ_ / 32, (H_ * DH_) / 32),    tb>>>(w_qb,  qb_h,  qb_l,  RQ_, H_ * DH_,  H_ * DH_);
    prep_w<<<dim3(D_ / 32,  KVA_NPAD / 32),      tb>>>(w_kva, kva_h, kva_l, D_,  KVA_N,     KVA_NPAD);
    prep_w<<<dim3(RKV_ / 32, (HKV_ * 256) / 32), tb>>>(w_kvb, kvb_h, kvb_l, RKV_, HKV_ * 256, HKV_ * 256);
    prep_w<<<dim3(D_ / 32,  D_ / 32),            tb>>>(w_o,   o_h,   o_l,   D_,  D_,        D_);
    pad_bias_kva<<<(KVA_NPAD + 255) / 256, 256>>>(b_kva);
    rope_table<<<(S_ * 32 + 255) / 256, 256>>>();
    {
        constexpr size_t n4 = (size_t)M_ * D_ / 4;
        split_act4<<<(unsigned)((n4 + 255) / 256), 256>>>(
            (const float4*)hs, (uint2*)hs_h, (uint2*)hs_l, n4);
    }

    // ---- projections ----
    gemm_mma2<<<dim3(RQ_ / 128, M_ / 128), 256, GEMM_SMEM2>>>(hs_h, hs_l, qa_h, qa_l, b_qa, p_qa, M_, RQ_, D_);
    rmsnorm_split<<<M_, 256>>>(p_qa, gq, qn_h, qn_l, RQ_, RQ_);
    // qb GEMM with fused RoPE + Q assembly
    gemm_qb_rope<<<dim3((H_ * DH_) / 128, M_ / 128), 256, GEMM_SMEM2>>>(qn_h, qn_l, qb_h, qb_l, b_qb);
    gemm_mma2<<<dim3(KVA_NPAD / 128, M_ / 128), 256, GEMM_SMEM2>>>(hs_h, hs_l, kva_h, kva_l, p_bkva, p_kva, M_, KVA_NPAD, D_);
    rmsnorm_split<<<M_, 256>>>(p_kva, gkv, kvn_h, kvn_l, RKV_, KVA_NPAD);
    gemm_mma2<<<dim3((HKV_ * 256) / 128, M_ / 128), 256, GEMM_SMEM2>>>(kvn_h, kvn_l, kvb_h, kvb_l, b_kvb, p_kvb, M_, HKV_ * 256, RKV_);

    // ---- assemble K/V (vectorized 4-wide) ----
    {
        constexpr size_t tk4 = (size_t)B_ * HKV_ * S_ * DH_ / 4;
        assemble_k4<<<(unsigned)((tk4 + 255) / 256), 256>>>();
        constexpr size_t tv4 = (size_t)B_ * HKV_ * DV_ * S_ / 4;
        assemble_v4<<<(unsigned)((tv4 + 255) / 256), 256>>>();
    }

    // ---- attention + output projection ----
    flash_mma<<<dim3(B_ * H_, S_ / 128), 256, FA_SMEM>>>();
    gemm_mma2<<<dim3(D_ / 128, M_ / 128), 256, GEMM_SMEM2>>>(
        att_h, att_l, o_h, o_l, b_o, out, M_, D_, D_);
}

// round 16
// speedup vs baseline: 1.1138x; 1.0141x over previous
#include <cuda_runtime.h>
#include <cuda_bf16.h>
#include <cstdint>
#include <math.h>

// ---------------------------------------------------------------------------
// Problem constants
// ---------------------------------------------------------------------------
namespace {
constexpr int B_   = 2;
constexpr int S_   = 2048;
constexpr int D_   = 2048;
constexpr int H_   = 16;
constexpr int HKV_ = 4;
constexpr int G_   = H_ / HKV_;
constexpr int RQ_  = 1024;
constexpr int RKV_ = 512;
constexpr int DH_  = 192;
constexpr int DR_  = 64;
constexpr int DN_  = 128;
constexpr int DV_  = 128;
constexpr int M_   = B_ * S_;          // 4096
constexpr int KVA_N    = RKV_ + DR_;   // 576
constexpr int KVA_NPAD = 640;
}

// ---------------------------------------------------------------------------
// Scratch (static device globals)
// ---------------------------------------------------------------------------
__device__ float g_qa  [(size_t)M_ * RQ_];
__device__ float g_kva [(size_t)M_ * KVA_NPAD];
__device__ float g_bkva[KVA_NPAD];
__device__ float g_ct  [S_ * 32];
__device__ float g_st  [S_ * 32];

// pre-split activations (bf16 hi/lo)
__device__ __nv_bfloat16 g_hsh [(size_t)M_ * D_];
__device__ __nv_bfloat16 g_hsl [(size_t)M_ * D_];
__device__ __nv_bfloat16 g_qnh [(size_t)M_ * RQ_];
__device__ __nv_bfloat16 g_qnl [(size_t)M_ * RQ_];
__device__ __nv_bfloat16 g_kvnh[(size_t)M_ * RKV_];
__device__ __nv_bfloat16 g_kvnl[(size_t)M_ * RKV_];
__device__ __nv_bfloat16 g_atth[(size_t)M_ * H_ * DV_];
__device__ __nv_bfloat16 g_attl[(size_t)M_ * H_ * DV_];

// bf16 hi/lo Q/K ([b,h/hkv,s,d]) and V transposed ([b,hkv,d,s])
__device__ __nv_bfloat16 g_Qh [(size_t)B_ * H_   * S_ * DH_];
__device__ __nv_bfloat16 g_Ql [(size_t)B_ * H_   * S_ * DH_];
__device__ __nv_bfloat16 g_Kh [(size_t)B_ * HKV_ * S_ * DH_];
__device__ __nv_bfloat16 g_Kl [(size_t)B_ * HKV_ * S_ * DH_];
__device__ __nv_bfloat16 g_Vth[(size_t)B_ * HKV_ * DV_ * S_];
__device__ __nv_bfloat16 g_Vtl[(size_t)B_ * HKV_ * DV_ * S_];

// Pre-split / transposed weights: [N, K] bf16, hi + lo
__device__ __nv_bfloat16 g_wqa_h [(size_t)RQ_ * D_];
__device__ __nv_bfloat16 g_wqa_l [(size_t)RQ_ * D_];
__device__ __nv_bfloat16 g_wqb_h [(size_t)(H_ * DH_) * RQ_];
__device__ __nv_bfloat16 g_wqb_l [(size_t)(H_ * DH_) * RQ_];
__device__ __nv_bfloat16 g_wkva_h[(size_t)KVA_NPAD * D_];
__device__ __nv_bfloat16 g_wkva_l[(size_t)KVA_NPAD * D_];
__device__ __nv_bfloat16 g_wkvb_h[(size_t)(HKV_ * (DN_ + DV_)) * RKV_];
__device__ __nv_bfloat16 g_wkvb_l[(size_t)(HKV_ * (DN_ + DV_)) * RKV_];
__device__ __nv_bfloat16 g_wo_h  [(size_t)D_ * D_];
__device__ __nv_bfloat16 g_wo_l  [(size_t)D_ * D_];

// ---------------------------------------------------------------------------
// mma.sync / cp.async helpers
// ---------------------------------------------------------------------------
__device__ __forceinline__ uint32_t smem_u32(const void* p) {
    return (uint32_t)__cvta_generic_to_shared(p);
}
__device__ __forceinline__ void ldm_x4(uint32_t* r, uint32_t addr) {
    asm volatile("ldmatrix.sync.aligned.m8n8.x4.shared.b16 {%0,%1,%2,%3}, [%4];"
                 : "=r"(r[0]), "=r"(r[1]), "=r"(r[2]), "=r"(r[3]) : "r"(addr));
}
__device__ __forceinline__ void mma_bf16(float* c, const uint32_t* a, const uint32_t* b) {
    asm volatile("mma.sync.aligned.m16n8k16.row.col.f32.bf16.bf16.f32 "
                 "{%0,%1,%2,%3}, {%4,%5,%6,%7}, {%8,%9}, {%0,%1,%2,%3};"
                 : "+f"(c[0]), "+f"(c[1]), "+f"(c[2]), "+f"(c[3])
                 : "r"(a[0]), "r"(a[1]), "r"(a[2]), "r"(a[3]), "r"(b[0]), "r"(b[1]));
}
__device__ __forceinline__ void cp16(uint32_t dst, const void* src) {
    asm volatile("cp.async.cg.shared.global [%0], [%1], 16;"
                 :: "r"(dst), "l"(__cvta_generic_to_global(src)));
}
__device__ __forceinline__ void cp_commit() {
    asm volatile("cp.async.commit_group;");
}
template <int N_> __device__ __forceinline__ void cp_wait() {
    asm volatile("cp.async.wait_group %0;" :: "n"(N_));
}
__device__ __forceinline__ uint32_t pack_bf2(__nv_bfloat16 a, __nv_bfloat16 b) {
    return (uint32_t)__bfloat16_as_ushort(a) | ((uint32_t)__bfloat16_as_ushort(b) << 16);
}
__device__ __forceinline__ uint32_t pack_hi2(float x, float y) {
    return pack_bf2(__float2bfloat16(x), __float2bfloat16(y));
}
__device__ __forceinline__ uint32_t pack_lo2(float x, float y) {
    __nv_bfloat16 hx = __float2bfloat16(x), hy = __float2bfloat16(y);
    return pack_bf2(__float2bfloat16(x - __bfloat162float(hx)),
                    __float2bfloat16(y - __bfloat162float(hy)));
}
__device__ __forceinline__ void split_store(__nv_bfloat16* Hh, __nv_bfloat16* Ll,
                                            size_t idx, float v) {
    __nv_bfloat16 h = __float2bfloat16(v);
    Hh[idx] = h;
    Ll[idx] = __float2bfloat16(v - __bfloat162float(h));
}
__device__ __forceinline__ void split_store4(__nv_bfloat16* Hh, __nv_bfloat16* Ll,
                                             size_t idx, const float* v) {
    *reinterpret_cast<uint2*>(Hh + idx) = make_uint2(pack_hi2(v[0], v[1]), pack_hi2(v[2], v[3]));
    *reinterpret_cast<uint2*>(Ll + idx) = make_uint2(pack_lo2(v[0], v[1]), pack_lo2(v[2], v[3]));
}

// ---------------------------------------------------------------------------
// Prep kernels
// ---------------------------------------------------------------------------
__global__ void prep_w(const float* __restrict__ W, __nv_bfloat16* __restrict__ Hh,
                       __nv_bfloat16* __restrict__ Ll, int K, int N, int Npad) {
    __shared__ float t[32][33];
    const int kb = blockIdx.x * 32, nb = blockIdx.y * 32;
    const int tx = threadIdx.x, ty = threadIdx.y;
    #pragma unroll
    for (int i = 0; i < 4; ++i) {
        int k = kb + ty + i * 8;
        int n = nb + tx;
        t[ty + i * 8][tx] = (n < N) ? W[(size_t)k * N + n] : 0.f;
    }
    __syncthreads();
    #pragma unroll
    for (int i = 0; i < 4; ++i) {
        int n = nb + ty + i * 8;
        if (n >= Npad) continue;
        int k = kb + tx;
        split_store(Hh, Ll, (size_t)n * K + k, t[tx][ty + i * 8]);
    }
}

__global__ void pad_bias_kva(const float* __restrict__ b) {
    int i = threadIdx.x + blockIdx.x * blockDim.x;
    if (i < KVA_NPAD) g_bkva[i] = (i < KVA_N) ? b[i] : 0.f;
}

__global__ void rope_table() {
    int i = blockIdx.x * blockDim.x + threadIdx.x;
    if (i >= S_ * 32) return;
    int s = i >> 5, fi = i & 31;
    float ang = (float)s * powf(10000.0f, -(float)(2 * fi) / 64.0f);
    g_ct[i] = cosf(ang);
    g_st[i] = sinf(ang);
}

__global__ void split_act4(const float4* __restrict__ X, uint2* __restrict__ Hh,
                           uint2* __restrict__ Ll, size_t n4) {
    size_t i = (size_t)blockIdx.x * blockDim.x + threadIdx.x;
    if (i >= n4) return;
    float4 v = X[i];
    Hh[i] = make_uint2(pack_hi2(v.x, v.y), pack_hi2(v.z, v.w));
    Ll[i] = make_uint2(pack_lo2(v.x, v.y), pack_lo2(v.z, v.w));
}

// ---------------------------------------------------------------------------
// HMMA GEMM (R7-proven): 2-stage cp.async, k-chunk 32, one sync per chunk.
// ---------------------------------------------------------------------------
constexpr int ASTRIDE = 40;
constexpr int GARR    = 128 * ASTRIDE;
constexpr int GEMM_SMEM2 = 2 * 4 * GARR * 2;

#define GEMM_MAINLOOP(Agh, Agl, Bgh, Bgl, K)                                          \
    const int nch = (K) >> 5;                                                         \
    auto prefetch = [&](int c) {                                                      \
        const int k0 = c << 5;                                                        \
        const int s = c & 1;                                                          \
        _Pragma("unroll")                                                             \
        for (int it = 0; it < 8; ++it) {                                              \
            int idx = tid + it * 256;                                                 \
            int arr = idx >> 9;                                                       \
            int j   = idx & 511;                                                      \
            int r   = j >> 2, q = j & 3;                                              \
            const __nv_bfloat16* src = (arr == 0) ? (Agh) : (arr == 1) ? (Agl)        \
                                     : (arr == 2) ? (Bgh) : (Bgl);                    \
            size_t goff = (size_t)(((arr < 2) ? row0 : col0) + r) * (K) + k0 + q * 8; \
            uint32_t dst = sb + (uint32_t)(((s * 4 + arr) * 128 + r) * ASTRIDE + q * 8) * 2; \
            cp16(dst, src + goff);                                                    \
        }                                                                             \
        cp_commit();                                                                  \
    };                                                                                \
    prefetch(0);                                                                      \
    for (int c = 0; c < nch; ++c) {                                                   \
        cp_wait<0>();                                                                 \
        __syncthreads();                                                              \
        if (c + 1 < nch) prefetch(c + 1);                                             \
        const uint32_t base = sb + (uint32_t)((c & 1) * 4 * GARR) * 2;                \
        const uint32_t sAh = base;                                                    \
        const uint32_t sAl = base + (uint32_t)GARR * 2;                               \
        const uint32_t sBh = base + (uint32_t)GARR * 4;                               \
        const uint32_t sBl = base + (uint32_t)GARR * 6;                               \
        _Pragma("unroll")                                                             \
        for (int ks = 0; ks < 2; ++ks) {                                              \
            const int ke = ks * 16;                                                   \
            uint32_t a_h[2][4], a_l[2][4];                                            \
            _Pragma("unroll")                                                         \
            for (int mi = 0; mi < 2; ++mi) {                                          \
                int r = wm * 32 + mi * 16 + a_row;                                    \
                uint32_t off = (uint32_t)(r * ASTRIDE + ke + a_kof) * 2;              \
                ldm_x4(a_h[mi], sAh + off);                                           \
                ldm_x4(a_l[mi], sAl + off);                                           \
            }                                                                         \
            _Pragma("unroll")                                                         \
            for (int nb = 0; nb < 4; ++nb) {                                          \
                int n = wn * 64 + nb * 16 + b_row;                                    \
                uint32_t off = (uint32_t)(n * ASTRIDE + ke + b_kof) * 2;              \
                uint32_t b_h[4], b_l[4];                                              \
                ldm_x4(b_h, sBh + off);                                               \
                ldm_x4(b_l, sBl + off);                                               \
                _Pragma("unroll")                                                     \
                for (int mi = 0; mi < 2; ++mi) {                                      \
                    mma_bf16(acc[mi][nb * 2 + 0], a_h[mi], b_h + 0);                  \
                    mma_bf16(acc[mi][nb * 2 + 1], a_h[mi], b_h + 2);                  \
                    mma_bf16(acc[mi][nb * 2 + 0], a_h[mi], b_l + 0);                  \
                    mma_bf16(acc[mi][nb * 2 + 1], a_h[mi], b_l + 2);                  \
                    mma_bf16(acc[mi][nb * 2 + 0], a_l[mi], b_h + 0);                  \
                    mma_bf16(acc[mi][nb * 2 + 1], a_l[mi], b_h + 2);                  \
                }                                                                     \
            }                                                                         \
        }                                                                             \
    }

#define GEMM_PREAMBLE                                                                 \
    extern __shared__ __align__(16) uint16_t gs[];                                    \
    const int tid  = threadIdx.x;                                                     \
    const int lane = tid & 31;                                                        \
    const int wid  = tid >> 5;                                                        \
    const int wm   = wid & 3;                                                         \
    const int wn   = wid >> 2;                                                        \
    const int row0 = blockIdx.y * 128, col0 = blockIdx.x * 128;                       \
    const uint32_t sb = smem_u32(gs);                                                 \
    float acc[2][8][4];                                                               \
    _Pragma("unroll")                                                                 \
    for (int i = 0; i < 2; ++i)                                                       \
        _Pragma("unroll")                                                             \
        for (int j = 0; j < 8; ++j)                                                   \
            _Pragma("unroll")                                                         \
            for (int q = 0; q < 4; ++q) acc[i][j][q] = 0.f;                           \
    const int a_row = ((lane >> 3) & 1) * 8 + (lane & 7);                             \
    const int a_kof = (lane >> 4) * 8;                                                \
    const int b_row = (lane >> 4) * 8 + (lane & 7);                                   \
    const int b_kof = ((lane >> 3) & 1) * 8;

__global__ void __launch_bounds__(256)
gemm_mma2(const __nv_bfloat16* __restrict__ Agh, const __nv_bfloat16* __restrict__ Agl,
          const __nv_bfloat16* __restrict__ Bgh, const __nv_bfloat16* __restrict__ Bgl,
          const float* __restrict__ bias, float* __restrict__ C,
          int M, int N, int K) {
    GEMM_PREAMBLE
    GEMM_MAINLOOP(Agh, Agl, Bgh, Bgl, K)

    #pragma unroll
    for (int mi = 0; mi < 2; ++mi) {
        int r = row0 + wm * 32 + mi * 16 + (lane >> 2);
        #pragma unroll
        for (int nj = 0; nj < 8; ++nj) {
            int c = col0 + wn * 64 + nj * 8 + (lane & 3) * 2;
            float2 b2 = *reinterpret_cast<const float2*>(bias + c);
            float2 o0, o1;
            o0.x = acc[mi][nj][0] + b2.x;
            o0.y = acc[mi][nj][1] + b2.y;
            o1.x = acc[mi][nj][2] + b2.x;
            o1.y = acc[mi][nj][3] + b2.y;
            *reinterpret_cast<float2*>(C + (size_t)r * N + c)       = o0;
            *reinterpret_cast<float2*>(C + (size_t)(r + 8) * N + c) = o1;
        }
    }
}

// qb GEMM with fused bias + RoPE + hi/lo split epilogue -> g_Qh/g_Ql. (R14-proven)
__global__ void __launch_bounds__(256)
gemm_qb_rope(const __nv_bfloat16* __restrict__ Agh, const __nv_bfloat16* __restrict__ Agl,
             const __nv_bfloat16* __restrict__ Bgh, const __nv_bfloat16* __restrict__ Bgl,
             const float* __restrict__ bias) {
    GEMM_PREAMBLE
    GEMM_MAINLOOP(Agh, Agl, Bgh, Bgl, RQ_)

    const int bi   = (col0 >> 6) + wn;
    const int type = bi % 3;
    const int hh   = bi / 3;
    const int cbl  = (lane & 3) * 2;
    const float* biasw = bias + col0 + wn * 64;

    #pragma unroll
    for (int mi = 0; mi < 2; ++mi) {
        #pragma unroll
        for (int rr = 0; rr < 2; ++rr) {
            int r = row0 + wm * 32 + mi * 16 + (lane >> 2) + rr * 8;
            int bb = r >> 11, s = r & (S_ - 1);
            size_t qbase = ((size_t)(bb * H_ + hh) * S_ + s) * DH_;
            #pragma unroll
            for (int nj = 0; nj < 8; ++nj) {
                int cc = nj * 8 + cbl;
                float x0 = acc[mi][nj][rr * 2 + 0] + biasw[cc];
                float x1 = acc[mi][nj][rr * 2 + 1] + biasw[cc + 1];
                int out_d;
                float v0, v1;
                if (type < 2) {
                    out_d = DR_ + type * 64 + cc;
                    v0 = x0; v1 = x1;
                } else {
                    out_d = cc;
                    int fi = cc & 31;
                    float ct0 = g_ct[s * 32 + fi],     st0 = g_st[s * 32 + fi];
                    float ct1 = g_ct[s * 32 + fi + 1], st1 = g_st[s * 32 + fi + 1];
                    float p0, p1;
                    if (nj < 4) {
                        p0 = -(acc[mi][nj + 4][rr * 2 + 0] + biasw[cc + 32]);
                        p1 = -(acc[mi][nj + 4][rr * 2 + 1] + biasw[cc + 33]);
                    } else {
                        p0 =  (acc[mi][nj - 4][rr * 2 + 0] + biasw[cc - 32]);
                        p1 =  (acc[mi][nj - 4][rr * 2 + 1] + biasw[cc - 31]);
                    }
                    v0 = x0 * ct0 + p0 * st0;
                    v1 = x1 * ct1 + p1 * st1;
                }
                *reinterpret_cast<uint32_t*>(g_Qh + qbase + out_d) = pack_hi2(v0, v1);
                *reinterpret_cast<uint32_t*>(g_Ql + qbase + out_d) = pack_lo2(v0, v1);
            }
        }
    }
}

// kvb GEMM with fused epilogue. N=1024; 128-col blocks alternate:
// even block -> k_nrope (write g_Kh/g_Kl at d=64+cc, [s,d] layout),
// odd block  -> V (transpose via smem -> g_Vth/g_Vtl, [d,s] layout).
constexpr int VT_STR = 136;   // smem uint16 stride for V transpose (16B-aligned rows)

__global__ void __launch_bounds__(256)
gemm_kvb_fused(const __nv_bfloat16* __restrict__ Agh, const __nv_bfloat16* __restrict__ Agl,
               const __nv_bfloat16* __restrict__ Bgh, const __nv_bfloat16* __restrict__ Bgl,
               const float* __restrict__ bias) {
    GEMM_PREAMBLE
    GEMM_MAINLOOP(Agh, Agl, Bgh, Bgl, RKV_)

    const int colblk = (int)blockIdx.x;    // 0..7
    const int hk  = colblk >> 1;
    const int isv = colblk & 1;
    const int cbl = (lane & 3) * 2;
    const float* biasw = bias + col0;
    const int bb = row0 >> 11;
    const int s_base = row0 & (S_ - 1);

    if (!isv) {
        // ---- K-nrope: d = 64 + cc128 ----
        #pragma unroll
        for (int mi = 0; mi < 2; ++mi) {
            #pragma unroll
            for (int rr = 0; rr < 2; ++rr) {
                int r = row0 + wm * 32 + mi * 16 + (lane >> 2) + rr * 8;
                int s = r & (S_ - 1);
                size_t kbase = ((size_t)(bb * HKV_ + hk) * S_ + s) * DH_ + DR_;
                #pragma unroll
                for (int nj = 0; nj < 8; ++nj) {
                    int cc = wn * 64 + nj * 8 + cbl;
                    float v0 = acc[mi][nj][rr * 2 + 0] + biasw[cc];
                    float v1 = acc[mi][nj][rr * 2 + 1] + biasw[cc + 1];
                    *reinterpret_cast<uint32_t*>(g_Kh + kbase + cc) = pack_hi2(v0, v1);
                    *reinterpret_cast<uint32_t*>(g_Kl + kbase + cc) = pack_lo2(v0, v1);
                }
            }
        }
    } else {
        // ---- V: transpose 128x128 tile via smem ----
        uint16_t* sh = gs;                    // hi: 128 * VT_STR uint16
        uint16_t* sl = gs + 128 * VT_STR;     // lo
        __syncthreads();                      // mainloop smem reads done
        #pragma unroll
        for (int mi = 0; mi < 2; ++mi) {
            #pragma unroll
            for (int rr = 0; rr < 2; ++rr) {
                int rl2 = wm * 32 + mi * 16 + (lane >> 2) + rr * 8;   // 0..127
                #pragma unroll
                for (int nj = 0; nj < 8; ++nj) {
                    int cc = wn * 64 + nj * 8 + cbl;
                    float v0 = acc[mi][nj][rr * 2 + 0] + biasw[cc];
                    float v1 = acc[mi][nj][rr * 2 + 1] + biasw[cc + 1];
                    __nv_bfloat16 h0 = __float2bfloat16(v0);
                    __nv_bfloat16 h1 = __float2bfloat16(v1);
                    sh[cc * VT_STR + rl2]       = __bfloat16_as_ushort(h0);
                    sh[(cc + 1) * VT_STR + rl2] = __bfloat16_as_ushort(h1);
                    sl[cc * VT_STR + rl2]       =
                        __bfloat16_as_ushort(__float2bfloat16(v0 - __bfloat162float(h0)));
                    sl[(cc + 1) * VT_STR + rl2] =
                        __bfloat16_as_ushort(__float2bfloat16(v1 - __bfloat162float(h1)));
                }
            }
        }
        __syncthreads();
        size_t vbase = ((size_t)(bb * HKV_ + hk) * DV_) * S_;
        #pragma unroll
        for (int it = 0; it < 8; ++it) {
            int chunk = tid + it * 256;       // 0..2047
            int d = chunk >> 4, seg = chunk & 15;
            uint4 vh = *reinterpret_cast<const uint4*>(sh + d * VT_STR + seg * 8);
            uint4 vl = *reinterpret_cast<const uint4*>(sl + d * VT_STR + seg * 8);
            size_t o = vbase + (size_t)d * S_ + s_base + seg * 8;
            *reinterpret_cast<uint4*>(g_Vth + o) = vh;
            *reinterpret_cast<uint4*>(g_Vtl + o) = vl;
        }
    }
}

// ---------------------------------------------------------------------------
// RMSNorm with fused hi/lo split output
// ---------------------------------------------------------------------------
__global__ void rmsnorm_split(const float* __restrict__ in, const float* __restrict__ g,
                              __nv_bfloat16* __restrict__ oh, __nv_bfloat16* __restrict__ ol,
                              int ncols, int in_stride) {
    const int row = blockIdx.x;
    const float* x = in + (size_t)row * in_stride;
    float ss = 0.f;
    for (int c = threadIdx.x; c < ncols; c += blockDim.x) {
        float v = x[c];
        ss += v * v;
    }
    __shared__ float red[32];
    #pragma unroll
    for (int o = 16; o > 0; o >>= 1) ss += __shfl_xor_sync(0xffffffff, ss, o);
    if ((threadIdx.x & 31) == 0) red[threadIdx.x >> 5] = ss;
    __syncthreads();
    __shared__ float s_scale;
    if (threadIdx.x == 0) {
        float t = 0.f;
        int nw = blockDim.x >> 5;
        for (int i = 0; i < nw; ++i) t += red[i];
        s_scale = 1.0f / sqrtf(t / (float)ncols + 1e-20f);
    }
    __syncthreads();
    const float sc = s_scale;
    size_t base = (size_t)row * ncols;
    for (int c = threadIdx.x; c < ncols; c += blockDim.x)
        split_store(oh, ol, base + c, x[c] * sc * g[c]);
}

// ---------------------------------------------------------------------------
// K rope part only (d < 64, from g_kva), vectorized 4-wide
// ---------------------------------------------------------------------------
__global__ void assemble_krope4() {
    constexpr size_t total4 = (size_t)B_ * HKV_ * S_ * DR_ / 4;
    size_t i = (size_t)blockIdx.x * blockDim.x + threadIdx.x;
    if (i >= total4) return;
    size_t idx = i * 4;
    int d  = (int)(idx % DR_);
    int s  = (int)((idx / DR_) % S_);
    int hk = (int)((idx / ((size_t)DR_ * S_)) % HKV_);
    int b  = (int)(idx / ((size_t)DR_ * S_ * HKV_));
    int fi = d & 31;
    const float* kr = g_kva + (size_t)(b * S_ + s) * KVA_NPAD + RKV_;
    float4 x = *reinterpret_cast<const float4*>(kr + d);
    float4 r4;
    if (d < 32) {
        float4 p = *reinterpret_cast<const float4*>(kr + d + 32);
        r4 = make_float4(-p.x, -p.y, -p.z, -p.w);
    } else {
        r4 = *reinterpret_cast<const float4*>(kr + d - 32);
    }
    float4 ct = *reinterpret_cast<const float4*>(g_ct + s * 32 + fi);
    float4 st = *reinterpret_cast<const float4*>(g_st + s * 32 + fi);
    float v[4];
    v[0] = x.x * ct.x + r4.x * st.x;
    v[1] = x.y * ct.y + r4.y * st.y;
    v[2] = x.z * ct.z + r4.z * st.z;
    v[3] = x.w * ct.w + r4.w * st.w;
    size_t outb = ((size_t)(b * HKV_ + hk) * S_ + s) * DH_ + d;
    split_store4(g_Kh, g_Kl, outb, v);
}

// ---------------------------------------------------------------------------
// Flash attention on mma.sync bf16 hi/lo (R7-proven version: pre-split Q).
// ---------------------------------------------------------------------------
constexpr int FA_QSTR = 200;
constexpr int FA_VSTR = 72;
constexpr int FA_SMEM = (2 * 128 * FA_QSTR + 2 * 64 * FA_QSTR + 2 * 128 * FA_VSTR) * 2;

__global__ void __launch_bounds__(256, 1)
flash_mma() {
    extern __shared__ __align__(16) uint16_t fs[];
    uint16_t* Qh = fs;
    uint16_t* Ql = Qh + 128 * FA_QSTR;
    uint16_t* Kh = Ql + 128 * FA_QSTR;
    uint16_t* Kl = Kh + 64 * FA_QSTR;
    uint16_t* Vh = Kl + 64 * FA_QSTR;
    uint16_t* Vl = Vh + 128 * FA_VSTR;

    const int bh = blockIdx.x;
    const int b  = bh / H_;
    const int h  = bh % H_;
    const int hkv = h / G_;
    const int qb = (int)gridDim.y - 1 - (int)blockIdx.y;
    const int q0 = qb * 128;

    const int tid  = threadIdx.x;
    const int lane = tid & 31;
    const int wid  = tid >> 5;

    const __nv_bfloat16* Qhg = g_Qh + ((size_t)(b * H_ + h) * S_) * DH_;
    const __nv_bfloat16* Qlg = g_Ql + ((size_t)(b * H_ + h) * S_) * DH_;
    const __nv_bfloat16* Khg = g_Kh + ((size_t)(b * HKV_ + hkv) * S_) * DH_;
    const __nv_bfloat16* Klg = g_Kl + ((size_t)(b * HKV_ + hkv) * S_) * DH_;
    const __nv_bfloat16* Vhg = g_Vth + ((size_t)(b * HKV_ + hkv) * DV_) * S_;
    const __nv_bfloat16* Vlg = g_Vtl + ((size_t)(b * HKV_ + hkv) * DV_) * S_;

    {
        int r = tid >> 1, half = tid & 1;
        #pragma unroll
        for (int i = 0; i < 12; ++i) {
            int q = half * 12 + i;
            *reinterpret_cast<uint4*>(Qh + r * FA_QSTR + q * 8) =
                *reinterpret_cast<const uint4*>(Qhg + (size_t)(q0 + r) * DH_ + q * 8);
            *reinterpret_cast<uint4*>(Ql + r * FA_QSTR + q * 8) =
                *reinterpret_cast<const uint4*>(Qlg + (size_t)(q0 + r) * DH_ + q * 8);
        }
    }

    const int a_row = ((lane >> 3) & 1) * 8 + (lane & 7);
    const int a_kof = (lane >> 4) * 8;
    const int b_row = (lane >> 4) * 8 + (lane & 7);
    const int b_kof = ((lane >> 3) & 1) * 8;
    const int rl = lane >> 2, cb = (lane & 3) * 2;
    const int rg0 = q0 + wid * 16 + rl;
    const float scale = rsqrtf((float)DH_);

    float accO[8][2][4];
    #pragma unroll
    for (int i = 0; i < 8; ++i)
        #pragma unroll
        for (int j = 0; j < 2; ++j)
            #pragma unroll
            for (int q = 0; q < 4; ++q) accO[i][j][q] = 0.f;
    float m0 = -1e30f, m1 = -1e30f, l0 = 0.f, l1 = 0.f;

    const int T = 2 * (qb + 1);
    for (int t = 0; t < T; ++t) {
        const int j0 = t * 64;
        __syncthreads();
        {
            int r = tid >> 2, part = tid & 3;
            #pragma unroll
            for (int i = 0; i < 6; ++i) {
                int q = part * 6 + i;
                *reinterpret_cast<uint4*>(Kh + r * FA_QSTR + q * 8) =
                    *reinterpret_cast<const uint4*>(Khg + (size_t)(j0 + r) * DH_ + q * 8);
                *reinterpret_cast<uint4*>(Kl + r * FA_QSTR + q * 8) =
                    *reinterpret_cast<const uint4*>(Klg + (size_t)(j0 + r) * DH_ + q * 8);
            }
        }
        {
            int r = tid >> 1, part = tid & 1;
            #pragma unroll
            for (int i = 0; i < 4; ++i) {
                int q = part * 4 + i;
                *reinterpret_cast<uint4*>(Vh + r * FA_VSTR + q * 8) =
                    *reinterpret_cast<const uint4*>(Vhg + (size_t)r * S_ + j0 + q * 8);
                *reinterpret_cast<uint4*>(Vl + r * FA_VSTR + q * 8) =
                    *reinterpret_cast<const uint4*>(Vlg + (size_t)r * S_ + j0 + q * 8);
            }
        }
        __syncthreads();

        float Sc[4][2][4];
        #pragma unroll
        for (int i = 0; i < 4; ++i)
            #pragma unroll
            for (int j = 0; j < 2; ++j)
                #pragma unroll
                for (int q = 0; q < 4; ++q) Sc[i][j][q] = 0.f;

        #pragma unroll
        for (int ks = 0; ks < 12; ++ks) {
            uint32_t ah[4], al[4];
            uint32_t qoff = (uint32_t)((wid * 16 + a_row) * FA_QSTR + ks * 16 + a_kof) * 2;
            ldm_x4(ah, smem_u32(Qh) + qoff);
            ldm_x4(al, smem_u32(Ql) + qoff);
            #pragma unroll
            for (int nb = 0; nb < 4; ++nb) {
                uint32_t koff = (uint32_t)((nb * 16 + b_row) * FA_QSTR + ks * 16 + b_kof) * 2;
                uint32_t bh4[4], bl4[4];
                ldm_x4(bh4, smem_u32(Kh) + koff);
                ldm_x4(bl4, smem_u32(Kl) + koff);
                mma_bf16(Sc[nb][0], ah, bh4 + 0);
                mma_bf16(Sc[nb][1], ah, bh4 + 2);
                mma_bf16(Sc[nb][0], ah, bl4 + 0);
                mma_bf16(Sc[nb][1], ah, bl4 + 2);
                mma_bf16(Sc[nb][0], al, bh4 + 0);
                mma_bf16(Sc[nb][1], al, bh4 + 2);
            }
        }

        const bool domask = (j0 + 63) > (q0 + wid * 16);
        #pragma unroll
        for (int nb = 0; nb < 4; ++nb)
            #pragma unroll
            for (int mm = 0; mm < 2; ++mm) {
                int c = j0 + nb * 16 + mm * 8 + cb;
                float* s4 = Sc[nb][mm];
                s4[0] *= scale; s4[1] *= scale; s4[2] *= scale; s4[3] *= scale;
                if (domask) {
                    if (c     > rg0)     s4[0] = -1e30f;
                    if (c + 1 > rg0)     s4[1] = -1e30f;
                    if (c     > rg0 + 8) s4[2] = -1e30f;
                    if (c + 1 > rg0 + 8) s4[3] = -1e30f;
                }
            }

        float mx0 = -1e30f, mx1 = -1e30f;
        #pragma unroll
        for (int nb = 0; nb < 4; ++nb)
            #pragma unroll
            for (int mm = 0; mm < 2; ++mm) {
                mx0 = fmaxf(mx0, fmaxf(Sc[nb][mm][0], Sc[nb][mm][1]));
                mx1 = fmaxf(mx1, fmaxf(Sc[nb][mm][2], Sc[nb][mm][3]));
            }
        mx0 = fmaxf(mx0, __shfl_xor_sync(0xffffffff, mx0, 1));
        mx0 = fmaxf(mx0, __shfl_xor_sync(0xffffffff, mx0, 2));
        mx1 = fmaxf(mx1, __shfl_xor_sync(0xffffffff, mx1, 1));
        mx1 = fmaxf(mx1, __shfl_xor_sync(0xffffffff, mx1, 2));
        float mn0 = fmaxf(m0, mx0), mn1 = fmaxf(m1, mx1);
        float corr0 = __expf(m0 - mn0), corr1 = __expf(m1 - mn1);
        m0 = mn0; m1 = mn1;

        uint32_t aPh[4][4], aPl[4][4];
        float sum0 = 0.f, sum1 = 0.f;
        #pragma unroll
        for (int nb = 0; nb < 4; ++nb) {
            float e00, e01, e02, e03, e10, e11, e12, e13;
            e00 = __expf(Sc[nb][0][0] - mn0);  e01 = __expf(Sc[nb][0][1] - mn0);
            e02 = __expf(Sc[nb][0][2] - mn1);  e03 = __expf(Sc[nb][0][3] - mn1);
            e10 = __expf(Sc[nb][1][0] - mn0);  e11 = __expf(Sc[nb][1][1] - mn0);
            e12 = __expf(Sc[nb][1][2] - mn1);  e13 = __expf(Sc[nb][1][3] - mn1);
            sum0 += e00 + e01 + e10 + e11;
            sum1 += e02 + e03 + e12 + e13;
            aPh[nb][0] = pack_hi2(e00, e01);  aPl[nb][0] = pack_lo2(e00, e01);
            aPh[nb][1] = pack_hi2(e02, e03);  aPl[nb][1] = pack_lo2(e02, e03);
            aPh[nb][2] = pack_hi2(e10, e11);  aPl[nb][2] = pack_lo2(e10, e11);
            aPh[nb][3] = pack_hi2(e12, e13);  aPl[nb][3] = pack_lo2(e12, e13);
        }
        sum0 += __shfl_xor_sync(0xffffffff, sum0, 1);
        sum0 += __shfl_xor_sync(0xffffffff, sum0, 2);
        sum1 += __shfl_xor_sync(0xffffffff, sum1, 1);
        sum1 += __shfl_xor_sync(0xffffffff, sum1, 2);
        l0 = l0 * corr0 + sum0;
        l1 = l1 * corr1 + sum1;

        #pragma unroll
        for (int nv = 0; nv < 8; ++nv)
            #pragma unroll
            for (int mm = 0; mm < 2; ++mm) {
                accO[nv][mm][0] *= corr0; accO[nv][mm][1] *= corr0;
                accO[nv][mm][2] *= corr1; accO[nv][mm][3] *= corr1;
            }

        #pragma unroll
        for (int ks = 0; ks < 4; ++ks) {
            #pragma unroll
            for (int nv = 0; nv < 8; ++nv) {
                uint32_t voff = (uint32_t)((nv * 16 + b_row) * FA_VSTR + ks * 16 + b_kof) * 2;
                uint32_t bh4[4], bl4[4];
                ldm_x4(bh4, smem_u32(Vh) + voff);
                ldm_x4(bl4, smem_u32(Vl) + voff);
                mma_bf16(accO[nv][0], aPh[ks], bh4 + 0);
                mma_bf16(accO[nv][1], aPh[ks], bh4 + 2);
                mma_bf16(accO[nv][0], aPh[ks], bl4 + 0);
                mma_bf16(accO[nv][1], aPh[ks], bl4 + 2);
                mma_bf16(accO[nv][0], aPl[ks], bh4 + 0);
                mma_bf16(accO[nv][1], aPl[ks], bh4 + 2);
            }
        }
    }

    const float il0 = 1.0f / l0, il1 = 1.0f / l1;
    #pragma unroll
    for (int nv = 0; nv < 8; ++nv)
        #pragma unroll
        for (int mm = 0; mm < 2; ++mm) {
            int c = nv * 16 + mm * 8 + cb;
            size_t base0 = ((size_t)(b * S_) + rg0)     * (H_ * DV_) + h * DV_ + c;
            size_t base1 = ((size_t)(b * S_) + rg0 + 8) * (H_ * DV_) + h * DV_ + c;
            float x0 = accO[nv][mm][0] * il0, y0 = accO[nv][mm][1] * il0;
            float x1 = accO[nv][mm][2] * il1, y1 = accO[nv][mm][3] * il1;
            *reinterpret_cast<uint32_t*>(g_atth + base0) = pack_hi2(x0, y0);
            *reinterpret_cast<uint32_t*>(g_attl + base0) = pack_lo2(x0, y0);
            *reinterpret_cast<uint32_t*>(g_atth + base1) = pack_hi2(x1, y1);
            *reinterpret_cast<uint32_t*>(g_attl + base1) = pack_lo2(x1, y1);
        }
}

// ---------------------------------------------------------------------------
// Launch sequence (single stream)
// ---------------------------------------------------------------------------
extern "C" void kernel_launch(void* const* d_in, const int* in_sizes, int n_in,
                              void* d_out, int out_size) {
    const float* hs    = (const float*)d_in[0];
    const float* w_qa  = (const float*)d_in[2];
    const float* b_qa  = (const float*)d_in[3];
    const float* gq    = (const float*)d_in[4];
    const float* w_qb  = (const float*)d_in[5];
    const float* b_qb  = (const float*)d_in[6];
    const float* w_kva = (const float*)d_in[7];
    const float* b_kva = (const float*)d_in[8];
    const float* gkv   = (const float*)d_in[9];
    const float* w_kvb = (const float*)d_in[10];
    const float* b_kvb = (const float*)d_in[11];
    const float* w_o   = (const float*)d_in[12];
    const float* b_o   = (const float*)d_in[13];
    float* out = (float*)d_out;

    float *p_qa, *p_kva, *p_bkva;
    cudaGetSymbolAddress((void**)&p_qa,   g_qa);
    cudaGetSymbolAddress((void**)&p_kva,  g_kva);
    cudaGetSymbolAddress((void**)&p_bkva, g_bkva);
    __nv_bfloat16 *qa_h, *qa_l, *qb_h, *qb_l, *kva_h, *kva_l, *kvb_h, *kvb_l, *o_h, *o_l;
    cudaGetSymbolAddress((void**)&qa_h,  g_wqa_h);  cudaGetSymbolAddress((void**)&qa_l,  g_wqa_l);
    cudaGetSymbolAddress((void**)&qb_h,  g_wqb_h);  cudaGetSymbolAddress((void**)&qb_l,  g_wqb_l);
    cudaGetSymbolAddress((void**)&kva_h, g_wkva_h); cudaGetSymbolAddress((void**)&kva_l, g_wkva_l);
    cudaGetSymbolAddress((void**)&kvb_h, g_wkvb_h); cudaGetSymbolAddress((void**)&kvb_l, g_wkvb_l);
    cudaGetSymbolAddress((void**)&o_h,   g_wo_h);   cudaGetSymbolAddress((void**)&o_l,   g_wo_l);
    __nv_bfloat16 *hs_h, *hs_l, *qn_h, *qn_l, *kvn_h, *kvn_l, *att_h, *att_l;
    cudaGetSymbolAddress((void**)&hs_h,  g_hsh);  cudaGetSymbolAddress((void**)&hs_l,  g_hsl);
    cudaGetSymbolAddress((void**)&qn_h,  g_qnh);  cudaGetSymbolAddress((void**)&qn_l,  g_qnl);
    cudaGetSymbolAddress((void**)&kvn_h, g_kvnh); cudaGetSymbolAddress((void**)&kvn_l, g_kvnl);
    cudaGetSymbolAddress((void**)&att_h, g_atth); cudaGetSymbolAddress((void**)&att_l, g_attl);

    cudaFuncSetAttribute(flash_mma, cudaFuncAttributeMaxDynamicSharedMemorySize, FA_SMEM);
    cudaFuncSetAttribute(gemm_mma2, cudaFuncAttributeMaxDynamicSharedMemorySize, GEMM_SMEM2);
    cudaFuncSetAttribute(gemm_qb_rope, cudaFuncAttributeMaxDynamicSharedMemorySize, GEMM_SMEM2);
    cudaFuncSetAttribute(gemm_kvb_fused, cudaFuncAttributeMaxDynamicSharedMemorySize, GEMM_SMEM2);

    // ---- prep: weights, bias pad, rope table, hs split ----
    dim3 tb(32, 8);
    prep_w<<<dim3(D_ / 32,  RQ_ / 32),           tb>>>(w_qa,  qa_h,  qa_l,  D_,  RQ_,       RQ_);
    prep_w<<<dim3(RQ_ / 32, (H_ * DH_) / 32),    tb>>>(w_qb,  qb_h,  qb_l,  RQ_, H_ * DH_,  H_ * DH_);
    prep_w<<<dim3(D_ / 32,  KVA_NPAD / 32),      tb>>>(w_kva, kva_h, kva_l, D_,  KVA_N,     KVA_NPAD);
    prep_w<<<dim3(RKV_ / 32, (HKV_ * 256) / 32), tb>>>(w_kvb, kvb_h, kvb_l, RKV_, HKV_ * 256, HKV_ * 256);
    prep_w<<<dim3(D_ / 32,  D_ / 32),            tb>>>(w_o,   o_h,   o_l,   D_,  D_,        D_);
    pad_bias_kva<<<(KVA_NPAD + 255) / 256, 256>>>(b_kva);
    rope_table<<<(S_ * 32 + 255) / 256, 256>>>();
    {
        constexpr size_t n4 = (size_t)M_ * D_ / 4;
        split_act4<<<(unsigned)((n4 + 255) / 256), 256>>>(
            (const float4*)hs, (uint2*)hs_h, (uint2*)hs_l, n4);
    }

    // ---- projections ----
    gemm_mma2<<<dim3(RQ_ / 128, M_ / 128), 256, GEMM_SMEM2>>>(hs_h, hs_l, qa_h, qa_l, b_qa, p_qa, M_, RQ_, D_);
    rmsnorm_split<<<M_, 256>>>(p_qa, gq, qn_h, qn_l, RQ_, RQ_);
    gemm_qb_rope<<<dim3((H_ * DH_) / 128, M_ / 128), 256, GEMM_SMEM2>>>(qn_h, qn_l, qb_h, qb_l, b_qb);
    gemm_mma2<<<dim3(KVA_NPAD / 128, M_ / 128), 256, GEMM_SMEM2>>>(hs_h, hs_l, kva_h, kva_l, p_bkva, p_kva, M_, KVA_NPAD, D_);
    rmsnorm_split<<<M_, 256>>>(p_kva, gkv, kvn_h, kvn_l, RKV_, KVA_NPAD);
    // kvb GEMM with fused K-nrope / V-transpose epilogue
    gemm_kvb_fused<<<dim3((HKV_ * 256) / 128, M_ / 128), 256, GEMM_SMEM2>>>(kvn_h, kvn_l, kvb_h, kvb_l, b_kvb);

    // ---- K rope part (d<64) ----
    {
        constexpr size_t tk4 = (size_t)B_ * HKV_ * S_ * DR_ / 4;
        assemble_krope4<<<(unsigned)((tk4 + 255) / 256), 256>>>();
    }

    // ---- attention + output projection ----
    flash_mma<<<dim3(B_ * H_, S_ / 128), 256, FA_SMEM>>>();
    gemm_mma2<<<dim3(D_ / 128, M_ / 128), 256, GEMM_SMEM2>>>(
        att_h, att_l, o_h, o_l, b_o, out, M_, D_, D_);
}

// round 17
// speedup vs baseline: 1.1304x; 1.0149x over previous
#include <cuda_runtime.h>
#include <cuda_bf16.h>
#include <cstdint>
#include <math.h>

// ---------------------------------------------------------------------------
// Problem constants
// ---------------------------------------------------------------------------
namespace {
constexpr int B_   = 2;
constexpr int S_   = 2048;
constexpr int D_   = 2048;
constexpr int H_   = 16;
constexpr int HKV_ = 4;
constexpr int G_   = H_ / HKV_;
constexpr int RQ_  = 1024;
constexpr int RKV_ = 512;
constexpr int DH_  = 192;
constexpr int DR_  = 64;
constexpr int DN_  = 128;
constexpr int DV_  = 128;
constexpr int M_   = B_ * S_;          // 4096
constexpr int KVA_N    = RKV_ + DR_;   // 576
constexpr int KVA_NPAD = 640;
}

// ---------------------------------------------------------------------------
// Scratch (static device globals)
// ---------------------------------------------------------------------------
__device__ float g_qa  [(size_t)M_ * RQ_];
__device__ float g_kva [(size_t)M_ * KVA_NPAD];
__device__ float g_bkva[KVA_NPAD];
__device__ float g_ct  [S_ * 32];
__device__ float g_st  [S_ * 32];

// pre-split activations (bf16 hi/lo)
__device__ __nv_bfloat16 g_hsh [(size_t)M_ * D_];
__device__ __nv_bfloat16 g_hsl [(size_t)M_ * D_];
__device__ __nv_bfloat16 g_qnh [(size_t)M_ * RQ_];
__device__ __nv_bfloat16 g_qnl [(size_t)M_ * RQ_];
__device__ __nv_bfloat16 g_kvnh[(size_t)M_ * RKV_];
__device__ __nv_bfloat16 g_kvnl[(size_t)M_ * RKV_];
__device__ __nv_bfloat16 g_atth[(size_t)M_ * H_ * DV_];
__device__ __nv_bfloat16 g_attl[(size_t)M_ * H_ * DV_];

// bf16 hi/lo Q/K ([b,h/hkv,s,d]) and V transposed ([b,hkv,d,s])
__device__ __nv_bfloat16 g_Qh [(size_t)B_ * H_   * S_ * DH_];
__device__ __nv_bfloat16 g_Ql [(size_t)B_ * H_   * S_ * DH_];
__device__ __nv_bfloat16 g_Kh [(size_t)B_ * HKV_ * S_ * DH_];
__device__ __nv_bfloat16 g_Kl [(size_t)B_ * HKV_ * S_ * DH_];
__device__ __nv_bfloat16 g_Vth[(size_t)B_ * HKV_ * DV_ * S_];
__device__ __nv_bfloat16 g_Vtl[(size_t)B_ * HKV_ * DV_ * S_];

// Pre-split / transposed weights: [N, K] bf16, hi + lo
__device__ __nv_bfloat16 g_wqa_h [(size_t)RQ_ * D_];
__device__ __nv_bfloat16 g_wqa_l [(size_t)RQ_ * D_];
__device__ __nv_bfloat16 g_wqb_h [(size_t)(H_ * DH_) * RQ_];
__device__ __nv_bfloat16 g_wqb_l [(size_t)(H_ * DH_) * RQ_];
__device__ __nv_bfloat16 g_wkva_h[(size_t)KVA_NPAD * D_];
__device__ __nv_bfloat16 g_wkva_l[(size_t)KVA_NPAD * D_];
__device__ __nv_bfloat16 g_wkvb_h[(size_t)(HKV_ * (DN_ + DV_)) * RKV_];
__device__ __nv_bfloat16 g_wkvb_l[(size_t)(HKV_ * (DN_ + DV_)) * RKV_];
__device__ __nv_bfloat16 g_wo_h  [(size_t)D_ * D_];
__device__ __nv_bfloat16 g_wo_l  [(size_t)D_ * D_];

// ---------------------------------------------------------------------------
// mma.sync / cp.async helpers
// ---------------------------------------------------------------------------
__device__ __forceinline__ uint32_t smem_u32(const void* p) {
    return (uint32_t)__cvta_generic_to_shared(p);
}
__device__ __forceinline__ void ldm_x4(uint32_t* r, uint32_t addr) {
    asm volatile("ldmatrix.sync.aligned.m8n8.x4.shared.b16 {%0,%1,%2,%3}, [%4];"
                 : "=r"(r[0]), "=r"(r[1]), "=r"(r[2]), "=r"(r[3]) : "r"(addr));
}
__device__ __forceinline__ void mma_bf16(float* c, const uint32_t* a, const uint32_t* b) {
    asm volatile("mma.sync.aligned.m16n8k16.row.col.f32.bf16.bf16.f32 "
                 "{%0,%1,%2,%3}, {%4,%5,%6,%7}, {%8,%9}, {%0,%1,%2,%3};"
                 : "+f"(c[0]), "+f"(c[1]), "+f"(c[2]), "+f"(c[3])
                 : "r"(a[0]), "r"(a[1]), "r"(a[2]), "r"(a[3]), "r"(b[0]), "r"(b[1]));
}
__device__ __forceinline__ void cp16(uint32_t dst, const void* src) {
    asm volatile("cp.async.cg.shared.global [%0], [%1], 16;"
                 :: "r"(dst), "l"(__cvta_generic_to_global(src)));
}
__device__ __forceinline__ void cp_commit() {
    asm volatile("cp.async.commit_group;");
}
template <int N_> __device__ __forceinline__ void cp_wait() {
    asm volatile("cp.async.wait_group %0;" :: "n"(N_));
}
__device__ __forceinline__ uint32_t pack_bf2(__nv_bfloat16 a, __nv_bfloat16 b) {
    return (uint32_t)__bfloat16_as_ushort(a) | ((uint32_t)__bfloat16_as_ushort(b) << 16);
}
__device__ __forceinline__ uint32_t pack_hi2(float x, float y) {
    return pack_bf2(__float2bfloat16(x), __float2bfloat16(y));
}
__device__ __forceinline__ uint32_t pack_lo2(float x, float y) {
    __nv_bfloat16 hx = __float2bfloat16(x), hy = __float2bfloat16(y);
    return pack_bf2(__float2bfloat16(x - __bfloat162float(hx)),
                    __float2bfloat16(y - __bfloat162float(hy)));
}
__device__ __forceinline__ void split_store(__nv_bfloat16* Hh, __nv_bfloat16* Ll,
                                            size_t idx, float v) {
    __nv_bfloat16 h = __float2bfloat16(v);
    Hh[idx] = h;
    Ll[idx] = __float2bfloat16(v - __bfloat162float(h));
}
__device__ __forceinline__ void split_store4(__nv_bfloat16* Hh, __nv_bfloat16* Ll,
                                             size_t idx, const float* v) {
    *reinterpret_cast<uint2*>(Hh + idx) = make_uint2(pack_hi2(v[0], v[1]), pack_hi2(v[2], v[3]));
    *reinterpret_cast<uint2*>(Ll + idx) = make_uint2(pack_lo2(v[0], v[1]), pack_lo2(v[2], v[3]));
}

// ---------------------------------------------------------------------------
// Prep kernels
// ---------------------------------------------------------------------------
__global__ void prep_w(const float* __restrict__ W, __nv_bfloat16* __restrict__ Hh,
                       __nv_bfloat16* __restrict__ Ll, int K, int N, int Npad) {
    __shared__ float t[32][33];
    const int kb = blockIdx.x * 32, nb = blockIdx.y * 32;
    const int tx = threadIdx.x, ty = threadIdx.y;
    #pragma unroll
    for (int i = 0; i < 4; ++i) {
        int k = kb + ty + i * 8;
        int n = nb + tx;
        t[ty + i * 8][tx] = (n < N) ? W[(size_t)k * N + n] : 0.f;
    }
    __syncthreads();
    #pragma unroll
    for (int i = 0; i < 4; ++i) {
        int n = nb + ty + i * 8;
        if (n >= Npad) continue;
        int k = kb + tx;
        split_store(Hh, Ll, (size_t)n * K + k, t[tx][ty + i * 8]);
    }
}

__global__ void pad_bias_kva(const float* __restrict__ b) {
    int i = threadIdx.x + blockIdx.x * blockDim.x;
    if (i < KVA_NPAD) g_bkva[i] = (i < KVA_N) ? b[i] : 0.f;
}

__global__ void rope_table() {
    int i = blockIdx.x * blockDim.x + threadIdx.x;
    if (i >= S_ * 32) return;
    int s = i >> 5, fi = i & 31;
    float ang = (float)s * powf(10000.0f, -(float)(2 * fi) / 64.0f);
    g_ct[i] = cosf(ang);
    g_st[i] = sinf(ang);
}

__global__ void split_act4(const float4* __restrict__ X, uint2* __restrict__ Hh,
                           uint2* __restrict__ Ll, size_t n4) {
    size_t i = (size_t)blockIdx.x * blockDim.x + threadIdx.x;
    if (i >= n4) return;
    float4 v = X[i];
    Hh[i] = make_uint2(pack_hi2(v.x, v.y), pack_hi2(v.z, v.w));
    Ll[i] = make_uint2(pack_lo2(v.x, v.y), pack_lo2(v.z, v.w));
}

// ---------------------------------------------------------------------------
// HMMA GEMM (R7-proven): 2-stage cp.async, k-chunk 32, one sync per chunk.
// ---------------------------------------------------------------------------
constexpr int ASTRIDE = 40;
constexpr int GARR    = 128 * ASTRIDE;
constexpr int GEMM_SMEM2 = 2 * 4 * GARR * 2;

#define GEMM_MAINLOOP(Agh, Agl, Bgh, Bgl, K)                                          \
    const int nch = (K) >> 5;                                                         \
    auto prefetch = [&](int c) {                                                      \
        const int k0 = c << 5;                                                        \
        const int s = c & 1;                                                          \
        _Pragma("unroll")                                                             \
        for (int it = 0; it < 8; ++it) {                                              \
            int idx = tid + it * 256;                                                 \
            int arr = idx >> 9;                                                       \
            int j   = idx & 511;                                                      \
            int r   = j >> 2, q = j & 3;                                              \
            const __nv_bfloat16* src = (arr == 0) ? (Agh) : (arr == 1) ? (Agl)        \
                                     : (arr == 2) ? (Bgh) : (Bgl);                    \
            size_t goff = (size_t)(((arr < 2) ? row0 : col0) + r) * (K) + k0 + q * 8; \
            uint32_t dst = sb + (uint32_t)(((s * 4 + arr) * 128 + r) * ASTRIDE + q * 8) * 2; \
            cp16(dst, src + goff);                                                    \
        }                                                                             \
        cp_commit();                                                                  \
    };                                                                                \
    prefetch(0);                                                                      \
    for (int c = 0; c < nch; ++c) {                                                   \
        cp_wait<0>();                                                                 \
        __syncthreads();                                                              \
        if (c + 1 < nch) prefetch(c + 1);                                             \
        const uint32_t base = sb + (uint32_t)((c & 1) * 4 * GARR) * 2;                \
        const uint32_t sAh = base;                                                    \
        const uint32_t sAl = base + (uint32_t)GARR * 2;                               \
        const uint32_t sBh = base + (uint32_t)GARR * 4;                               \
        const uint32_t sBl = base + (uint32_t)GARR * 6;                               \
        _Pragma("unroll")                                                             \
        for (int ks = 0; ks < 2; ++ks) {                                              \
            const int ke = ks * 16;                                                   \
            uint32_t a_h[2][4], a_l[2][4];                                            \
            _Pragma("unroll")                                                         \
            for (int mi = 0; mi < 2; ++mi) {                                          \
                int r = wm * 32 + mi * 16 + a_row;                                    \
                uint32_t off = (uint32_t)(r * ASTRIDE + ke + a_kof) * 2;              \
                ldm_x4(a_h[mi], sAh + off);                                           \
                ldm_x4(a_l[mi], sAl + off);                                           \
            }                                                                         \
            _Pragma("unroll")                                                         \
            for (int nb = 0; nb < 4; ++nb) {                                          \
                int n = wn * 64 + nb * 16 + b_row;                                    \
                uint32_t off = (uint32_t)(n * ASTRIDE + ke + b_kof) * 2;              \
                uint32_t b_h[4], b_l[4];                                              \
                ldm_x4(b_h, sBh + off);                                               \
                ldm_x4(b_l, sBl + off);                                               \
                _Pragma("unroll")                                                     \
                for (int mi = 0; mi < 2; ++mi) {                                      \
                    mma_bf16(acc[mi][nb * 2 + 0], a_h[mi], b_h + 0);                  \
                    mma_bf16(acc[mi][nb * 2 + 1], a_h[mi], b_h + 2);                  \
                    mma_bf16(acc[mi][nb * 2 + 0], a_h[mi], b_l + 0);                  \
                    mma_bf16(acc[mi][nb * 2 + 1], a_h[mi], b_l + 2);                  \
                    mma_bf16(acc[mi][nb * 2 + 0], a_l[mi], b_h + 0);                  \
                    mma_bf16(acc[mi][nb * 2 + 1], a_l[mi], b_h + 2);                  \
                }                                                                     \
            }                                                                         \
        }                                                                             \
    }

#define GEMM_PREAMBLE                                                                 \
    extern __shared__ __align__(16) uint16_t gs[];                                    \
    const int tid  = threadIdx.x;                                                     \
    const int lane = tid & 31;                                                        \
    const int wid  = tid >> 5;                                                        \
    const int wm   = wid & 3;                                                         \
    const int wn   = wid >> 2;                                                        \
    const int row0 = blockIdx.y * 128, col0 = blockIdx.x * 128;                       \
    const uint32_t sb = smem_u32(gs);                                                 \
    float acc[2][8][4];                                                               \
    _Pragma("unroll")                                                                 \
    for (int i = 0; i < 2; ++i)                                                       \
        _Pragma("unroll")                                                             \
        for (int j = 0; j < 8; ++j)                                                   \
            _Pragma("unroll")                                                         \
            for (int q = 0; q < 4; ++q) acc[i][j][q] = 0.f;                           \
    const int a_row = ((lane >> 3) & 1) * 8 + (lane & 7);                             \
    const int a_kof = (lane >> 4) * 8;                                                \
    const int b_row = (lane >> 4) * 8 + (lane & 7);                                   \
    const int b_kof = ((lane >> 3) & 1) * 8;

__global__ void __launch_bounds__(256)
gemm_mma2(const __nv_bfloat16* __restrict__ Agh, const __nv_bfloat16* __restrict__ Agl,
          const __nv_bfloat16* __restrict__ Bgh, const __nv_bfloat16* __restrict__ Bgl,
          const float* __restrict__ bias, float* __restrict__ C,
          int M, int N, int K) {
    GEMM_PREAMBLE
    GEMM_MAINLOOP(Agh, Agl, Bgh, Bgl, K)

    #pragma unroll
    for (int mi = 0; mi < 2; ++mi) {
        int r = row0 + wm * 32 + mi * 16 + (lane >> 2);
        #pragma unroll
        for (int nj = 0; nj < 8; ++nj) {
            int c = col0 + wn * 64 + nj * 8 + (lane & 3) * 2;
            float2 b2 = *reinterpret_cast<const float2*>(bias + c);
            float2 o0, o1;
            o0.x = acc[mi][nj][0] + b2.x;
            o0.y = acc[mi][nj][1] + b2.y;
            o1.x = acc[mi][nj][2] + b2.x;
            o1.y = acc[mi][nj][3] + b2.y;
            *reinterpret_cast<float2*>(C + (size_t)r * N + c)       = o0;
            *reinterpret_cast<float2*>(C + (size_t)(r + 8) * N + c) = o1;
        }
    }
}

// qb GEMM with fused bias + RoPE + hi/lo split epilogue -> g_Qh/g_Ql. (R14-proven)
__global__ void __launch_bounds__(256)
gemm_qb_rope(const __nv_bfloat16* __restrict__ Agh, const __nv_bfloat16* __restrict__ Agl,
             const __nv_bfloat16* __restrict__ Bgh, const __nv_bfloat16* __restrict__ Bgl,
             const float* __restrict__ bias) {
    GEMM_PREAMBLE
    GEMM_MAINLOOP(Agh, Agl, Bgh, Bgl, RQ_)

    const int bi   = (col0 >> 6) + wn;
    const int type = bi % 3;
    const int hh   = bi / 3;
    const int cbl  = (lane & 3) * 2;
    const float* biasw = bias + col0 + wn * 64;

    #pragma unroll
    for (int mi = 0; mi < 2; ++mi) {
        #pragma unroll
        for (int rr = 0; rr < 2; ++rr) {
            int r = row0 + wm * 32 + mi * 16 + (lane >> 2) + rr * 8;
            int bb = r >> 11, s = r & (S_ - 1);
            size_t qbase = ((size_t)(bb * H_ + hh) * S_ + s) * DH_;
            #pragma unroll
            for (int nj = 0; nj < 8; ++nj) {
                int cc = nj * 8 + cbl;
                float x0 = acc[mi][nj][rr * 2 + 0] + biasw[cc];
                float x1 = acc[mi][nj][rr * 2 + 1] + biasw[cc + 1];
                int out_d;
                float v0, v1;
                if (type < 2) {
                    out_d = DR_ + type * 64 + cc;
                    v0 = x0; v1 = x1;
                } else {
                    out_d = cc;
                    int fi = cc & 31;
                    float ct0 = g_ct[s * 32 + fi],     st0 = g_st[s * 32 + fi];
                    float ct1 = g_ct[s * 32 + fi + 1], st1 = g_st[s * 32 + fi + 1];
                    float p0, p1;
                    if (nj < 4) {
                        p0 = -(acc[mi][nj + 4][rr * 2 + 0] + biasw[cc + 32]);
                        p1 = -(acc[mi][nj + 4][rr * 2 + 1] + biasw[cc + 33]);
                    } else {
                        p0 =  (acc[mi][nj - 4][rr * 2 + 0] + biasw[cc - 32]);
                        p1 =  (acc[mi][nj - 4][rr * 2 + 1] + biasw[cc - 31]);
                    }
                    v0 = x0 * ct0 + p0 * st0;
                    v1 = x1 * ct1 + p1 * st1;
                }
                *reinterpret_cast<uint32_t*>(g_Qh + qbase + out_d) = pack_hi2(v0, v1);
                *reinterpret_cast<uint32_t*>(g_Ql + qbase + out_d) = pack_lo2(v0, v1);
            }
        }
    }
}

// kva GEMM with fused K-rope epilogue. Blocks 0-3: plain fp32 C (for rmsnorm).
// Block 4 (cols 512-639): wn=0 warps apply bias+RoPE to cols 512-575 (= k_rope)
// and broadcast-write g_Kh/g_Kl[.., d<64] for all HKV heads; wn=1 (pad) idle.
__global__ void __launch_bounds__(256)
gemm_kva_fused(const __nv_bfloat16* __restrict__ Agh, const __nv_bfloat16* __restrict__ Agl,
               const __nv_bfloat16* __restrict__ Bgh, const __nv_bfloat16* __restrict__ Bgl,
               const float* __restrict__ bias, float* __restrict__ C) {
    GEMM_PREAMBLE
    GEMM_MAINLOOP(Agh, Agl, Bgh, Bgl, D_)

    const int cbl = (lane & 3) * 2;

    if (blockIdx.x < 4) {
        #pragma unroll
        for (int mi = 0; mi < 2; ++mi) {
            int r = row0 + wm * 32 + mi * 16 + (lane >> 2);
            #pragma unroll
            for (int nj = 0; nj < 8; ++nj) {
                int c = col0 + wn * 64 + nj * 8 + cbl;
                float2 b2 = *reinterpret_cast<const float2*>(bias + c);
                float2 o0, o1;
                o0.x = acc[mi][nj][0] + b2.x;
                o0.y = acc[mi][nj][1] + b2.y;
                o1.x = acc[mi][nj][2] + b2.x;
                o1.y = acc[mi][nj][3] + b2.y;
                *reinterpret_cast<float2*>(C + (size_t)r * KVA_NPAD + c)       = o0;
                *reinterpret_cast<float2*>(C + (size_t)(r + 8) * KVA_NPAD + c) = o1;
            }
        }
    } else if (wn == 0) {
        // rope columns: global col = 512 + cc, d = cc in [0,64)
        const float* biasw = bias + 512;
        #pragma unroll
        for (int mi = 0; mi < 2; ++mi) {
            #pragma unroll
            for (int rr = 0; rr < 2; ++rr) {
                int r = row0 + wm * 32 + mi * 16 + (lane >> 2) + rr * 8;
                int bb = r >> 11, s = r & (S_ - 1);
                #pragma unroll
                for (int nj = 0; nj < 8; ++nj) {
                    int cc = nj * 8 + cbl;
                    float x0 = acc[mi][nj][rr * 2 + 0] + biasw[cc];
                    float x1 = acc[mi][nj][rr * 2 + 1] + biasw[cc + 1];
                    int fi = cc & 31;
                    float ct0 = g_ct[s * 32 + fi],     st0 = g_st[s * 32 + fi];
                    float ct1 = g_ct[s * 32 + fi + 1], st1 = g_st[s * 32 + fi + 1];
                    float p0, p1;
                    if (nj < 4) {
                        p0 = -(acc[mi][nj + 4][rr * 2 + 0] + biasw[cc + 32]);
                        p1 = -(acc[mi][nj + 4][rr * 2 + 1] + biasw[cc + 33]);
                    } else {
                        p0 =  (acc[mi][nj - 4][rr * 2 + 0] + biasw[cc - 32]);
                        p1 =  (acc[mi][nj - 4][rr * 2 + 1] + biasw[cc - 31]);
                    }
                    float v0 = x0 * ct0 + p0 * st0;
                    float v1 = x1 * ct1 + p1 * st1;
                    uint32_t ph = pack_hi2(v0, v1), pl = pack_lo2(v0, v1);
                    #pragma unroll
                    for (int hk = 0; hk < HKV_; ++hk) {
                        size_t kbase = ((size_t)(bb * HKV_ + hk) * S_ + s) * DH_ + cc;
                        *reinterpret_cast<uint32_t*>(g_Kh + kbase) = ph;
                        *reinterpret_cast<uint32_t*>(g_Kl + kbase) = pl;
                    }
                }
            }
        }
    }
}

// kvb GEMM with fused epilogue (R16-proven).
constexpr int VT_STR = 136;

__global__ void __launch_bounds__(256)
gemm_kvb_fused(const __nv_bfloat16* __restrict__ Agh, const __nv_bfloat16* __restrict__ Agl,
               const __nv_bfloat16* __restrict__ Bgh, const __nv_bfloat16* __restrict__ Bgl,
               const float* __restrict__ bias) {
    GEMM_PREAMBLE
    GEMM_MAINLOOP(Agh, Agl, Bgh, Bgl, RKV_)

    const int colblk = (int)blockIdx.x;
    const int hk  = colblk >> 1;
    const int isv = colblk & 1;
    const int cbl = (lane & 3) * 2;
    const float* biasw = bias + col0;
    const int bb = row0 >> 11;
    const int s_base = row0 & (S_ - 1);

    if (!isv) {
        #pragma unroll
        for (int mi = 0; mi < 2; ++mi) {
            #pragma unroll
            for (int rr = 0; rr < 2; ++rr) {
                int r = row0 + wm * 32 + mi * 16 + (lane >> 2) + rr * 8;
                int s = r & (S_ - 1);
                size_t kbase = ((size_t)(bb * HKV_ + hk) * S_ + s) * DH_ + DR_;
                #pragma unroll
                for (int nj = 0; nj < 8; ++nj) {
                    int cc = wn * 64 + nj * 8 + cbl;
                    float v0 = acc[mi][nj][rr * 2 + 0] + biasw[cc];
                    float v1 = acc[mi][nj][rr * 2 + 1] + biasw[cc + 1];
                    *reinterpret_cast<uint32_t*>(g_Kh + kbase + cc) = pack_hi2(v0, v1);
                    *reinterpret_cast<uint32_t*>(g_Kl + kbase + cc) = pack_lo2(v0, v1);
                }
            }
        }
    } else {
        uint16_t* sh = gs;
        uint16_t* sl = gs + 128 * VT_STR;
        __syncthreads();
        #pragma unroll
        for (int mi = 0; mi < 2; ++mi) {
            #pragma unroll
            for (int rr = 0; rr < 2; ++rr) {
                int rl2 = wm * 32 + mi * 16 + (lane >> 2) + rr * 8;
                #pragma unroll
                for (int nj = 0; nj < 8; ++nj) {
                    int cc = wn * 64 + nj * 8 + cbl;
                    float v0 = acc[mi][nj][rr * 2 + 0] + biasw[cc];
                    float v1 = acc[mi][nj][rr * 2 + 1] + biasw[cc + 1];
                    __nv_bfloat16 h0 = __float2bfloat16(v0);
                    __nv_bfloat16 h1 = __float2bfloat16(v1);
                    sh[cc * VT_STR + rl2]       = __bfloat16_as_ushort(h0);
                    sh[(cc + 1) * VT_STR + rl2] = __bfloat16_as_ushort(h1);
                    sl[cc * VT_STR + rl2]       =
                        __bfloat16_as_ushort(__float2bfloat16(v0 - __bfloat162float(h0)));
                    sl[(cc + 1) * VT_STR + rl2] =
                        __bfloat16_as_ushort(__float2bfloat16(v1 - __bfloat162float(h1)));
                }
            }
        }
        __syncthreads();
        size_t vbase = ((size_t)(bb * HKV_ + hk) * DV_) * S_;
        #pragma unroll
        for (int it = 0; it < 8; ++it) {
            int chunk = tid + it * 256;
            int d = chunk >> 4, seg = chunk & 15;
            uint4 vh = *reinterpret_cast<const uint4*>(sh + d * VT_STR + seg * 8);
            uint4 vl = *reinterpret_cast<const uint4*>(sl + d * VT_STR + seg * 8);
            size_t o = vbase + (size_t)d * S_ + s_base + seg * 8;
            *reinterpret_cast<uint4*>(g_Vth + o) = vh;
            *reinterpret_cast<uint4*>(g_Vtl + o) = vl;
        }
    }
}

// ---------------------------------------------------------------------------
// RMSNorm, 4-wide vectorized (blockDim = ncols/4; one float4 per thread)
// ---------------------------------------------------------------------------
__global__ void rmsnorm_split4(const float* __restrict__ in, const float* __restrict__ g,
                               __nv_bfloat16* __restrict__ oh, __nv_bfloat16* __restrict__ ol,
                               int ncols, int in_stride) {
    const int row = blockIdx.x;
    const int c = threadIdx.x * 4;
    float4 v = *reinterpret_cast<const float4*>(in + (size_t)row * in_stride + c);
    float ss = v.x * v.x + v.y * v.y + v.z * v.z + v.w * v.w;
    __shared__ float red[32];
    #pragma unroll
    for (int o = 16; o > 0; o >>= 1) ss += __shfl_xor_sync(0xffffffff, ss, o);
    if ((threadIdx.x & 31) == 0) red[threadIdx.x >> 5] = ss;
    __syncthreads();
    __shared__ float s_scale;
    if (threadIdx.x == 0) {
        float t = 0.f;
        int nw = blockDim.x >> 5;
        for (int i = 0; i < nw; ++i) t += red[i];
        s_scale = 1.0f / sqrtf(t / (float)ncols + 1e-20f);
    }
    __syncthreads();
    const float sc = s_scale;
    float4 gv = *reinterpret_cast<const float4*>(g + c);
    float w[4];
    w[0] = v.x * sc * gv.x;
    w[1] = v.y * sc * gv.y;
    w[2] = v.z * sc * gv.z;
    w[3] = v.w * sc * gv.w;
    split_store4(oh, ol, (size_t)row * ncols + c, w);
}

// ---------------------------------------------------------------------------
// Flash attention on mma.sync bf16 hi/lo (R7-proven version: pre-split Q).
// ---------------------------------------------------------------------------
constexpr int FA_QSTR = 200;
constexpr int FA_VSTR = 72;
constexpr int FA_SMEM = (2 * 128 * FA_QSTR + 2 * 64 * FA_QSTR + 2 * 128 * FA_VSTR) * 2;

__global__ void __launch_bounds__(256, 1)
flash_mma() {
    extern __shared__ __align__(16) uint16_t fs[];
    uint16_t* Qh = fs;
    uint16_t* Ql = Qh + 128 * FA_QSTR;
    uint16_t* Kh = Ql + 128 * FA_QSTR;
    uint16_t* Kl = Kh + 64 * FA_QSTR;
    uint16_t* Vh = Kl + 64 * FA_QSTR;
    uint16_t* Vl = Vh + 128 * FA_VSTR;

    const int bh = blockIdx.x;
    const int b  = bh / H_;
    const int h  = bh % H_;
    const int hkv = h / G_;
    const int qb = (int)gridDim.y - 1 - (int)blockIdx.y;
    const int q0 = qb * 128;

    const int tid  = threadIdx.x;
    const int lane = tid & 31;
    const int wid  = tid >> 5;

    const __nv_bfloat16* Qhg = g_Qh + ((size_t)(b * H_ + h) * S_) * DH_;
    const __nv_bfloat16* Qlg = g_Ql + ((size_t)(b * H_ + h) * S_) * DH_;
    const __nv_bfloat16* Khg = g_Kh + ((size_t)(b * HKV_ + hkv) * S_) * DH_;
    const __nv_bfloat16* Klg = g_Kl + ((size_t)(b * HKV_ + hkv) * S_) * DH_;
    const __nv_bfloat16* Vhg = g_Vth + ((size_t)(b * HKV_ + hkv) * DV_) * S_;
    const __nv_bfloat16* Vlg = g_Vtl + ((size_t)(b * HKV_ + hkv) * DV_) * S_;

    {
        int r = tid >> 1, half = tid & 1;
        #pragma unroll
        for (int i = 0; i < 12; ++i) {
            int q = half * 12 + i;
            *reinterpret_cast<uint4*>(Qh + r * FA_QSTR + q * 8) =
                *reinterpret_cast<const uint4*>(Qhg + (size_t)(q0 + r) * DH_ + q * 8);
            *reinterpret_cast<uint4*>(Ql + r * FA_QSTR + q * 8) =
                *reinterpret_cast<const uint4*>(Qlg + (size_t)(q0 + r) * DH_ + q * 8);
        }
    }

    const int a_row = ((lane >> 3) & 1) * 8 + (lane & 7);
    const int a_kof = (lane >> 4) * 8;
    const int b_row = (lane >> 4) * 8 + (lane & 7);
    const int b_kof = ((lane >> 3) & 1) * 8;
    const int rl = lane >> 2, cb = (lane & 3) * 2;
    const int rg0 = q0 + wid * 16 + rl;
    const float scale = rsqrtf((float)DH_);

    float accO[8][2][4];
    #pragma unroll
    for (int i = 0; i < 8; ++i)
        #pragma unroll
        for (int j = 0; j < 2; ++j)
            #pragma unroll
            for (int q = 0; q < 4; ++q) accO[i][j][q] = 0.f;
    float m0 = -1e30f, m1 = -1e30f, l0 = 0.f, l1 = 0.f;

    const int T = 2 * (qb + 1);
    for (int t = 0; t < T; ++t) {
        const int j0 = t * 64;
        __syncthreads();
        {
            int r = tid >> 2, part = tid & 3;
            #pragma unroll
            for (int i = 0; i < 6; ++i) {
                int q = part * 6 + i;
                *reinterpret_cast<uint4*>(Kh + r * FA_QSTR + q * 8) =
                    *reinterpret_cast<const uint4*>(Khg + (size_t)(j0 + r) * DH_ + q * 8);
                *reinterpret_cast<uint4*>(Kl + r * FA_QSTR + q * 8) =
                    *reinterpret_cast<const uint4*>(Klg + (size_t)(j0 + r) * DH_ + q * 8);
            }
        }
        {
            int r = tid >> 1, part = tid & 1;
            #pragma unroll
            for (int i = 0; i < 4; ++i) {
                int q = part * 4 + i;
                *reinterpret_cast<uint4*>(Vh + r * FA_VSTR + q * 8) =
                    *reinterpret_cast<const uint4*>(Vhg + (size_t)r * S_ + j0 + q * 8);
                *reinterpret_cast<uint4*>(Vl + r * FA_VSTR + q * 8) =
                    *reinterpret_cast<const uint4*>(Vlg + (size_t)r * S_ + j0 + q * 8);
            }
        }
        __syncthreads();

        float Sc[4][2][4];
        #pragma unroll
        for (int i = 0; i < 4; ++i)
            #pragma unroll
            for (int j = 0; j < 2; ++j)
                #pragma unroll
                for (int q = 0; q < 4; ++q) Sc[i][j][q] = 0.f;

        #pragma unroll
        for (int ks = 0; ks < 12; ++ks) {
            uint32_t ah[4], al[4];
            uint32_t qoff = (uint32_t)((wid * 16 + a_row) * FA_QSTR + ks * 16 + a_kof) * 2;
            ldm_x4(ah, smem_u32(Qh) + qoff);
            ldm_x4(al, smem_u32(Ql) + qoff);
            #pragma unroll
            for (int nb = 0; nb < 4; ++nb) {
                uint32_t koff = (uint32_t)((nb * 16 + b_row) * FA_QSTR + ks * 16 + b_kof) * 2;
                uint32_t bh4[4], bl4[4];
                ldm_x4(bh4, smem_u32(Kh) + koff);
                ldm_x4(bl4, smem_u32(Kl) + koff);
                mma_bf16(Sc[nb][0], ah, bh4 + 0);
                mma_bf16(Sc[nb][1], ah, bh4 + 2);
                mma_bf16(Sc[nb][0], ah, bl4 + 0);
                mma_bf16(Sc[nb][1], ah, bl4 + 2);
                mma_bf16(Sc[nb][0], al, bh4 + 0);
                mma_bf16(Sc[nb][1], al, bh4 + 2);
            }
        }

        const bool domask = (j0 + 63) > (q0 + wid * 16);
        #pragma unroll
        for (int nb = 0; nb < 4; ++nb)
            #pragma unroll
            for (int mm = 0; mm < 2; ++mm) {
                int c = j0 + nb * 16 + mm * 8 + cb;
                float* s4 = Sc[nb][mm];
                s4[0] *= scale; s4[1] *= scale; s4[2] *= scale; s4[3] *= scale;
                if (domask) {
                    if (c     > rg0)     s4[0] = -1e30f;
                    if (c + 1 > rg0)     s4[1] = -1e30f;
                    if (c     > rg0 + 8) s4[2] = -1e30f;
                    if (c + 1 > rg0 + 8) s4[3] = -1e30f;
                }
            }

        float mx0 = -1e30f, mx1 = -1e30f;
        #pragma unroll
        for (int nb = 0; nb < 4; ++nb)
            #pragma unroll
            for (int mm = 0; mm < 2; ++mm) {
                mx0 = fmaxf(mx0, fmaxf(Sc[nb][mm][0], Sc[nb][mm][1]));
                mx1 = fmaxf(mx1, fmaxf(Sc[nb][mm][2], Sc[nb][mm][3]));
            }
        mx0 = fmaxf(mx0, __shfl_xor_sync(0xffffffff, mx0, 1));
        mx0 = fmaxf(mx0, __shfl_xor_sync(0xffffffff, mx0, 2));
        mx1 = fmaxf(mx1, __shfl_xor_sync(0xffffffff, mx1, 1));
        mx1 = fmaxf(mx1, __shfl_xor_sync(0xffffffff, mx1, 2));
        float mn0 = fmaxf(m0, mx0), mn1 = fmaxf(m1, mx1);
        float corr0 = __expf(m0 - mn0), corr1 = __expf(m1 - mn1);
        m0 = mn0; m1 = mn1;

        uint32_t aPh[4][4], aPl[4][4];
        float sum0 = 0.f, sum1 = 0.f;
        #pragma unroll
        for (int nb = 0; nb < 4; ++nb) {
            float e00, e01, e02, e03, e10, e11, e12, e13;
            e00 = __expf(Sc[nb][0][0] - mn0);  e01 = __expf(Sc[nb][0][1] - mn0);
            e02 = __expf(Sc[nb][0][2] - mn1);  e03 = __expf(Sc[nb][0][3] - mn1);
            e10 = __expf(Sc[nb][1][0] - mn0);  e11 = __expf(Sc[nb][1][1] - mn0);
            e12 = __expf(Sc[nb][1][2] - mn1);  e13 = __expf(Sc[nb][1][3] - mn1);
            sum0 += e00 + e01 + e10 + e11;
            sum1 += e02 + e03 + e12 + e13;
            aPh[nb][0] = pack_hi2(e00, e01);  aPl[nb][0] = pack_lo2(e00, e01);
            aPh[nb][1] = pack_hi2(e02, e03);  aPl[nb][1] = pack_lo2(e02, e03);
            aPh[nb][2] = pack_hi2(e10, e11);  aPl[nb][2] = pack_lo2(e10, e11);
            aPh[nb][3] = pack_hi2(e12, e13);  aPl[nb][3] = pack_lo2(e12, e13);
        }
        sum0 += __shfl_xor_sync(0xffffffff, sum0, 1);
        sum0 += __shfl_xor_sync(0xffffffff, sum0, 2);
        sum1 += __shfl_xor_sync(0xffffffff, sum1, 1);
        sum1 += __shfl_xor_sync(0xffffffff, sum1, 2);
        l0 = l0 * corr0 + sum0;
        l1 = l1 * corr1 + sum1;

        #pragma unroll
        for (int nv = 0; nv < 8; ++nv)
            #pragma unroll
            for (int mm = 0; mm < 2; ++mm) {
                accO[nv][mm][0] *= corr0; accO[nv][mm][1] *= corr0;
                accO[nv][mm][2] *= corr1; accO[nv][mm][3] *= corr1;
            }

        #pragma unroll
        for (int ks = 0; ks < 4; ++ks) {
            #pragma unroll
            for (int nv = 0; nv < 8; ++nv) {
                uint32_t voff = (uint32_t)((nv * 16 + b_row) * FA_VSTR + ks * 16 + b_kof) * 2;
                uint32_t bh4[4], bl4[4];
                ldm_x4(bh4, smem_u32(Vh) + voff);
                ldm_x4(bl4, smem_u32(Vl) + voff);
                mma_bf16(accO[nv][0], aPh[ks], bh4 + 0);
                mma_bf16(accO[nv][1], aPh[ks], bh4 + 2);
                mma_bf16(accO[nv][0], aPh[ks], bl4 + 0);
                mma_bf16(accO[nv][1], aPh[ks], bl4 + 2);
                mma_bf16(accO[nv][0], aPl[ks], bh4 + 0);
                mma_bf16(accO[nv][1], aPl[ks], bh4 + 2);
            }
        }
    }

    const float il0 = 1.0f / l0, il1 = 1.0f / l1;
    #pragma unroll
    for (int nv = 0; nv < 8; ++nv)
        #pragma unroll
        for (int mm = 0; mm < 2; ++mm) {
            int c = nv * 16 + mm * 8 + cb;
            size_t base0 = ((size_t)(b * S_) + rg0)     * (H_ * DV_) + h * DV_ + c;
            size_t base1 = ((size_t)(b * S_) + rg0 + 8) * (H_ * DV_) + h * DV_ + c;
            float x0 = accO[nv][mm][0] * il0, y0 = accO[nv][mm][1] * il0;
            float x1 = accO[nv][mm][2] * il1, y1 = accO[nv][mm][3] * il1;
            *reinterpret_cast<uint32_t*>(g_atth + base0) = pack_hi2(x0, y0);
            *reinterpret_cast<uint32_t*>(g_attl + base0) = pack_lo2(x0, y0);
            *reinterpret_cast<uint32_t*>(g_atth + base1) = pack_hi2(x1, y1);
            *reinterpret_cast<uint32_t*>(g_attl + base1) = pack_lo2(x1, y1);
        }
}

// ---------------------------------------------------------------------------
// Launch sequence (single stream)
// ---------------------------------------------------------------------------
extern "C" void kernel_launch(void* const* d_in, const int* in_sizes, int n_in,
                              void* d_out, int out_size) {
    const float* hs    = (const float*)d_in[0];
    const float* w_qa  = (const float*)d_in[2];
    const float* b_qa  = (const float*)d_in[3];
    const float* gq    = (const float*)d_in[4];
    const float* w_qb  = (const float*)d_in[5];
    const float* b_qb  = (const float*)d_in[6];
    const float* w_kva = (const float*)d_in[7];
    const float* b_kva = (const float*)d_in[8];
    const float* gkv   = (const float*)d_in[9];
    const float* w_kvb = (const float*)d_in[10];
    const float* b_kvb = (const float*)d_in[11];
    const float* w_o   = (const float*)d_in[12];
    const float* b_o   = (const float*)d_in[13];
    float* out = (float*)d_out;

    float *p_qa, *p_kva, *p_bkva;
    cudaGetSymbolAddress((void**)&p_qa,   g_qa);
    cudaGetSymbolAddress((void**)&p_kva,  g_kva);
    cudaGetSymbolAddress((void**)&p_bkva, g_bkva);
    __nv_bfloat16 *qa_h, *qa_l, *qb_h, *qb_l, *kva_h, *kva_l, *kvb_h, *kvb_l, *o_h, *o_l;
    cudaGetSymbolAddress((void**)&qa_h,  g_wqa_h);  cudaGetSymbolAddress((void**)&qa_l,  g_wqa_l);
    cudaGetSymbolAddress((void**)&qb_h,  g_wqb_h);  cudaGetSymbolAddress((void**)&qb_l,  g_wqb_l);
    cudaGetSymbolAddress((void**)&kva_h, g_wkva_h); cudaGetSymbolAddress((void**)&kva_l, g_wkva_l);
    cudaGetSymbolAddress((void**)&kvb_h, g_wkvb_h); cudaGetSymbolAddress((void**)&kvb_l, g_wkvb_l);
    cudaGetSymbolAddress((void**)&o_h,   g_wo_h);   cudaGetSymbolAddress((void**)&o_l,   g_wo_l);
    __nv_bfloat16 *hs_h, *hs_l, *qn_h, *qn_l, *kvn_h, *kvn_l, *att_h, *att_l;
    cudaGetSymbolAddress((void**)&hs_h,  g_hsh);  cudaGetSymbolAddress((void**)&hs_l,  g_hsl);
    cudaGetSymbolAddress((void**)&qn_h,  g_qnh);  cudaGetSymbolAddress((void**)&qn_l,  g_qnl);
    cudaGetSymbolAddress((void**)&kvn_h, g_kvnh); cudaGetSymbolAddress((void**)&kvn_l, g_kvnl);
    cudaGetSymbolAddress((void**)&att_h, g_atth); cudaGetSymbolAddress((void**)&att_l, g_attl);

    cudaFuncSetAttribute(flash_mma, cudaFuncAttributeMaxDynamicSharedMemorySize, FA_SMEM);
    cudaFuncSetAttribute(gemm_mma2, cudaFuncAttributeMaxDynamicSharedMemorySize, GEMM_SMEM2);
    cudaFuncSetAttribute(gemm_qb_rope, cudaFuncAttributeMaxDynamicSharedMemorySize, GEMM_SMEM2);
    cudaFuncSetAttribute(gemm_kva_fused, cudaFuncAttributeMaxDynamicSharedMemorySize, GEMM_SMEM2);
    cudaFuncSetAttribute(gemm_kvb_fused, cudaFuncAttributeMaxDynamicSharedMemorySize, GEMM_SMEM2);

    // ---- prep: weights, bias pad, rope table, hs split ----
    dim3 tb(32, 8);
    prep_w<<<dim3(D_ / 32,  RQ_ / 32),           tb>>>(w_qa,  qa_h,  qa_l,  D_,  RQ_,       RQ_);
    prep_w<<<dim3(RQ_ / 32, (H_ * DH_) / 32),    tb>>>(w_qb,  qb_h,  qb_l,  RQ_, H_ * DH_,  H_ * DH_);
    prep_w<<<dim3(D_ / 32,  KVA_NPAD / 32),      tb>>>(w_kva, kva_h, kva_l, D_,  KVA_N,     KVA_NPAD);
    prep_w<<<dim3(RKV_ / 32, (HKV_ * 256) / 32), tb>>>(w_kvb, kvb_h, kvb_l, RKV_, HKV_ * 256, HKV_ * 256);
    prep_w<<<dim3(D_ / 32,  D_ / 32),            tb>>>(w_o,   o_h,   o_l,   D_,  D_,        D_);
    pad_bias_kva<<<(KVA_NPAD + 255) / 256, 256>>>(b_kva);
    rope_table<<<(S_ * 32 + 255) / 256, 256>>>();
    {
        constexpr size_t n4 = (size_t)M_ * D_ / 4;
        split_act4<<<(unsigned)((n4 + 255) / 256), 256>>>(
            (const float4*)hs, (uint2*)hs_h, (uint2*)hs_l, n4);
    }

    // ---- projections ----
    gemm_mma2<<<dim3(RQ_ / 128, M_ / 128), 256, GEMM_SMEM2>>>(hs_h, hs_l, qa_h, qa_l, b_qa, p_qa, M_, RQ_, D_);
    rmsnorm_split4<<<M_, RQ_ / 4>>>(p_qa, gq, qn_h, qn_l, RQ_, RQ_);
    gemm_qb_rope<<<dim3((H_ * DH_) / 128, M_ / 128), 256, GEMM_SMEM2>>>(qn_h, qn_l, qb_h, qb_l, b_qb);
    // kva GEMM: fp32 cols 0-511 for rmsnorm + fused K-rope epilogue (cols 512-575)
    gemm_kva_fused<<<dim3(KVA_NPAD / 128, M_ / 128), 256, GEMM_SMEM2>>>(hs_h, hs_l, kva_h, kva_l, p_bkva, p_kva);
    rmsnorm_split4<<<M_, RKV_ / 4>>>(p_kva, gkv, kvn_h, kvn_l, RKV_, KVA_NPAD);
    gemm_kvb_fused<<<dim3((HKV_ * 256) / 128, M_ / 128), 256, GEMM_SMEM2>>>(kvn_h, kvn_l, kvb_h, kvb_l, b_kvb);

    // ---- attention + output projection ----
    flash_mma<<<dim3(B_ * H_, S_ / 128), 256, FA_SMEM>>>();
    gemm_mma2<<<dim3(D_ / 128, M_ / 128), 256, GEMM_SMEM2>>>(
        att_h, att_l, o_h, o_l, b_o, out, M_, D_, D_);
}